// round 6
// baseline (speedup 1.0000x reference)
#include <cuda_runtime.h>
#include <cuda_bf16.h>
#include <math.h>
#include <stdint.h>

// ---------------------------------------------------------------------------
// Problem constants
// ---------------------------------------------------------------------------
#define S_LEN     8192
#define T_LEN     256
#define NUM_HEADS 16
#define HEAD_DIM  64
#define INNER     1024
#define INNER3    3072
#define SPARSE_N  8
#define G_LEN     1024
#define STOT      1280
#define NJH       128
#define EPS_RMS   1e-5f
#define ATTN_SCALE 0.125f
#define ATT_ELEMS (NJH * STOT * HEAD_DIM)

// ---------------------------------------------------------------------------
// Static device scratch
// ---------------------------------------------------------------------------
__device__ float g_qkvraw[S_LEN * INNER3];
__device__ float g_aqkvraw[T_LEN * INNER3];
__device__ float g_encpart[4 * T_LEN * INNER3];
__device__ float g_txtpart[4 * T_LEN * INNER];
__device__ float g_OA[ATT_ELEMS];

__device__ __nv_bfloat16 g_hs_h[S_LEN * INNER];
__device__ __nv_bfloat16 g_hs_l[S_LEN * INNER];
__device__ __nv_bfloat16 g_enc_h[T_LEN * INNER];
__device__ __nv_bfloat16 g_enc_l[T_LEN * INNER];
__device__ __nv_bfloat16 g_w_h[8 * INNER * INNER];
__device__ __nv_bfloat16 g_w_l[8 * INNER * INNER];
__device__ __nv_bfloat16 g_vis_h[S_LEN * INNER];
__device__ __nv_bfloat16 g_vis_l[S_LEN * INNER];
__device__ __nv_bfloat16 g_txt_h[T_LEN * INNER];
__device__ __nv_bfloat16 g_txt_l[T_LEN * INNER];
__device__ __nv_bfloat16 g_QAh[ATT_ELEMS];
__device__ __nv_bfloat16 g_QAl[ATT_ELEMS];
__device__ __nv_bfloat16 g_KAh[ATT_ELEMS];
__device__ __nv_bfloat16 g_KAl[ATT_ELEMS];
__device__ __nv_bfloat16 g_VAh[ATT_ELEMS];
__device__ __nv_bfloat16 g_VAl[ATT_ELEMS];

// ---------------------------------------------------------------------------
// Helpers
// ---------------------------------------------------------------------------
__device__ __forceinline__ uint32_t smem_u32(const void* p) {
    uint32_t a;
    asm("{ .reg .u64 t; cvta.to.shared.u64 t, %1; cvt.u32.u64 %0, t; }"
        : "=r"(a) : "l"(p));
    return a;
}

#define CP_ASYNC16(dst, src) \
    asm volatile("cp.async.cg.shared.global [%0], [%1], 16;" :: "r"(dst), "l"(src))
#define CP_COMMIT() asm volatile("cp.async.commit_group;" ::: "memory")
#define CP_WAIT0()  asm volatile("cp.async.wait_group 0;" ::: "memory")
#define CP_WAIT1()  asm volatile("cp.async.wait_group 1;" ::: "memory")
#define CP_WAIT2()  asm volatile("cp.async.wait_group 2;" ::: "memory")

__device__ __forceinline__ void ldsm_x4(uint32_t* r, uint32_t a) {
    asm volatile("ldmatrix.sync.aligned.m8n8.x4.shared.b16 {%0,%1,%2,%3}, [%4];"
        : "=r"(r[0]), "=r"(r[1]), "=r"(r[2]), "=r"(r[3]) : "r"(a));
}
__device__ __forceinline__ void ldsm_x4_t(uint32_t* r, uint32_t a) {
    asm volatile("ldmatrix.sync.aligned.m8n8.x4.trans.shared.b16 {%0,%1,%2,%3}, [%4];"
        : "=r"(r[0]), "=r"(r[1]), "=r"(r[2]), "=r"(r[3]) : "r"(a));
}
__device__ __forceinline__ void mma16816(float* c, const uint32_t* a, const uint32_t* b) {
    asm volatile(
        "mma.sync.aligned.m16n8k16.row.col.f32.bf16.bf16.f32 "
        "{%0,%1,%2,%3}, {%4,%5,%6,%7}, {%8,%9}, {%0,%1,%2,%3};"
        : "+f"(c[0]), "+f"(c[1]), "+f"(c[2]), "+f"(c[3])
        : "r"(a[0]), "r"(a[1]), "r"(a[2]), "r"(a[3]), "r"(b[0]), "r"(b[1]));
}

__device__ __forceinline__ uint32_t packbf(__nv_bfloat16 x, __nv_bfloat16 y) {
    return (uint32_t)__bfloat16_as_ushort(x) | ((uint32_t)__bfloat16_as_ushort(y) << 16);
}
__device__ __forceinline__ void split2(float x, float y, uint32_t& hi, uint32_t& lo) {
    __nv_bfloat16 hx = __float2bfloat16(x), hy = __float2bfloat16(y);
    __nv_bfloat16 lx = __float2bfloat16(x - __bfloat162float(hx));
    __nv_bfloat16 ly = __float2bfloat16(y - __bfloat162float(hy));
    hi = packbf(hx, hy);
    lo = packbf(lx, ly);
}
__device__ __forceinline__ void store_split(__nv_bfloat16* ph, __nv_bfloat16* pl,
                                            size_t idx, float v) {
    __nv_bfloat16 h = __float2bfloat16(v);
    ph[idx] = h;
    pl[idx] = __float2bfloat16(v - __bfloat162float(h));
}
__device__ __forceinline__ float warp_sum32(float v) {
#pragma unroll
    for (int o = 16; o > 0; o >>= 1)
        v += __shfl_xor_sync(0xffffffffu, v, o);
    return v;
}

// ---------------------------------------------------------------------------
// fp32 -> bf16 hi/lo conversions
// ---------------------------------------------------------------------------
__global__ void __launch_bounds__(256)
cvt_kernel(const float* __restrict__ src, __nv_bfloat16* __restrict__ hi,
           __nv_bfloat16* __restrict__ lo, int n4)
{
    const int i = blockIdx.x * 256 + threadIdx.x;
    if (i >= n4) return;
    float4 v = ((const float4*)src)[i];
    uint32_t h01, l01, h23, l23;
    split2(v.x, v.y, h01, l01);
    split2(v.z, v.w, h23, l23);
    ((uint2*)hi)[i] = make_uint2(h01, h23);
    ((uint2*)lo)[i] = make_uint2(l01, l23);
}

__global__ void __launch_bounds__(256)
cvt8_kernel(const float* w0, const float* w1, const float* w2, const float* w3,
            const float* w4, const float* w5, const float* w6, const float* w7,
            __nv_bfloat16* __restrict__ hi, __nv_bfloat16* __restrict__ lo)
{
    const int wi = blockIdx.x >> 10;
    const int i  = (blockIdx.x & 1023) * 256 + threadIdx.x;
    const float* src;
    switch (wi) {
        case 0: src = w0; break;  case 1: src = w1; break;
        case 2: src = w2; break;  case 3: src = w3; break;
        case 4: src = w4; break;  case 5: src = w5; break;
        case 6: src = w6; break;  default: src = w7; break;
    }
    float4 v = ((const float4*)src)[i];
    uint32_t h01, l01, h23, l23;
    split2(v.x, v.y, h01, l01);
    split2(v.z, v.w, h23, l23);
    const size_t o = (size_t)wi * (INNER * INNER / 4) + i;
    ((uint2*)hi)[o] = make_uint2(h01, h23);
    ((uint2*)lo)[o] = make_uint2(l01, l23);
}

// ---------------------------------------------------------------------------
// GEMM v2: bf16x3 tensor-core NT GEMM, 256x128 CTA tile, 512 threads,
// 3-stage cp.async pipeline, optional K-split via blockIdx.z.
// C[m][n] = sum_k A[m][k]*W[n][k] (+bias if kparts==1).
// kparts>1: writes partials to C + z*M*N (no bias).
// ---------------------------------------------------------------------------
#define PADK 40
#define V2_TILE_A (256 * PADK)
#define V2_TILE_W (128 * PADK)
#define V2_STAGE (2 * V2_TILE_A + 2 * V2_TILE_W)   // 30720 elems
#define GEMM_SMEM_BYTES (3 * V2_STAGE * 2)          // 184320 B

__global__ void __launch_bounds__(512, 1)
gemm_v2_kernel(const __nv_bfloat16* __restrict__ Ah, const __nv_bfloat16* __restrict__ Al,
               const __nv_bfloat16* __restrict__ Wh, const __nv_bfloat16* __restrict__ Wl,
               const float* __restrict__ bias, float* __restrict__ C,
               int M, int N, int K, int kparts)
{
    extern __shared__ __nv_bfloat16 sm[];
    const int t    = threadIdx.x;
    const int lane = t & 31;
    const int wid  = t >> 5;          // 0..15
    const int wm   = wid >> 1;        // 0..7
    const int wn   = wid & 1;         // 0..1
    const int m0   = blockIdx.y * 256;
    const int n0   = blockIdx.x * 128;

    const int KC    = K / kparts;
    const int kbase = blockIdx.z * KC;
    const int NT    = KC / 32;

    float acc[2][8][4];
#pragma unroll
    for (int i = 0; i < 2; i++)
#pragma unroll
        for (int j = 0; j < 8; j++)
#pragma unroll
            for (int q = 0; q < 4; q++) acc[i][j][q] = 0.f;

    // loader: rr = t>>2 (0..127), cc = (t&3)*8; 6 chunks per thread/stage
    const int rr = t >> 2;
    const int cc = (t & 3) * 8;
    const uint32_t smb = smem_u32(sm);

    const __nv_bfloat16* pA0 = Ah + (size_t)(m0 + rr)       * K + kbase + cc;
    const __nv_bfloat16* pA1 = Ah + (size_t)(m0 + rr + 128) * K + kbase + cc;
    const __nv_bfloat16* pL0 = Al + (size_t)(m0 + rr)       * K + kbase + cc;
    const __nv_bfloat16* pL1 = Al + (size_t)(m0 + rr + 128) * K + kbase + cc;
    const __nv_bfloat16* pWh = Wh + (size_t)(n0 + rr)       * K + kbase + cc;
    const __nv_bfloat16* pWl = Wl + (size_t)(n0 + rr)       * K + kbase + cc;

    const uint32_t dA0 = (uint32_t)((rr * PADK + cc) << 1);
    const uint32_t dA1 = (uint32_t)(((rr + 128) * PADK + cc) << 1);
    const uint32_t dL0 = dA0 + (uint32_t)(V2_TILE_A << 1);
    const uint32_t dL1 = dA1 + (uint32_t)(V2_TILE_A << 1);
    const uint32_t dWh = dA0 + (uint32_t)((2 * V2_TILE_A) << 1);
    const uint32_t dWl = dA0 + (uint32_t)(((2 * V2_TILE_A) + V2_TILE_W) << 1);

#define V2_LOAD(kt, stg) do {                                              \
    const uint32_t sb = smb + (uint32_t)(((stg) * V2_STAGE) << 1);         \
    const int ko = (kt) * 32;                                              \
    CP_ASYNC16(sb + dA0, pA0 + ko);                                        \
    CP_ASYNC16(sb + dA1, pA1 + ko);                                        \
    CP_ASYNC16(sb + dL0, pL0 + ko);                                        \
    CP_ASYNC16(sb + dL1, pL1 + ko);                                        \
    CP_ASYNC16(sb + dWh, pWh + ko);                                        \
    CP_ASYNC16(sb + dWl, pWl + ko);                                        \
    CP_COMMIT();                                                           \
} while (0)

    V2_LOAD(0, 0);
    V2_LOAD(1, 1);

    const uint32_t abase_rel = (uint32_t)((((wm * 32 + (lane & 15)) * PADK +
                                            ((lane >> 4) << 3))) << 1);
    const uint32_t bbase_rel = (uint32_t)(((2 * V2_TILE_A +
                     (wn * 64 + (lane & 7) + ((lane >> 4) << 3)) * PADK +
                     (((lane >> 3) & 1) << 3))) << 1);

    int stg = 0;
    for (int kt = 0; kt < NT; kt++) {
        if (kt + 2 < NT) {
            const int ps = (stg + 2 >= 3) ? (stg - 1) : (stg + 2);
            V2_LOAD(kt + 2, ps);
            CP_WAIT2();
        } else {
            CP_WAIT0();
        }
        __syncthreads();

        const uint32_t stage  = smb + (uint32_t)((stg * V2_STAGE) << 1);
        const uint32_t abaseh = stage + abase_rel;
        const uint32_t abasel = abaseh + (uint32_t)(V2_TILE_A << 1);
        const uint32_t bbaseh = stage + bbase_rel;
        const uint32_t bbasel = bbaseh + (uint32_t)(V2_TILE_W << 1);

#pragma unroll
        for (int ks = 0; ks < 32; ks += 16) {
            uint32_t a0h[4], a1h[4], a0l[4], a1l[4];
            ldsm_x4(a0h, abaseh + ks * 2);
            ldsm_x4(a1h, abaseh + ks * 2 + 16 * PADK * 2);
            ldsm_x4(a0l, abasel + ks * 2);
            ldsm_x4(a1l, abasel + ks * 2 + 16 * PADK * 2);
#pragma unroll
            for (int nbp = 0; nbp < 4; nbp++) {
                uint32_t bh[4], bl[4];
                ldsm_x4(bh, bbaseh + ks * 2 + nbp * 16 * PADK * 2);
                ldsm_x4(bl, bbasel + ks * 2 + nbp * 16 * PADK * 2);
                mma16816(acc[0][2 * nbp],     a0h, bh);
                mma16816(acc[0][2 * nbp + 1], a0h, bh + 2);
                mma16816(acc[1][2 * nbp],     a1h, bh);
                mma16816(acc[1][2 * nbp + 1], a1h, bh + 2);
                mma16816(acc[0][2 * nbp],     a0h, bl);
                mma16816(acc[0][2 * nbp + 1], a0h, bl + 2);
                mma16816(acc[1][2 * nbp],     a1h, bl);
                mma16816(acc[1][2 * nbp + 1], a1h, bl + 2);
                mma16816(acc[0][2 * nbp],     a0l, bh);
                mma16816(acc[0][2 * nbp + 1], a0l, bh + 2);
                mma16816(acc[1][2 * nbp],     a1l, bh);
                mma16816(acc[1][2 * nbp + 1], a1l, bh + 2);
            }
        }
        __syncthreads();
        stg = (stg + 1 >= 3) ? 0 : (stg + 1);
    }

    float* Cz = C + (size_t)blockIdx.z * M * N;
    const float* bp = (kparts == 1) ? bias : nullptr;
    const int r0 = m0 + wm * 32 + (lane >> 2);
    const int c0 = n0 + wn * 64 + (lane & 3) * 2;
#pragma unroll
    for (int mi = 0; mi < 2; mi++) {
        const int r = r0 + mi * 16;
#pragma unroll
        for (int nb = 0; nb < 8; nb++) {
            const int c = c0 + nb * 8;
            float b0 = 0.f, b1 = 0.f;
            if (bp) { b0 = bp[c]; b1 = bp[c + 1]; }
            *(float2*)(Cz + (size_t)r * N + c) =
                make_float2(acc[mi][nb][0] + b0, acc[mi][nb][1] + b1);
            *(float2*)(Cz + (size_t)(r + 8) * N + c) =
                make_float2(acc[mi][nb][2] + b0, acc[mi][nb][3] + b1);
        }
    }
}

// ---------------------------------------------------------------------------
// K-split reduction: out = sum of 4 partials (+ bias per column)
// ---------------------------------------------------------------------------
__global__ void __launch_bounds__(256)
reduce4_kernel(const float* __restrict__ part, const float* __restrict__ bias,
               float* __restrict__ out, int MN, int N)
{
    const int i = blockIdx.x * 256 + threadIdx.x;   // float4 index
    if (i * 4 >= MN) return;
    const int q = MN / 4;
    float4 a = ((const float4*)part)[i];
    float4 b = ((const float4*)part)[i + q];
    float4 c = ((const float4*)part)[i + 2 * q];
    float4 d = ((const float4*)part)[i + 3 * q];
    float4 r = make_float4(a.x + b.x + c.x + d.x, a.y + b.y + c.y + d.y,
                           a.z + b.z + c.z + d.z, a.w + b.w + c.w + d.w);
    if (bias) {
        const int col = (i * 4) % N;
        r.x += bias[col];  r.y += bias[col + 1];
        r.z += bias[col + 2];  r.w += bias[col + 3];
    }
    ((float4*)out)[i] = r;
}

// ---------------------------------------------------------------------------
// RMSNorm + RoPE + sparse scatter (visual)
// ---------------------------------------------------------------------------
__global__ void __launch_bounds__(256)
qkv_post_kernel(const float* __restrict__ qkv,
                const float* __restrict__ gq, const float* __restrict__ gk,
                const float* __restrict__ cosb, const float* __restrict__ sinb,
                __nv_bfloat16* __restrict__ QAh, __nv_bfloat16* __restrict__ QAl,
                __nv_bfloat16* __restrict__ KAh, __nv_bfloat16* __restrict__ KAl,
                __nv_bfloat16* __restrict__ VAh, __nv_bfloat16* __restrict__ VAl)
{
    const int warp = (blockIdx.x * blockDim.x + threadIdx.x) >> 5;
    const int lane = threadIdx.x & 31;
    const int s = warp >> 4;
    const int h = warp & 15;
    if (s >= S_LEN) return;

    const size_t src = (size_t)s * INNER3 + h * HEAD_DIM;
    float q0 = qkv[src + lane],            q1 = qkv[src + lane + 32];
    float k0 = qkv[src + INNER + lane],    k1 = qkv[src + INNER + lane + 32];
    float v0 = qkv[src + 2*INNER + lane],  v1 = qkv[src + 2*INNER + lane + 32];

    float rq = rsqrtf(warp_sum32(q0 * q0 + q1 * q1) * (1.f / HEAD_DIM) + EPS_RMS);
    float rk = rsqrtf(warp_sum32(k0 * k0 + k1 * k1) * (1.f / HEAD_DIM) + EPS_RMS);

    q0 *= rq * gq[lane];  q1 *= rq * gq[lane + 32];
    k0 *= rk * gk[lane];  k1 *= rk * gk[lane + 32];

    const float c0 = cosb[(size_t)s * HEAD_DIM + lane];
    const float c1 = cosb[(size_t)s * HEAD_DIM + lane + 32];
    const float s0 = sinb[(size_t)s * HEAD_DIM + lane];
    const float s1 = sinb[(size_t)s * HEAD_DIM + lane + 32];

    const float oq0 = (q0 * c0 - q1 * s0) * ATTN_SCALE;
    const float oq1 = (q1 * c1 + q0 * s1) * ATTN_SCALE;
    const float ok0 = k0 * c0 - k1 * s0;
    const float ok1 = k1 * c1 + k0 * s1;

    const int j = s & 7, tt = s >> 3;
    const size_t dst = (((size_t)(j * NUM_HEADS + h)) * STOT + tt) * HEAD_DIM;
    store_split(QAh, QAl, dst + lane,      oq0);
    store_split(QAh, QAl, dst + lane + 32, oq1);
    store_split(KAh, KAl, dst + lane,      ok0);
    store_split(KAh, KAl, dst + lane + 32, ok1);
    store_split(VAh, VAl, dst + lane,      v0);
    store_split(VAh, VAl, dst + lane + 32, v1);
}

// ---------------------------------------------------------------------------
// RMSNorm + broadcast scatter (text)
// ---------------------------------------------------------------------------
__global__ void __launch_bounds__(256)
enc_post_kernel(const float* __restrict__ aqkv,
                const float* __restrict__ gaq, const float* __restrict__ gak,
                __nv_bfloat16* __restrict__ QAh, __nv_bfloat16* __restrict__ QAl,
                __nv_bfloat16* __restrict__ KAh, __nv_bfloat16* __restrict__ KAl,
                __nv_bfloat16* __restrict__ VAh, __nv_bfloat16* __restrict__ VAl)
{
    const int warp = (blockIdx.x * blockDim.x + threadIdx.x) >> 5;
    const int lane = threadIdx.x & 31;
    const int tt = warp >> 4;
    const int h  = warp & 15;
    if (tt >= T_LEN) return;

    const size_t src = (size_t)tt * INNER3 + h * HEAD_DIM;
    float a0 = aqkv[src + lane],           a1 = aqkv[src + lane + 32];
    float b0 = aqkv[src + INNER + lane],   b1 = aqkv[src + INNER + lane + 32];
    const float v0 = aqkv[src + 2*INNER + lane], v1 = aqkv[src + 2*INNER + lane + 32];

    float ra = rsqrtf(warp_sum32(a0 * a0 + a1 * a1) * (1.f / HEAD_DIM) + EPS_RMS);
    float rb = rsqrtf(warp_sum32(b0 * b0 + b1 * b1) * (1.f / HEAD_DIM) + EPS_RMS);

    a0 *= ra * gaq[lane] * ATTN_SCALE;  a1 *= ra * gaq[lane + 32] * ATTN_SCALE;
    b0 *= rb * gak[lane];               b1 *= rb * gak[lane + 32];

#pragma unroll
    for (int j = 0; j < SPARSE_N; j++) {
        const size_t dst =
            (((size_t)(j * NUM_HEADS + h)) * STOT + G_LEN + tt) * HEAD_DIM;
        store_split(QAh, QAl, dst + lane,      a0);
        store_split(QAh, QAl, dst + lane + 32, a1);
        store_split(KAh, KAl, dst + lane,      b0);
        store_split(KAh, KAl, dst + lane + 32, b1);
        store_split(VAh, VAl, dst + lane,      v0);
        store_split(VAh, VAl, dst + lane + 32, v1);
    }
}

// ---------------------------------------------------------------------------
// Flash attention, BQ=256, 512 threads, cp.async K/V double buffering
// ---------------------------------------------------------------------------
#define APAD 72
#define AQ_ELEMS (2 * 256 * APAD)
#define KV_TILE  (64 * APAD)
#define KV_STAGE (4 * KV_TILE)
#define ATT_SM_BYTES ((AQ_ELEMS + 2 * KV_STAGE) * 2)   // 147456

__global__ void __launch_bounds__(512, 1)
attn_mma_kernel(const __nv_bfloat16* __restrict__ Qhg, const __nv_bfloat16* __restrict__ Qlg,
                const __nv_bfloat16* __restrict__ Khg, const __nv_bfloat16* __restrict__ Klg,
                const __nv_bfloat16* __restrict__ Vhg, const __nv_bfloat16* __restrict__ Vlg,
                float* __restrict__ OA)
{
    extern __shared__ __nv_bfloat16 smA[];
    const int t    = threadIdx.x;
    const int lane = t & 31;
    const int w    = t >> 5;
    const int jh   = blockIdx.y;
    const int q0   = blockIdx.x * 256;
    const size_t base = (size_t)jh * STOT * HEAD_DIM;

    const uint32_t smb = smem_u32(smA);

    const int tile = t >> 7;
    const int l128 = t & 127;
    const int krr  = l128 >> 3;
    const int kcc  = (l128 & 7) * 8;
    const __nv_bfloat16* kvsrc =
        (tile == 0) ? Khg : (tile == 1) ? Klg : (tile == 2) ? Vhg : Vlg;
    const uint32_t kvdst0 = smb + ((AQ_ELEMS + tile * KV_TILE + krr * APAD + kcc) << 1);

    {
        const __nv_bfloat16* g = kvsrc + base + (size_t)krr * 64 + kcc;
#pragma unroll
        for (int i = 0; i < 4; i++)
            CP_ASYNC16(kvdst0 + (uint32_t)((i * 16 * APAD) << 1),
                       g + (size_t)(i * 16) * 64);
        CP_COMMIT();
    }

    {
        const int row = t >> 1, c0 = (t & 1) * 32;
        const __nv_bfloat16* gh = Qhg + base + (size_t)(q0 + row) * 64 + c0;
        const __nv_bfloat16* gl = Qlg + base + (size_t)(q0 + row) * 64 + c0;
        __nv_bfloat16* sh = smA + row * APAD + c0;
        __nv_bfloat16* sl = smA + 256 * APAD + row * APAD + c0;
#pragma unroll
        for (int c = 0; c < 32; c += 8) {
            *(uint4*)(sh + c) = *(const uint4*)(gh + c);
            *(uint4*)(sl + c) = *(const uint4*)(gl + c);
        }
    }

    float o[8][4];
#pragma unroll
    for (int i = 0; i < 8; i++)
#pragma unroll
        for (int j = 0; j < 4; j++) o[i][j] = 0.f;
    float m0r = -1e30f, m1r = -1e30f, l0r = 0.f, l1r = 0.f;

    const uint32_t qfragh = smb + (((w * 16 + (lane & 15)) * APAD + ((lane >> 4) << 3)) << 1);
    const uint32_t qfragl = qfragh + ((256 * APAD) << 1);
    const uint32_t kfrag_rel = ((((lane & 7) + ((lane >> 4) << 3)) * APAD + (((lane >> 3) & 1) << 3)) << 1);
    const uint32_t vfrag_rel = (((2 * KV_TILE) + ((lane & 7) + (((lane >> 3) & 1) << 3)) * APAD + ((lane >> 4) << 3)) << 1);

    for (int kt = 0; kt < 20; kt++) {
        const int b = kt & 1;
        if (kt + 1 < 20) {
            const __nv_bfloat16* g = kvsrc + base + (size_t)((kt + 1) * 64 + krr) * 64 + kcc;
            const uint32_t d = kvdst0 + (uint32_t)((((kt + 1) & 1) * KV_STAGE) << 1);
#pragma unroll
            for (int i = 0; i < 4; i++)
                CP_ASYNC16(d + (uint32_t)((i * 16 * APAD) << 1),
                           g + (size_t)(i * 16) * 64);
            CP_COMMIT();
            CP_WAIT1();
        } else {
            CP_WAIT0();
        }
        __syncthreads();

        const uint32_t kvstage = smb + (uint32_t)(((AQ_ELEMS + b * KV_STAGE)) << 1);
        const uint32_t kfragh = kvstage + kfrag_rel;
        const uint32_t kfragl = kfragh + (KV_TILE << 1);
        const uint32_t vfrag  = kvstage + vfrag_rel;

        float s[8][4];
#pragma unroll
        for (int i = 0; i < 8; i++)
#pragma unroll
            for (int j = 0; j < 4; j++) s[i][j] = 0.f;

#pragma unroll
        for (int ks = 0; ks < 64; ks += 16) {
            uint32_t ah[4], al[4];
            ldsm_x4(ah, qfragh + ks * 2);
            ldsm_x4(al, qfragl + ks * 2);
#pragma unroll
            for (int nbp = 0; nbp < 4; nbp++) {
                uint32_t kh[4], kl[4];
                ldsm_x4(kh, kfragh + ks * 2 + nbp * 16 * APAD * 2);
                ldsm_x4(kl, kfragl + ks * 2 + nbp * 16 * APAD * 2);
                mma16816(s[2 * nbp],     ah, kh);
                mma16816(s[2 * nbp + 1], ah, kh + 2);
                mma16816(s[2 * nbp],     ah, kl);
                mma16816(s[2 * nbp + 1], ah, kl + 2);
                mma16816(s[2 * nbp],     al, kh);
                mma16816(s[2 * nbp + 1], al, kh + 2);
            }
        }

        float mt0 = -1e30f, mt1 = -1e30f;
#pragma unroll
        for (int nb = 0; nb < 8; nb++) {
            mt0 = fmaxf(mt0, fmaxf(s[nb][0], s[nb][1]));
            mt1 = fmaxf(mt1, fmaxf(s[nb][2], s[nb][3]));
        }
        mt0 = fmaxf(mt0, __shfl_xor_sync(0xffffffffu, mt0, 1));
        mt0 = fmaxf(mt0, __shfl_xor_sync(0xffffffffu, mt0, 2));
        mt1 = fmaxf(mt1, __shfl_xor_sync(0xffffffffu, mt1, 1));
        mt1 = fmaxf(mt1, __shfl_xor_sync(0xffffffffu, mt1, 2));
        const float mn0 = fmaxf(m0r, mt0), mn1 = fmaxf(m1r, mt1);
        const float cf0 = __expf(m0r - mn0), cf1 = __expf(m1r - mn1);
        m0r = mn0;  m1r = mn1;
        float rs0 = 0.f, rs1 = 0.f;
#pragma unroll
        for (int nb = 0; nb < 8; nb++) {
            s[nb][0] = __expf(s[nb][0] - mn0);  rs0 += s[nb][0];
            s[nb][1] = __expf(s[nb][1] - mn0);  rs0 += s[nb][1];
            s[nb][2] = __expf(s[nb][2] - mn1);  rs1 += s[nb][2];
            s[nb][3] = __expf(s[nb][3] - mn1);  rs1 += s[nb][3];
        }
        rs0 += __shfl_xor_sync(0xffffffffu, rs0, 1);
        rs0 += __shfl_xor_sync(0xffffffffu, rs0, 2);
        rs1 += __shfl_xor_sync(0xffffffffu, rs1, 1);
        rs1 += __shfl_xor_sync(0xffffffffu, rs1, 2);
        l0r = l0r * cf0 + rs0;
        l1r = l1r * cf1 + rs1;
#pragma unroll
        for (int db = 0; db < 8; db++) {
            o[db][0] *= cf0;  o[db][1] *= cf0;
            o[db][2] *= cf1;  o[db][3] *= cf1;
        }

#pragma unroll
        for (int kb2 = 0; kb2 < 4; kb2++) {
            uint32_t ph[4], pl[4];
            split2(s[2 * kb2][0],     s[2 * kb2][1],     ph[0], pl[0]);
            split2(s[2 * kb2][2],     s[2 * kb2][3],     ph[1], pl[1]);
            split2(s[2 * kb2 + 1][0], s[2 * kb2 + 1][1], ph[2], pl[2]);
            split2(s[2 * kb2 + 1][2], s[2 * kb2 + 1][3], ph[3], pl[3]);
            const uint32_t vb = vfrag + kb2 * 16 * APAD * 2;
#pragma unroll
            for (int dbp = 0; dbp < 4; dbp++) {
                uint32_t vh4[4], vl4[4];
                ldsm_x4_t(vh4, vb + dbp * 16 * 2);
                ldsm_x4_t(vl4, vb + (KV_TILE << 1) + dbp * 16 * 2);
                mma16816(o[2 * dbp],     ph, vh4);
                mma16816(o[2 * dbp + 1], ph, vh4 + 2);
                mma16816(o[2 * dbp],     ph, vl4);
                mma16816(o[2 * dbp + 1], ph, vl4 + 2);
                mma16816(o[2 * dbp],     pl, vh4);
                mma16816(o[2 * dbp + 1], pl, vh4 + 2);
            }
        }
        __syncthreads();
    }

    const float inv0 = 1.f / l0r, inv1 = 1.f / l1r;
    const int row = q0 + w * 16 + (lane >> 2);
    const int col = (lane & 3) * 2;
#pragma unroll
    for (int db = 0; db < 8; db++) {
        *(float2*)(OA + base + (size_t)row * 64 + db * 8 + col) =
            make_float2(o[db][0] * inv0, o[db][1] * inv0);
        *(float2*)(OA + base + (size_t)(row + 8) * 64 + db * 8 + col) =
            make_float2(o[db][2] * inv1, o[db][3] * inv1);
    }
}

// ---------------------------------------------------------------------------
// Gather kernels
// ---------------------------------------------------------------------------
__global__ void __launch_bounds__(256)
gather_vis_kernel(const float* __restrict__ OA,
                  __nv_bfloat16* __restrict__ vh, __nv_bfloat16* __restrict__ vl)
{
    const int i = blockIdx.x * 256 + threadIdx.x;
    const int idx = i * 4;
    const int s = idx >> 10, e = idx & 1023;
    const int j = s & 7, tt = s >> 3;
    const int h = e >> 6, d = e & 63;
    float4 v = *(const float4*)(OA + (((size_t)(j * NUM_HEADS + h)) * STOT + tt) * HEAD_DIM + d);
    uint32_t h01, l01, h23, l23;
    split2(v.x, v.y, h01, l01);
    split2(v.z, v.w, h23, l23);
    ((uint2*)vh)[i] = make_uint2(h01, h23);
    ((uint2*)vl)[i] = make_uint2(l01, l23);
}

__global__ void __launch_bounds__(256)
gather_txt_kernel(const float* __restrict__ OA,
                  __nv_bfloat16* __restrict__ th, __nv_bfloat16* __restrict__ tl)
{
    const int i = blockIdx.x * 256 + threadIdx.x;
    const int idx = i * 4;
    const int tt = idx >> 10, e = idx & 1023;
    const int h = e >> 6, d = e & 63;
    float4 acc = make_float4(0.f, 0.f, 0.f, 0.f);
#pragma unroll
    for (int j = 0; j < SPARSE_N; j++) {
        float4 v = *(const float4*)(OA +
            (((size_t)(j * NUM_HEADS + h)) * STOT + G_LEN + tt) * HEAD_DIM + d);
        acc.x += v.x; acc.y += v.y; acc.z += v.z; acc.w += v.w;
    }
    acc.x *= 0.125f; acc.y *= 0.125f; acc.z *= 0.125f; acc.w *= 0.125f;
    uint32_t h01, l01, h23, l23;
    split2(acc.x, acc.y, h01, l01);
    split2(acc.z, acc.w, h23, l23);
    ((uint2*)th)[i] = make_uint2(h01, h23);
    ((uint2*)tl)[i] = make_uint2(l01, l23);
}

// ---------------------------------------------------------------------------
// kernel_launch
// ---------------------------------------------------------------------------
extern "C" void kernel_launch(void* const* d_in, const int* in_sizes, int n_in,
                              void* d_out, int out_size)
{
    const float* hs   = (const float*)d_in[0];
    const float* enc  = (const float*)d_in[1];
    const float* bout  = (const float*)d_in[9];
    const float* baout = (const float*)d_in[11];
    const float* gq   = (const float*)d_in[12];
    const float* gk   = (const float*)d_in[13];
    const float* gaq  = (const float*)d_in[14];
    const float* gak  = (const float*)d_in[15];
    const float* rc   = (const float*)d_in[16];
    const float* rs   = (const float*)d_in[17];
    float* out = (float*)d_out;

    float *qkvraw, *aqkvraw, *encpart, *txtpart, *OA;
    __nv_bfloat16 *hs_h, *hs_l, *enc_h, *enc_l, *w_h, *w_l;
    __nv_bfloat16 *vis_h, *vis_l, *txt_h, *txt_l;
    __nv_bfloat16 *QAh, *QAl, *KAh, *KAl, *VAh, *VAl;
    cudaGetSymbolAddress((void**)&qkvraw,  g_qkvraw);
    cudaGetSymbolAddress((void**)&aqkvraw, g_aqkvraw);
    cudaGetSymbolAddress((void**)&encpart, g_encpart);
    cudaGetSymbolAddress((void**)&txtpart, g_txtpart);
    cudaGetSymbolAddress((void**)&OA,    g_OA);
    cudaGetSymbolAddress((void**)&hs_h,  g_hs_h);
    cudaGetSymbolAddress((void**)&hs_l,  g_hs_l);
    cudaGetSymbolAddress((void**)&enc_h, g_enc_h);
    cudaGetSymbolAddress((void**)&enc_l, g_enc_l);
    cudaGetSymbolAddress((void**)&w_h,   g_w_h);
    cudaGetSymbolAddress((void**)&w_l,   g_w_l);
    cudaGetSymbolAddress((void**)&vis_h, g_vis_h);
    cudaGetSymbolAddress((void**)&vis_l, g_vis_l);
    cudaGetSymbolAddress((void**)&txt_h, g_txt_h);
    cudaGetSymbolAddress((void**)&txt_l, g_txt_l);
    cudaGetSymbolAddress((void**)&QAh,   g_QAh);
    cudaGetSymbolAddress((void**)&QAl,   g_QAl);
    cudaGetSymbolAddress((void**)&KAh,   g_KAh);
    cudaGetSymbolAddress((void**)&KAl,   g_KAl);
    cudaGetSymbolAddress((void**)&VAh,   g_VAh);
    cudaGetSymbolAddress((void**)&VAl,   g_VAl);

    cudaFuncSetAttribute(gemm_v2_kernel,
                         cudaFuncAttributeMaxDynamicSharedMemorySize, GEMM_SMEM_BYTES);
    cudaFuncSetAttribute(attn_mma_kernel,
                         cudaFuncAttributeMaxDynamicSharedMemorySize, ATT_SM_BYTES);

    const size_t WS = (size_t)INNER * INNER;

    // [0] weight conversions, [1] hs, [2] enc
    cvt8_kernel<<<8 * 1024, 256>>>(
        (const float*)d_in[2], (const float*)d_in[3], (const float*)d_in[4],
        (const float*)d_in[5], (const float*)d_in[6], (const float*)d_in[7],
        (const float*)d_in[8], (const float*)d_in[10], w_h, w_l);
    cvt_kernel<<<(S_LEN * INNER / 4) / 256, 256>>>(hs,  hs_h,  hs_l,  S_LEN * INNER / 4);
    cvt_kernel<<<(T_LEN * INNER / 4) / 256, 256>>>(enc, enc_h, enc_l, T_LEN * INNER / 4);

    // [3] enc QKV GEMM (K-split x4), [4] reduce
    gemm_v2_kernel<<<dim3(INNER3 / 128, T_LEN / 256, 4), 512, GEMM_SMEM_BYTES>>>(
        enc_h, enc_l, w_h + 3 * WS, w_l + 3 * WS, nullptr, encpart,
        T_LEN, INNER3, INNER, 4);
    reduce4_kernel<<<(T_LEN * INNER3 / 4) / 256, 256>>>(
        encpart, nullptr, aqkvraw, T_LEN * INNER3, INNER3);

    // [5] big QKV GEMM
    gemm_v2_kernel<<<dim3(INNER3 / 128, S_LEN / 256, 1), 512, GEMM_SMEM_BYTES>>>(
        hs_h, hs_l, w_h + 0 * WS, w_l + 0 * WS, nullptr, qkvraw,
        S_LEN, INNER3, INNER, 1);

    // [6] enc post, [7] visual post
    enc_post_kernel<<<(T_LEN * NUM_HEADS) / 8, 256>>>(
        aqkvraw, gaq, gak, QAh, QAl, KAh, KAl, VAh, VAl);
    qkv_post_kernel<<<(S_LEN * NUM_HEADS) / 8, 256>>>(
        qkvraw, gq, gk, rc, rs, QAh, QAl, KAh, KAl, VAh, VAl);

    // [8] attention
    attn_mma_kernel<<<dim3(STOT / 256, NJH), 512, ATT_SM_BYTES>>>(
        QAh, QAl, KAh, KAl, VAh, VAl, OA);

    // [9..10] gathers
    gather_vis_kernel<<<(S_LEN * INNER / 4) / 256, 256>>>(OA, vis_h, vis_l);
    gather_txt_kernel<<<(T_LEN * INNER / 4) / 256, 256>>>(OA, txt_h, txt_l);

    // [11] vis out GEMM, [12..13] txt out GEMM (K-split x4) + reduce
    gemm_v2_kernel<<<dim3(INNER / 128, S_LEN / 256, 1), 512, GEMM_SMEM_BYTES>>>(
        vis_h, vis_l, w_h + 6 * WS, w_l + 6 * WS, bout, out,
        S_LEN, INNER, INNER, 1);
    gemm_v2_kernel<<<dim3(INNER / 128, T_LEN / 256, 4), 512, GEMM_SMEM_BYTES>>>(
        txt_h, txt_l, w_h + 7 * WS, w_l + 7 * WS, nullptr, txtpart,
        T_LEN, INNER, INNER, 4);
    reduce4_kernel<<<(T_LEN * INNER / 4) / 256, 256>>>(
        txtpart, baout, out + (size_t)S_LEN * INNER, T_LEN * INNER, INNER);
}

// round 8
// speedup vs baseline: 1.0615x; 1.0615x over previous
#include <cuda_runtime.h>
#include <cuda_bf16.h>
#include <math.h>
#include <stdint.h>

// ---------------------------------------------------------------------------
// Problem constants
// ---------------------------------------------------------------------------
#define S_LEN     8192
#define T_LEN     256
#define NUM_HEADS 16
#define HEAD_DIM  64
#define INNER     1024
#define INNER3    3072
#define SPARSE_N  8
#define G_LEN     1024
#define STOT      1280
#define NJH       128
#define EPS_RMS   1e-5f
#define ATTN_SCALE 0.125f
#define ATT_ELEMS (NJH * STOT * HEAD_DIM)

// ---------------------------------------------------------------------------
// Static device scratch
// ---------------------------------------------------------------------------
__device__ float g_qkvraw[S_LEN * INNER3];
__device__ float g_encpart[4 * T_LEN * INNER3];
__device__ float g_txtpart[4 * T_LEN * INNER];
__device__ float g_OA[ATT_ELEMS];

__device__ __nv_bfloat16 g_hs_h[S_LEN * INNER];
__device__ __nv_bfloat16 g_hs_l[S_LEN * INNER];
__device__ __nv_bfloat16 g_enc_h[T_LEN * INNER];
__device__ __nv_bfloat16 g_enc_l[T_LEN * INNER];
__device__ __nv_bfloat16 g_w_h[8 * INNER * INNER];
__device__ __nv_bfloat16 g_w_l[8 * INNER * INNER];
__device__ __nv_bfloat16 g_vis_h[S_LEN * INNER];
__device__ __nv_bfloat16 g_vis_l[S_LEN * INNER];
__device__ __nv_bfloat16 g_txt_h[T_LEN * INNER];
__device__ __nv_bfloat16 g_txt_l[T_LEN * INNER];
__device__ __nv_bfloat16 g_QAh[ATT_ELEMS];
__device__ __nv_bfloat16 g_QAl[ATT_ELEMS];
__device__ __nv_bfloat16 g_KAh[ATT_ELEMS];
__device__ __nv_bfloat16 g_KAl[ATT_ELEMS];
__device__ __nv_bfloat16 g_VAh[ATT_ELEMS];
__device__ __nv_bfloat16 g_VAl[ATT_ELEMS];

// ---------------------------------------------------------------------------
// Helpers
// ---------------------------------------------------------------------------
__device__ __forceinline__ uint32_t smem_u32(const void* p) {
    uint32_t a;
    asm("{ .reg .u64 t; cvta.to.shared.u64 t, %1; cvt.u32.u64 %0, t; }"
        : "=r"(a) : "l"(p));
    return a;
}

#define CP_ASYNC16(dst, src) \
    asm volatile("cp.async.cg.shared.global [%0], [%1], 16;" :: "r"(dst), "l"(src))
#define CP_COMMIT() asm volatile("cp.async.commit_group;" ::: "memory")
#define CP_WAIT0()  asm volatile("cp.async.wait_group 0;" ::: "memory")
#define CP_WAIT1()  asm volatile("cp.async.wait_group 1;" ::: "memory")
#define CP_WAIT2()  asm volatile("cp.async.wait_group 2;" ::: "memory")

__device__ __forceinline__ void ldsm_x4(uint32_t* r, uint32_t a) {
    asm volatile("ldmatrix.sync.aligned.m8n8.x4.shared.b16 {%0,%1,%2,%3}, [%4];"
        : "=r"(r[0]), "=r"(r[1]), "=r"(r[2]), "=r"(r[3]) : "r"(a));
}
__device__ __forceinline__ void ldsm_x4_t(uint32_t* r, uint32_t a) {
    asm volatile("ldmatrix.sync.aligned.m8n8.x4.trans.shared.b16 {%0,%1,%2,%3}, [%4];"
        : "=r"(r[0]), "=r"(r[1]), "=r"(r[2]), "=r"(r[3]) : "r"(a));
}
__device__ __forceinline__ void mma16816(float* c, const uint32_t* a, const uint32_t* b) {
    asm volatile(
        "mma.sync.aligned.m16n8k16.row.col.f32.bf16.bf16.f32 "
        "{%0,%1,%2,%3}, {%4,%5,%6,%7}, {%8,%9}, {%0,%1,%2,%3};"
        : "+f"(c[0]), "+f"(c[1]), "+f"(c[2]), "+f"(c[3])
        : "r"(a[0]), "r"(a[1]), "r"(a[2]), "r"(a[3]), "r"(b[0]), "r"(b[1]));
}

__device__ __forceinline__ uint32_t packbf(__nv_bfloat16 x, __nv_bfloat16 y) {
    return (uint32_t)__bfloat16_as_ushort(x) | ((uint32_t)__bfloat16_as_ushort(y) << 16);
}
__device__ __forceinline__ void split2(float x, float y, uint32_t& hi, uint32_t& lo) {
    __nv_bfloat16 hx = __float2bfloat16(x), hy = __float2bfloat16(y);
    __nv_bfloat16 lx = __float2bfloat16(x - __bfloat162float(hx));
    __nv_bfloat16 ly = __float2bfloat16(y - __bfloat162float(hy));
    hi = packbf(hx, hy);
    lo = packbf(lx, ly);
}
__device__ __forceinline__ void store_split(__nv_bfloat16* ph, __nv_bfloat16* pl,
                                            size_t idx, float v) {
    __nv_bfloat16 h = __float2bfloat16(v);
    ph[idx] = h;
    pl[idx] = __float2bfloat16(v - __bfloat162float(h));
}
__device__ __forceinline__ float warp_sum32(float v) {
#pragma unroll
    for (int o = 16; o > 0; o >>= 1)
        v += __shfl_xor_sync(0xffffffffu, v, o);
    return v;
}

// ---------------------------------------------------------------------------
// One-shot fp32 -> bf16 hi/lo conversion: 8 weights + hs + enc in one launch
// blocks [0, 8192): weights ; [8192, 16384): hs ; [16384, 16640): enc
// ---------------------------------------------------------------------------
__global__ void __launch_bounds__(256)
cvt_all_kernel(const float* w0, const float* w1, const float* w2, const float* w3,
               const float* w4, const float* w5, const float* w6, const float* w7,
               const float* __restrict__ hs, const float* __restrict__ enc,
               __nv_bfloat16* __restrict__ w_h, __nv_bfloat16* __restrict__ w_l,
               __nv_bfloat16* __restrict__ hs_h, __nv_bfloat16* __restrict__ hs_l,
               __nv_bfloat16* __restrict__ enc_h, __nv_bfloat16* __restrict__ enc_l)
{
    const int bx = blockIdx.x;
    if (bx < 8192) {
        const int wi = bx >> 10;
        const int i  = (bx & 1023) * 256 + threadIdx.x;
        const float* src;
        switch (wi) {
            case 0: src = w0; break;  case 1: src = w1; break;
            case 2: src = w2; break;  case 3: src = w3; break;
            case 4: src = w4; break;  case 5: src = w5; break;
            case 6: src = w6; break;  default: src = w7; break;
        }
        const size_t o = (size_t)wi * (INNER * INNER / 4) + i;
        float4 v = ((const float4*)src)[i];
        uint32_t h01, l01, h23, l23;
        split2(v.x, v.y, h01, l01);
        split2(v.z, v.w, h23, l23);
        ((uint2*)w_h)[o] = make_uint2(h01, h23);
        ((uint2*)w_l)[o] = make_uint2(l01, l23);
    } else if (bx < 16384) {
        const int i = (bx - 8192) * 256 + threadIdx.x;
        float4 v = ((const float4*)hs)[i];
        uint32_t h01, l01, h23, l23;
        split2(v.x, v.y, h01, l01);
        split2(v.z, v.w, h23, l23);
        ((uint2*)hs_h)[i] = make_uint2(h01, h23);
        ((uint2*)hs_l)[i] = make_uint2(l01, l23);
    } else {
        const int i = (bx - 16384) * 256 + threadIdx.x;   // 256 blocks
        float4 v = ((const float4*)enc)[i];
        uint32_t h01, l01, h23, l23;
        split2(v.x, v.y, h01, l01);
        split2(v.z, v.w, h23, l23);
        ((uint2*)enc_h)[i] = make_uint2(h01, h23);
        ((uint2*)enc_l)[i] = make_uint2(l01, l23);
    }
}

// ---------------------------------------------------------------------------
// GEMM v1: bf16x3 NT GEMM, 128x128 CTA, 256 threads, 2 CTAs/SM, 2-stage
// ---------------------------------------------------------------------------
#define PADK 40
#define GT_TILE  (128 * PADK)
#define GT_STAGE (4 * GT_TILE)
#define GEMM1_SMEM_BYTES (2 * GT_STAGE * 2)

__global__ void __launch_bounds__(256, 2)
gemm_bf3_kernel(const __nv_bfloat16* __restrict__ Ah, const __nv_bfloat16* __restrict__ Al,
                const __nv_bfloat16* __restrict__ Wh, const __nv_bfloat16* __restrict__ Wl,
                const float* __restrict__ bias, float* __restrict__ C,
                int M, int N, int K)
{
    extern __shared__ __nv_bfloat16 sm[];
    const int t    = threadIdx.x;
    const int lane = t & 31;
    const int wid  = t >> 5;
    const int wm   = wid >> 1;
    const int wn   = wid & 1;
    const int m0   = blockIdx.y * 128;
    const int n0   = blockIdx.x * 128;

    float acc[2][8][4];
#pragma unroll
    for (int i = 0; i < 2; i++)
#pragma unroll
        for (int j = 0; j < 8; j++)
#pragma unroll
            for (int q = 0; q < 4; q++) acc[i][j][q] = 0.f;

    const int tile = t >> 6;
    const int l64  = t & 63;
    const int lrr  = l64 >> 2;
    const int lcc  = (l64 & 3) * 8;
    const __nv_bfloat16* gsrc =
        (tile == 0) ? Ah : (tile == 1) ? Al : (tile == 2) ? Wh : Wl;
    const int rowbase = (tile < 2) ? m0 : n0;
    const uint32_t smb = smem_u32(sm);
    const uint32_t sdst0 = smb + ((tile * GT_TILE + lrr * PADK + lcc) << 1);
    const __nv_bfloat16* gp = gsrc + (size_t)(rowbase + lrr) * K + lcc;

    const uint32_t abase_rel = (((wm * 32 + (lane & 15)) * PADK + ((lane >> 4) << 3)) << 1);
    const uint32_t bbase_rel = ((2 * GT_TILE +
                     (wn * 64 + (lane & 7) + ((lane >> 4) << 3)) * PADK +
                     (((lane >> 3) & 1) << 3)) << 1);

    const int NT = K / 32;

    {
        const __nv_bfloat16* g = gp;
#pragma unroll
        for (int i = 0; i < 8; i++)
            CP_ASYNC16(sdst0 + (uint32_t)((i * 16 * PADK) << 1),
                       g + (size_t)(i * 16) * K);
        CP_COMMIT();
    }

    for (int kt = 0; kt < NT; kt++) {
        const int b = kt & 1;
        if (kt + 1 < NT) {
            const __nv_bfloat16* g = gp + (kt + 1) * 32;
            const uint32_t d = sdst0 + (uint32_t)((((kt + 1) & 1) * GT_STAGE) << 1);
#pragma unroll
            for (int i = 0; i < 8; i++)
                CP_ASYNC16(d + (uint32_t)((i * 16 * PADK) << 1),
                           g + (size_t)(i * 16) * K);
            CP_COMMIT();
            CP_WAIT1();
        } else {
            CP_WAIT0();
        }
        __syncthreads();

        const uint32_t stage  = smb + (uint32_t)((b * GT_STAGE) << 1);
        const uint32_t abaseh = stage + abase_rel;
        const uint32_t abasel = abaseh + (GT_TILE << 1);
        const uint32_t bbaseh = stage + bbase_rel;
        const uint32_t bbasel = bbaseh + (GT_TILE << 1);

#pragma unroll
        for (int ks = 0; ks < 32; ks += 16) {
            uint32_t a0h[4], a1h[4], a0l[4], a1l[4];
            ldsm_x4(a0h, abaseh + ks * 2);
            ldsm_x4(a1h, abaseh + ks * 2 + 16 * PADK * 2);
            ldsm_x4(a0l, abasel + ks * 2);
            ldsm_x4(a1l, abasel + ks * 2 + 16 * PADK * 2);
#pragma unroll
            for (int nbp = 0; nbp < 4; nbp++) {
                uint32_t bh[4], bl[4];
                ldsm_x4(bh, bbaseh + ks * 2 + nbp * 16 * PADK * 2);
                ldsm_x4(bl, bbasel + ks * 2 + nbp * 16 * PADK * 2);
                mma16816(acc[0][2 * nbp],     a0h, bh);
                mma16816(acc[0][2 * nbp + 1], a0h, bh + 2);
                mma16816(acc[1][2 * nbp],     a1h, bh);
                mma16816(acc[1][2 * nbp + 1], a1h, bh + 2);
                mma16816(acc[0][2 * nbp],     a0h, bl);
                mma16816(acc[0][2 * nbp + 1], a0h, bl + 2);
                mma16816(acc[1][2 * nbp],     a1h, bl);
                mma16816(acc[1][2 * nbp + 1], a1h, bl + 2);
                mma16816(acc[0][2 * nbp],     a0l, bh);
                mma16816(acc[0][2 * nbp + 1], a0l, bh + 2);
                mma16816(acc[1][2 * nbp],     a1l, bh);
                mma16816(acc[1][2 * nbp + 1], a1l, bh + 2);
            }
        }
        __syncthreads();
    }

    const int r0 = m0 + wm * 32 + (lane >> 2);
    const int c0 = n0 + wn * 64 + (lane & 3) * 2;
#pragma unroll
    for (int mi = 0; mi < 2; mi++) {
        const int r = r0 + mi * 16;
#pragma unroll
        for (int nb = 0; nb < 8; nb++) {
            const int c = c0 + nb * 8;
            float b0 = 0.f, b1 = 0.f;
            if (bias) { b0 = bias[c]; b1 = bias[c + 1]; }
            *(float2*)(C + (size_t)r * N + c) =
                make_float2(acc[mi][nb][0] + b0, acc[mi][nb][1] + b1);
            *(float2*)(C + (size_t)(r + 8) * N + c) =
                make_float2(acc[mi][nb][2] + b0, acc[mi][nb][3] + b1);
        }
    }
}

// ---------------------------------------------------------------------------
// GEMM v2: 256x128 CTA, 512 threads, 3-stage, K-split (for small-M GEMMs)
// ---------------------------------------------------------------------------
#define V2_TILE_A (256 * PADK)
#define V2_TILE_W (128 * PADK)
#define V2_STAGE (2 * V2_TILE_A + 2 * V2_TILE_W)
#define GEMM2_SMEM_BYTES (3 * V2_STAGE * 2)

__global__ void __launch_bounds__(512, 1)
gemm_v2_kernel(const __nv_bfloat16* __restrict__ Ah, const __nv_bfloat16* __restrict__ Al,
               const __nv_bfloat16* __restrict__ Wh, const __nv_bfloat16* __restrict__ Wl,
               float* __restrict__ C, int M, int N, int K, int kparts)
{
    extern __shared__ __nv_bfloat16 sm[];
    const int t    = threadIdx.x;
    const int lane = t & 31;
    const int wid  = t >> 5;
    const int wm   = wid >> 1;
    const int wn   = wid & 1;
    const int m0   = blockIdx.y * 256;
    const int n0   = blockIdx.x * 128;

    const int KC    = K / kparts;
    const int kbase = blockIdx.z * KC;
    const int NT    = KC / 32;

    float acc[2][8][4];
#pragma unroll
    for (int i = 0; i < 2; i++)
#pragma unroll
        for (int j = 0; j < 8; j++)
#pragma unroll
            for (int q = 0; q < 4; q++) acc[i][j][q] = 0.f;

    const int rr = t >> 2;
    const int cc = (t & 3) * 8;
    const uint32_t smb = smem_u32(sm);

    const __nv_bfloat16* pA0 = Ah + (size_t)(m0 + rr)       * K + kbase + cc;
    const __nv_bfloat16* pA1 = Ah + (size_t)(m0 + rr + 128) * K + kbase + cc;
    const __nv_bfloat16* pL0 = Al + (size_t)(m0 + rr)       * K + kbase + cc;
    const __nv_bfloat16* pL1 = Al + (size_t)(m0 + rr + 128) * K + kbase + cc;
    const __nv_bfloat16* pWh = Wh + (size_t)(n0 + rr)       * K + kbase + cc;
    const __nv_bfloat16* pWl = Wl + (size_t)(n0 + rr)       * K + kbase + cc;

    const uint32_t dA0 = (uint32_t)((rr * PADK + cc) << 1);
    const uint32_t dA1 = (uint32_t)(((rr + 128) * PADK + cc) << 1);
    const uint32_t dL0 = dA0 + (uint32_t)(V2_TILE_A << 1);
    const uint32_t dL1 = dA1 + (uint32_t)(V2_TILE_A << 1);
    const uint32_t dWh = dA0 + (uint32_t)((2 * V2_TILE_A) << 1);
    const uint32_t dWl = dA0 + (uint32_t)(((2 * V2_TILE_A) + V2_TILE_W) << 1);

#define V2_LOAD(kt, stg) do {                                              \
    const uint32_t sb = smb + (uint32_t)(((stg) * V2_STAGE) << 1);         \
    const int ko = (kt) * 32;                                              \
    CP_ASYNC16(sb + dA0, pA0 + ko);                                        \
    CP_ASYNC16(sb + dA1, pA1 + ko);                                        \
    CP_ASYNC16(sb + dL0, pL0 + ko);                                        \
    CP_ASYNC16(sb + dL1, pL1 + ko);                                        \
    CP_ASYNC16(sb + dWh, pWh + ko);                                        \
    CP_ASYNC16(sb + dWl, pWl + ko);                                        \
    CP_COMMIT();                                                           \
} while (0)

    V2_LOAD(0, 0);
    V2_LOAD(1, 1);

    const uint32_t abase_rel = (uint32_t)((((wm * 32 + (lane & 15)) * PADK +
                                            ((lane >> 4) << 3))) << 1);
    const uint32_t bbase_rel = (uint32_t)(((2 * V2_TILE_A +
                     (wn * 64 + (lane & 7) + ((lane >> 4) << 3)) * PADK +
                     (((lane >> 3) & 1) << 3))) << 1);

    int stg = 0;
    for (int kt = 0; kt < NT; kt++) {
        if (kt + 2 < NT) {
            const int ps = (stg + 2 >= 3) ? (stg - 1) : (stg + 2);
            V2_LOAD(kt + 2, ps);
            CP_WAIT2();
        } else {
            CP_WAIT0();
        }
        __syncthreads();

        const uint32_t stage  = smb + (uint32_t)((stg * V2_STAGE) << 1);
        const uint32_t abaseh = stage + abase_rel;
        const uint32_t abasel = abaseh + (uint32_t)(V2_TILE_A << 1);
        const uint32_t bbaseh = stage + bbase_rel;
        const uint32_t bbasel = bbaseh + (uint32_t)(V2_TILE_W << 1);

#pragma unroll
        for (int ks = 0; ks < 32; ks += 16) {
            uint32_t a0h[4], a1h[4], a0l[4], a1l[4];
            ldsm_x4(a0h, abaseh + ks * 2);
            ldsm_x4(a1h, abaseh + ks * 2 + 16 * PADK * 2);
            ldsm_x4(a0l, abasel + ks * 2);
            ldsm_x4(a1l, abasel + ks * 2 + 16 * PADK * 2);
#pragma unroll
            for (int nbp = 0; nbp < 4; nbp++) {
                uint32_t bh[4], bl[4];
                ldsm_x4(bh, bbaseh + ks * 2 + nbp * 16 * PADK * 2);
                ldsm_x4(bl, bbasel + ks * 2 + nbp * 16 * PADK * 2);
                mma16816(acc[0][2 * nbp],     a0h, bh);
                mma16816(acc[0][2 * nbp + 1], a0h, bh + 2);
                mma16816(acc[1][2 * nbp],     a1h, bh);
                mma16816(acc[1][2 * nbp + 1], a1h, bh + 2);
                mma16816(acc[0][2 * nbp],     a0h, bl);
                mma16816(acc[0][2 * nbp + 1], a0h, bl + 2);
                mma16816(acc[1][2 * nbp],     a1h, bl);
                mma16816(acc[1][2 * nbp + 1], a1h, bl + 2);
                mma16816(acc[0][2 * nbp],     a0l, bh);
                mma16816(acc[0][2 * nbp + 1], a0l, bh + 2);
                mma16816(acc[1][2 * nbp],     a1l, bh);
                mma16816(acc[1][2 * nbp + 1], a1l, bh + 2);
            }
        }
        __syncthreads();
        stg = (stg + 1 >= 3) ? 0 : (stg + 1);
    }

    float* Cz = C + (size_t)blockIdx.z * M * N;
    const int r0 = m0 + wm * 32 + (lane >> 2);
    const int c0 = n0 + wn * 64 + (lane & 3) * 2;
#pragma unroll
    for (int mi = 0; mi < 2; mi++) {
        const int r = r0 + mi * 16;
#pragma unroll
        for (int nb = 0; nb < 8; nb++) {
            const int c = c0 + nb * 8;
            *(float2*)(Cz + (size_t)r * N + c) =
                make_float2(acc[mi][nb][0], acc[mi][nb][1]);
            *(float2*)(Cz + (size_t)(r + 8) * N + c) =
                make_float2(acc[mi][nb][2], acc[mi][nb][3]);
        }
    }
}

// ---------------------------------------------------------------------------
// K-split reduce for txt output GEMM (with bias)
// ---------------------------------------------------------------------------
__global__ void __launch_bounds__(256)
reduce4_kernel(const float* __restrict__ part, const float* __restrict__ bias,
               float* __restrict__ out, int MN, int N)
{
    const int i = blockIdx.x * 256 + threadIdx.x;
    if (i * 4 >= MN) return;
    const int q = MN / 4;
    float4 a = ((const float4*)part)[i];
    float4 b = ((const float4*)part)[i + q];
    float4 c = ((const float4*)part)[i + 2 * q];
    float4 d = ((const float4*)part)[i + 3 * q];
    float4 r = make_float4(a.x + b.x + c.x + d.x, a.y + b.y + c.y + d.y,
                           a.z + b.z + c.z + d.z, a.w + b.w + c.w + d.w);
    if (bias) {
        const int col = (i * 4) % N;
        r.x += bias[col];  r.y += bias[col + 1];
        r.z += bias[col + 2];  r.w += bias[col + 3];
    }
    ((float4*)out)[i] = r;
}

// ---------------------------------------------------------------------------
// RMSNorm + RoPE + sparse scatter (visual)
// ---------------------------------------------------------------------------
__global__ void __launch_bounds__(256)
qkv_post_kernel(const float* __restrict__ qkv,
                const float* __restrict__ gq, const float* __restrict__ gk,
                const float* __restrict__ cosb, const float* __restrict__ sinb,
                __nv_bfloat16* __restrict__ QAh, __nv_bfloat16* __restrict__ QAl,
                __nv_bfloat16* __restrict__ KAh, __nv_bfloat16* __restrict__ KAl,
                __nv_bfloat16* __restrict__ VAh, __nv_bfloat16* __restrict__ VAl)
{
    const int warp = (blockIdx.x * blockDim.x + threadIdx.x) >> 5;
    const int lane = threadIdx.x & 31;
    const int s = warp >> 4;
    const int h = warp & 15;
    if (s >= S_LEN) return;

    const size_t src = (size_t)s * INNER3 + h * HEAD_DIM;
    float q0 = qkv[src + lane],            q1 = qkv[src + lane + 32];
    float k0 = qkv[src + INNER + lane],    k1 = qkv[src + INNER + lane + 32];
    float v0 = qkv[src + 2*INNER + lane],  v1 = qkv[src + 2*INNER + lane + 32];

    float rq = rsqrtf(warp_sum32(q0 * q0 + q1 * q1) * (1.f / HEAD_DIM) + EPS_RMS);
    float rk = rsqrtf(warp_sum32(k0 * k0 + k1 * k1) * (1.f / HEAD_DIM) + EPS_RMS);

    q0 *= rq * gq[lane];  q1 *= rq * gq[lane + 32];
    k0 *= rk * gk[lane];  k1 *= rk * gk[lane + 32];

    const float c0 = cosb[(size_t)s * HEAD_DIM + lane];
    const float c1 = cosb[(size_t)s * HEAD_DIM + lane + 32];
    const float s0 = sinb[(size_t)s * HEAD_DIM + lane];
    const float s1 = sinb[(size_t)s * HEAD_DIM + lane + 32];

    const float oq0 = (q0 * c0 - q1 * s0) * ATTN_SCALE;
    const float oq1 = (q1 * c1 + q0 * s1) * ATTN_SCALE;
    const float ok0 = k0 * c0 - k1 * s0;
    const float ok1 = k1 * c1 + k0 * s1;

    const int j = s & 7, tt = s >> 3;
    const size_t dst = (((size_t)(j * NUM_HEADS + h)) * STOT + tt) * HEAD_DIM;
    store_split(QAh, QAl, dst + lane,      oq0);
    store_split(QAh, QAl, dst + lane + 32, oq1);
    store_split(KAh, KAl, dst + lane,      ok0);
    store_split(KAh, KAl, dst + lane + 32, ok1);
    store_split(VAh, VAl, dst + lane,      v0);
    store_split(VAh, VAl, dst + lane + 32, v1);
}

// ---------------------------------------------------------------------------
// RMSNorm + broadcast scatter (text), reads 4 K-split partials directly
// ---------------------------------------------------------------------------
__global__ void __launch_bounds__(256)
enc_post_kernel(const float* __restrict__ part,
                const float* __restrict__ gaq, const float* __restrict__ gak,
                __nv_bfloat16* __restrict__ QAh, __nv_bfloat16* __restrict__ QAl,
                __nv_bfloat16* __restrict__ KAh, __nv_bfloat16* __restrict__ KAl,
                __nv_bfloat16* __restrict__ VAh, __nv_bfloat16* __restrict__ VAl)
{
    const int warp = (blockIdx.x * blockDim.x + threadIdx.x) >> 5;
    const int lane = threadIdx.x & 31;
    const int tt = warp >> 4;
    const int h  = warp & 15;
    if (tt >= T_LEN) return;

    const size_t src = (size_t)tt * INNER3 + h * HEAD_DIM;
    const size_t PQ = (size_t)T_LEN * INNER3;
    float a0 = 0.f, a1 = 0.f, b0 = 0.f, b1 = 0.f, v0 = 0.f, v1 = 0.f;
#pragma unroll
    for (int z = 0; z < 4; z++) {
        const float* p = part + z * PQ + src;
        a0 += p[lane];              a1 += p[lane + 32];
        b0 += p[INNER + lane];      b1 += p[INNER + lane + 32];
        v0 += p[2*INNER + lane];    v1 += p[2*INNER + lane + 32];
    }

    float ra = rsqrtf(warp_sum32(a0 * a0 + a1 * a1) * (1.f / HEAD_DIM) + EPS_RMS);
    float rb = rsqrtf(warp_sum32(b0 * b0 + b1 * b1) * (1.f / HEAD_DIM) + EPS_RMS);

    a0 *= ra * gaq[lane] * ATTN_SCALE;  a1 *= ra * gaq[lane + 32] * ATTN_SCALE;
    b0 *= rb * gak[lane];               b1 *= rb * gak[lane + 32];

#pragma unroll
    for (int j = 0; j < SPARSE_N; j++) {
        const size_t dst =
            (((size_t)(j * NUM_HEADS + h)) * STOT + G_LEN + tt) * HEAD_DIM;
        store_split(QAh, QAl, dst + lane,      a0);
        store_split(QAh, QAl, dst + lane + 32, a1);
        store_split(KAh, KAl, dst + lane,      b0);
        store_split(KAh, KAl, dst + lane + 32, b1);
        store_split(VAh, VAl, dst + lane,      v0);
        store_split(VAh, VAl, dst + lane + 32, v1);
    }
}

// ---------------------------------------------------------------------------
// Flash attention, BQ=256, 512 threads, cp.async K/V double buffering.
// Visual q-tiles (blockIdx.x < 4) write bf16 hi/lo directly to vis buffers
// (fused gather); text q-tile (blockIdx.x == 4) writes fp32 OA.
// ---------------------------------------------------------------------------
#define APAD 72
#define AQ_ELEMS (2 * 256 * APAD)
#define KV_TILE  (64 * APAD)
#define KV_STAGE (4 * KV_TILE)
#define ATT_SM_BYTES ((AQ_ELEMS + 2 * KV_STAGE) * 2)

__global__ void __launch_bounds__(512, 1)
attn_mma_kernel(const __nv_bfloat16* __restrict__ Qhg, const __nv_bfloat16* __restrict__ Qlg,
                const __nv_bfloat16* __restrict__ Khg, const __nv_bfloat16* __restrict__ Klg,
                const __nv_bfloat16* __restrict__ Vhg, const __nv_bfloat16* __restrict__ Vlg,
                float* __restrict__ OA,
                __nv_bfloat16* __restrict__ vis_h, __nv_bfloat16* __restrict__ vis_l)
{
    extern __shared__ __nv_bfloat16 smA[];
    const int t    = threadIdx.x;
    const int lane = t & 31;
    const int w    = t >> 5;
    const int jh   = blockIdx.y;
    const int q0   = blockIdx.x * 256;
    const size_t base = (size_t)jh * STOT * HEAD_DIM;

    const uint32_t smb = smem_u32(smA);

    const int tile = t >> 7;
    const int l128 = t & 127;
    const int krr  = l128 >> 3;
    const int kcc  = (l128 & 7) * 8;
    const __nv_bfloat16* kvsrc =
        (tile == 0) ? Khg : (tile == 1) ? Klg : (tile == 2) ? Vhg : Vlg;
    const uint32_t kvdst0 = smb + ((AQ_ELEMS + tile * KV_TILE + krr * APAD + kcc) << 1);

    {
        const __nv_bfloat16* g = kvsrc + base + (size_t)krr * 64 + kcc;
#pragma unroll
        for (int i = 0; i < 4; i++)
            CP_ASYNC16(kvdst0 + (uint32_t)((i * 16 * APAD) << 1),
                       g + (size_t)(i * 16) * 64);
        CP_COMMIT();
    }

    {
        const int row = t >> 1, c0 = (t & 1) * 32;
        const __nv_bfloat16* gh = Qhg + base + (size_t)(q0 + row) * 64 + c0;
        const __nv_bfloat16* gl = Qlg + base + (size_t)(q0 + row) * 64 + c0;
        __nv_bfloat16* sh = smA + row * APAD + c0;
        __nv_bfloat16* sl = smA + 256 * APAD + row * APAD + c0;
#pragma unroll
        for (int c = 0; c < 32; c += 8) {
            *(uint4*)(sh + c) = *(const uint4*)(gh + c);
            *(uint4*)(sl + c) = *(const uint4*)(gl + c);
        }
    }

    float o[8][4];
#pragma unroll
    for (int i = 0; i < 8; i++)
#pragma unroll
        for (int j = 0; j < 4; j++) o[i][j] = 0.f;
    float m0r = -1e30f, m1r = -1e30f, l0r = 0.f, l1r = 0.f;

    const uint32_t qfragh = smb + (((w * 16 + (lane & 15)) * APAD + ((lane >> 4) << 3)) << 1);
    const uint32_t qfragl = qfragh + ((256 * APAD) << 1);
    const uint32_t kfrag_rel = ((((lane & 7) + ((lane >> 4) << 3)) * APAD + (((lane >> 3) & 1) << 3)) << 1);
    const uint32_t vfrag_rel = (((2 * KV_TILE) + ((lane & 7) + (((lane >> 3) & 1) << 3)) * APAD + ((lane >> 4) << 3)) << 1);

    for (int kt = 0; kt < 20; kt++) {
        const int b = kt & 1;
        if (kt + 1 < 20) {
            const __nv_bfloat16* g = kvsrc + base + (size_t)((kt + 1) * 64 + krr) * 64 + kcc;
            const uint32_t d = kvdst0 + (uint32_t)((((kt + 1) & 1) * KV_STAGE) << 1);
#pragma unroll
            for (int i = 0; i < 4; i++)
                CP_ASYNC16(d + (uint32_t)((i * 16 * APAD) << 1),
                           g + (size_t)(i * 16) * 64);
            CP_COMMIT();
            CP_WAIT1();
        } else {
            CP_WAIT0();
        }
        __syncthreads();

        const uint32_t kvstage = smb + (uint32_t)(((AQ_ELEMS + b * KV_STAGE)) << 1);
        const uint32_t kfragh = kvstage + kfrag_rel;
        const uint32_t kfragl = kfragh + (KV_TILE << 1);
        const uint32_t vfrag  = kvstage + vfrag_rel;

        float s[8][4];
#pragma unroll
        for (int i = 0; i < 8; i++)
#pragma unroll
            for (int j = 0; j < 4; j++) s[i][j] = 0.f;

#pragma unroll
        for (int ks = 0; ks < 64; ks += 16) {
            uint32_t ah[4], al[4];
            ldsm_x4(ah, qfragh + ks * 2);
            ldsm_x4(al, qfragl + ks * 2);
#pragma unroll
            for (int nbp = 0; nbp < 4; nbp++) {
                uint32_t kh[4], kl[4];
                ldsm_x4(kh, kfragh + ks * 2 + nbp * 16 * APAD * 2);
                ldsm_x4(kl, kfragl + ks * 2 + nbp * 16 * APAD * 2);
                mma16816(s[2 * nbp],     ah, kh);
                mma16816(s[2 * nbp + 1], ah, kh + 2);
                mma16816(s[2 * nbp],     ah, kl);
                mma16816(s[2 * nbp + 1], ah, kl + 2);
                mma16816(s[2 * nbp],     al, kh);
                mma16816(s[2 * nbp + 1], al, kh + 2);
            }
        }

        float mt0 = -1e30f, mt1 = -1e30f;
#pragma unroll
        for (int nb = 0; nb < 8; nb++) {
            mt0 = fmaxf(mt0, fmaxf(s[nb][0], s[nb][1]));
            mt1 = fmaxf(mt1, fmaxf(s[nb][2], s[nb][3]));
        }
        mt0 = fmaxf(mt0, __shfl_xor_sync(0xffffffffu, mt0, 1));
        mt0 = fmaxf(mt0, __shfl_xor_sync(0xffffffffu, mt0, 2));
        mt1 = fmaxf(mt1, __shfl_xor_sync(0xffffffffu, mt1, 1));
        mt1 = fmaxf(mt1, __shfl_xor_sync(0xffffffffu, mt1, 2));
        const float mn0 = fmaxf(m0r, mt0), mn1 = fmaxf(m1r, mt1);
        const float cf0 = __expf(m0r - mn0), cf1 = __expf(m1r - mn1);
        m0r = mn0;  m1r = mn1;
        float rs0 = 0.f, rs1 = 0.f;
#pragma unroll
        for (int nb = 0; nb < 8; nb++) {
            s[nb][0] = __expf(s[nb][0] - mn0);  rs0 += s[nb][0];
            s[nb][1] = __expf(s[nb][1] - mn0);  rs0 += s[nb][1];
            s[nb][2] = __expf(s[nb][2] - mn1);  rs1 += s[nb][2];
            s[nb][3] = __expf(s[nb][3] - mn1);  rs1 += s[nb][3];
        }
        rs0 += __shfl_xor_sync(0xffffffffu, rs0, 1);
        rs0 += __shfl_xor_sync(0xffffffffu, rs0, 2);
        rs1 += __shfl_xor_sync(0xffffffffu, rs1, 1);
        rs1 += __shfl_xor_sync(0xffffffffu, rs1, 2);
        l0r = l0r * cf0 + rs0;
        l1r = l1r * cf1 + rs1;
#pragma unroll
        for (int db = 0; db < 8; db++) {
            o[db][0] *= cf0;  o[db][1] *= cf0;
            o[db][2] *= cf1;  o[db][3] *= cf1;
        }

#pragma unroll
        for (int kb2 = 0; kb2 < 4; kb2++) {
            uint32_t ph[4], pl[4];
            split2(s[2 * kb2][0],     s[2 * kb2][1],     ph[0], pl[0]);
            split2(s[2 * kb2][2],     s[2 * kb2][3],     ph[1], pl[1]);
            split2(s[2 * kb2 + 1][0], s[2 * kb2 + 1][1], ph[2], pl[2]);
            split2(s[2 * kb2 + 1][2], s[2 * kb2 + 1][3], ph[3], pl[3]);
            const uint32_t vb = vfrag + kb2 * 16 * APAD * 2;
#pragma unroll
            for (int dbp = 0; dbp < 4; dbp++) {
                uint32_t vh4[4], vl4[4];
                ldsm_x4_t(vh4, vb + dbp * 16 * 2);
                ldsm_x4_t(vl4, vb + (KV_TILE << 1) + dbp * 16 * 2);
                mma16816(o[2 * dbp],     ph, vh4);
                mma16816(o[2 * dbp + 1], ph, vh4 + 2);
                mma16816(o[2 * dbp],     ph, vl4);
                mma16816(o[2 * dbp + 1], ph, vl4 + 2);
                mma16816(o[2 * dbp],     pl, vh4);
                mma16816(o[2 * dbp + 1], pl, vh4 + 2);
            }
        }
        __syncthreads();
    }

    const float inv0 = 1.f / l0r, inv1 = 1.f / l1r;
    const int row = q0 + w * 16 + (lane >> 2);
    const int col = (lane & 3) * 2;
    if (blockIdx.x < 4) {
        // fused gather: vis row s = row*8 + j, elem e = h*64 + d
        const int j = jh >> 4, h = jh & 15;
        uint32_t* vh32 = (uint32_t*)vis_h;
        uint32_t* vl32 = (uint32_t*)vis_l;
        const size_t b0 = ((size_t)row * 8 + j) * INNER + h * 64;
        const size_t b1 = ((size_t)(row + 8) * 8 + j) * INNER + h * 64;
#pragma unroll
        for (int db = 0; db < 8; db++) {
            uint32_t hi, lo;
            split2(o[db][0] * inv0, o[db][1] * inv0, hi, lo);
            vh32[(b0 + db * 8 + col) >> 1] = hi;
            vl32[(b0 + db * 8 + col) >> 1] = lo;
            split2(o[db][2] * inv1, o[db][3] * inv1, hi, lo);
            vh32[(b1 + db * 8 + col) >> 1] = hi;
            vl32[(b1 + db * 8 + col) >> 1] = lo;
        }
    } else {
#pragma unroll
        for (int db = 0; db < 8; db++) {
            *(float2*)(OA + base + (size_t)row * 64 + db * 8 + col) =
                make_float2(o[db][0] * inv0, o[db][1] * inv0);
            *(float2*)(OA + base + (size_t)(row + 8) * 64 + db * 8 + col) =
                make_float2(o[db][2] * inv1, o[db][3] * inv1);
        }
    }
}

// ---------------------------------------------------------------------------
// Gather text rows -> bf16 hi/lo (mean over j)
// ---------------------------------------------------------------------------
__global__ void __launch_bounds__(256)
gather_txt_kernel(const float* __restrict__ OA,
                  __nv_bfloat16* __restrict__ th, __nv_bfloat16* __restrict__ tl)
{
    const int i = blockIdx.x * 256 + threadIdx.x;
    const int idx = i * 4;
    const int tt = idx >> 10, e = idx & 1023;
    const int h = e >> 6, d = e & 63;
    float4 acc = make_float4(0.f, 0.f, 0.f, 0.f);
#pragma unroll
    for (int j = 0; j < SPARSE_N; j++) {
        float4 v = *(const float4*)(OA +
            (((size_t)(j * NUM_HEADS + h)) * STOT + G_LEN + tt) * HEAD_DIM + d);
        acc.x += v.x; acc.y += v.y; acc.z += v.z; acc.w += v.w;
    }
    acc.x *= 0.125f; acc.y *= 0.125f; acc.z *= 0.125f; acc.w *= 0.125f;
    uint32_t h01, l01, h23, l23;
    split2(acc.x, acc.y, h01, l01);
    split2(acc.z, acc.w, h23, l23);
    ((uint2*)th)[i] = make_uint2(h01, h23);
    ((uint2*)tl)[i] = make_uint2(l01, l23);
}

// ---------------------------------------------------------------------------
// kernel_launch
// ---------------------------------------------------------------------------
extern "C" void kernel_launch(void* const* d_in, const int* in_sizes, int n_in,
                              void* d_out, int out_size)
{
    const float* hs   = (const float*)d_in[0];
    const float* enc  = (const float*)d_in[1];
    const float* bout  = (const float*)d_in[9];
    const float* baout = (const float*)d_in[11];
    const float* gq   = (const float*)d_in[12];
    const float* gk   = (const float*)d_in[13];
    const float* gaq  = (const float*)d_in[14];
    const float* gak  = (const float*)d_in[15];
    const float* rc   = (const float*)d_in[16];
    const float* rs   = (const float*)d_in[17];
    float* out = (float*)d_out;

    float *qkvraw, *encpart, *txtpart, *OA;
    __nv_bfloat16 *hs_h, *hs_l, *enc_h, *enc_l, *w_h, *w_l;
    __nv_bfloat16 *vis_h, *vis_l, *txt_h, *txt_l;
    __nv_bfloat16 *QAh, *QAl, *KAh, *KAl, *VAh, *VAl;
    cudaGetSymbolAddress((void**)&qkvraw,  g_qkvraw);
    cudaGetSymbolAddress((void**)&encpart, g_encpart);
    cudaGetSymbolAddress((void**)&txtpart, g_txtpart);
    cudaGetSymbolAddress((void**)&OA,    g_OA);
    cudaGetSymbolAddress((void**)&hs_h,  g_hs_h);
    cudaGetSymbolAddress((void**)&hs_l,  g_hs_l);
    cudaGetSymbolAddress((void**)&enc_h, g_enc_h);
    cudaGetSymbolAddress((void**)&enc_l, g_enc_l);
    cudaGetSymbolAddress((void**)&w_h,   g_w_h);
    cudaGetSymbolAddress((void**)&w_l,   g_w_l);
    cudaGetSymbolAddress((void**)&vis_h, g_vis_h);
    cudaGetSymbolAddress((void**)&vis_l, g_vis_l);
    cudaGetSymbolAddress((void**)&txt_h, g_txt_h);
    cudaGetSymbolAddress((void**)&txt_l, g_txt_l);
    cudaGetSymbolAddress((void**)&QAh,   g_QAh);
    cudaGetSymbolAddress((void**)&QAl,   g_QAl);
    cudaGetSymbolAddress((void**)&KAh,   g_KAh);
    cudaGetSymbolAddress((void**)&KAl,   g_KAl);
    cudaGetSymbolAddress((void**)&VAh,   g_VAh);
    cudaGetSymbolAddress((void**)&VAl,   g_VAl);

    cudaFuncSetAttribute(gemm_bf3_kernel,
                         cudaFuncAttributeMaxDynamicSharedMemorySize, GEMM1_SMEM_BYTES);
    cudaFuncSetAttribute(gemm_v2_kernel,
                         cudaFuncAttributeMaxDynamicSharedMemorySize, GEMM2_SMEM_BYTES);
    cudaFuncSetAttribute(attn_mma_kernel,
                         cudaFuncAttributeMaxDynamicSharedMemorySize, ATT_SM_BYTES);

    const size_t WS = (size_t)INNER * INNER;

    // [0] all conversions (weights + hs + enc) — enc segment now 256 blocks
    cvt_all_kernel<<<16640, 256>>>(
        (const float*)d_in[2], (const float*)d_in[3], (const float*)d_in[4],
        (const float*)d_in[5], (const float*)d_in[6], (const float*)d_in[7],
        (const float*)d_in[8], (const float*)d_in[10], hs, enc,
        w_h, w_l, hs_h, hs_l, enc_h, enc_l);

    // [1] big QKV GEMM (v1)
    gemm_bf3_kernel<<<dim3(INNER3 / 128, S_LEN / 128), 256, GEMM1_SMEM_BYTES>>>(
        hs_h, hs_l, w_h + 0 * WS, w_l + 0 * WS, nullptr, qkvraw, S_LEN, INNER3, INNER);

    // [2] enc QKV GEMM (v2, K-split x4)
    gemm_v2_kernel<<<dim3(INNER3 / 128, 1, 4), 512, GEMM2_SMEM_BYTES>>>(
        enc_h, enc_l, w_h + 3 * WS, w_l + 3 * WS, encpart, T_LEN, INNER3, INNER, 4);

    // [3] enc post (fused 4-partial reduce)
    enc_post_kernel<<<(T_LEN * NUM_HEADS) / 8, 256>>>(
        encpart, gaq, gak, QAh, QAl, KAh, KAl, VAh, VAl);

    // [4] visual post
    qkv_post_kernel<<<(S_LEN * NUM_HEADS) / 8, 256>>>(
        qkvraw, gq, gk, rc, rs, QAh, QAl, KAh, KAl, VAh, VAl);

    // [5] attention (fused vis gather)  <- profiled launch
    attn_mma_kernel<<<dim3(STOT / 256, NJH), 512, ATT_SM_BYTES>>>(
        QAh, QAl, KAh, KAl, VAh, VAl, OA, vis_h, vis_l);

    // [6] text gather
    gather_txt_kernel<<<(T_LEN * INNER / 4) / 256, 256>>>(OA, txt_h, txt_l);

    // [7] vis out GEMM (v1)
    gemm_bf3_kernel<<<dim3(INNER / 128, S_LEN / 128), 256, GEMM1_SMEM_BYTES>>>(
        vis_h, vis_l, w_h + 6 * WS, w_l + 6 * WS, bout, out, S_LEN, INNER, INNER);

    // [8] txt out GEMM (v2, K-split x4), [9] reduce with bias
    gemm_v2_kernel<<<dim3(INNER / 128, 1, 4), 512, GEMM2_SMEM_BYTES>>>(
        txt_h, txt_l, w_h + 7 * WS, w_l + 7 * WS, txtpart, T_LEN, INNER, INNER, 4);
    reduce4_kernel<<<(T_LEN * INNER / 4) / 256, 256>>>(
        txtpart, baout, out + (size_t)S_LEN * INNER, T_LEN * INNER, INNER);
}

// round 9
// speedup vs baseline: 1.0636x; 1.0020x over previous
#include <cuda_runtime.h>
#include <cuda_bf16.h>
#include <math.h>
#include <stdint.h>

// ---------------------------------------------------------------------------
// Problem constants
// ---------------------------------------------------------------------------
#define S_LEN     8192
#define T_LEN     256
#define NUM_HEADS 16
#define HEAD_DIM  64
#define INNER     1024
#define INNER3    3072
#define SPARSE_N  8
#define G_LEN     1024
#define STOT      1280
#define NJH       128
#define EPS_RMS   1e-5f
#define ATTN_SCALE 0.125f
#define ATT_ELEMS (NJH * STOT * HEAD_DIM)

// ---------------------------------------------------------------------------
// Static device scratch
// ---------------------------------------------------------------------------
__device__ float g_encpart[4 * T_LEN * INNER3];
__device__ float g_txtpart[4 * T_LEN * INNER];
__device__ float g_OA[ATT_ELEMS];

__device__ __nv_bfloat16 g_hs_h[S_LEN * INNER];
__device__ __nv_bfloat16 g_hs_l[S_LEN * INNER];
__device__ __nv_bfloat16 g_enc_h[T_LEN * INNER];
__device__ __nv_bfloat16 g_enc_l[T_LEN * INNER];
__device__ __nv_bfloat16 g_w_h[8 * INNER * INNER];
__device__ __nv_bfloat16 g_w_l[8 * INNER * INNER];
__device__ __nv_bfloat16 g_vis_h[S_LEN * INNER];
__device__ __nv_bfloat16 g_vis_l[S_LEN * INNER];
__device__ __nv_bfloat16 g_txt_h[T_LEN * INNER];
__device__ __nv_bfloat16 g_txt_l[T_LEN * INNER];
__device__ __nv_bfloat16 g_QAh[ATT_ELEMS];
__device__ __nv_bfloat16 g_QAl[ATT_ELEMS];
__device__ __nv_bfloat16 g_KAh[ATT_ELEMS];
__device__ __nv_bfloat16 g_KAl[ATT_ELEMS];
__device__ __nv_bfloat16 g_VAh[ATT_ELEMS];
__device__ __nv_bfloat16 g_VAl[ATT_ELEMS];

// ---------------------------------------------------------------------------
// Helpers
// ---------------------------------------------------------------------------
__device__ __forceinline__ uint32_t smem_u32(const void* p) {
    uint32_t a;
    asm("{ .reg .u64 t; cvta.to.shared.u64 t, %1; cvt.u32.u64 %0, t; }"
        : "=r"(a) : "l"(p));
    return a;
}

#define CP_ASYNC16(dst, src) \
    asm volatile("cp.async.cg.shared.global [%0], [%1], 16;" :: "r"(dst), "l"(src))
#define CP_COMMIT() asm volatile("cp.async.commit_group;" ::: "memory")
#define CP_WAIT0()  asm volatile("cp.async.wait_group 0;" ::: "memory")
#define CP_WAIT1()  asm volatile("cp.async.wait_group 1;" ::: "memory")
#define CP_WAIT2()  asm volatile("cp.async.wait_group 2;" ::: "memory")

__device__ __forceinline__ void ldsm_x4(uint32_t* r, uint32_t a) {
    asm volatile("ldmatrix.sync.aligned.m8n8.x4.shared.b16 {%0,%1,%2,%3}, [%4];"
        : "=r"(r[0]), "=r"(r[1]), "=r"(r[2]), "=r"(r[3]) : "r"(a));
}
__device__ __forceinline__ void ldsm_x4_t(uint32_t* r, uint32_t a) {
    asm volatile("ldmatrix.sync.aligned.m8n8.x4.trans.shared.b16 {%0,%1,%2,%3}, [%4];"
        : "=r"(r[0]), "=r"(r[1]), "=r"(r[2]), "=r"(r[3]) : "r"(a));
}
__device__ __forceinline__ void mma16816(float* c, const uint32_t* a, const uint32_t* b) {
    asm volatile(
        "mma.sync.aligned.m16n8k16.row.col.f32.bf16.bf16.f32 "
        "{%0,%1,%2,%3}, {%4,%5,%6,%7}, {%8,%9}, {%0,%1,%2,%3};"
        : "+f"(c[0]), "+f"(c[1]), "+f"(c[2]), "+f"(c[3])
        : "r"(a[0]), "r"(a[1]), "r"(a[2]), "r"(a[3]), "r"(b[0]), "r"(b[1]));
}

__device__ __forceinline__ uint32_t packbf(__nv_bfloat16 x, __nv_bfloat16 y) {
    return (uint32_t)__bfloat16_as_ushort(x) | ((uint32_t)__bfloat16_as_ushort(y) << 16);
}
__device__ __forceinline__ void split2(float x, float y, uint32_t& hi, uint32_t& lo) {
    __nv_bfloat16 hx = __float2bfloat16(x), hy = __float2bfloat16(y);
    __nv_bfloat16 lx = __float2bfloat16(x - __bfloat162float(hx));
    __nv_bfloat16 ly = __float2bfloat16(y - __bfloat162float(hy));
    hi = packbf(hx, hy);
    lo = packbf(lx, ly);
}
__device__ __forceinline__ void store_split(__nv_bfloat16* ph, __nv_bfloat16* pl,
                                            size_t idx, float v) {
    __nv_bfloat16 h = __float2bfloat16(v);
    ph[idx] = h;
    pl[idx] = __float2bfloat16(v - __bfloat162float(h));
}
__device__ __forceinline__ float warp_sum32(float v) {
#pragma unroll
    for (int o = 16; o > 0; o >>= 1)
        v += __shfl_xor_sync(0xffffffffu, v, o);
    return v;
}

// ---------------------------------------------------------------------------
// One-shot fp32 -> bf16 hi/lo conversion: 8 weights + hs + enc
// ---------------------------------------------------------------------------
__global__ void __launch_bounds__(256)
cvt_all_kernel(const float* w0, const float* w1, const float* w2, const float* w3,
               const float* w4, const float* w5, const float* w6, const float* w7,
               const float* __restrict__ hs, const float* __restrict__ enc,
               __nv_bfloat16* __restrict__ w_h, __nv_bfloat16* __restrict__ w_l,
               __nv_bfloat16* __restrict__ hs_h, __nv_bfloat16* __restrict__ hs_l,
               __nv_bfloat16* __restrict__ enc_h, __nv_bfloat16* __restrict__ enc_l)
{
    const int bx = blockIdx.x;
    if (bx < 8192) {
        const int wi = bx >> 10;
        const int i  = (bx & 1023) * 256 + threadIdx.x;
        const float* src;
        switch (wi) {
            case 0: src = w0; break;  case 1: src = w1; break;
            case 2: src = w2; break;  case 3: src = w3; break;
            case 4: src = w4; break;  case 5: src = w5; break;
            case 6: src = w6; break;  default: src = w7; break;
        }
        const size_t o = (size_t)wi * (INNER * INNER / 4) + i;
        float4 v = ((const float4*)src)[i];
        uint32_t h01, l01, h23, l23;
        split2(v.x, v.y, h01, l01);
        split2(v.z, v.w, h23, l23);
        ((uint2*)w_h)[o] = make_uint2(h01, h23);
        ((uint2*)w_l)[o] = make_uint2(l01, l23);
    } else if (bx < 16384) {
        const int i = (bx - 8192) * 256 + threadIdx.x;
        float4 v = ((const float4*)hs)[i];
        uint32_t h01, l01, h23, l23;
        split2(v.x, v.y, h01, l01);
        split2(v.z, v.w, h23, l23);
        ((uint2*)hs_h)[i] = make_uint2(h01, h23);
        ((uint2*)hs_l)[i] = make_uint2(l01, l23);
    } else {
        const int i = (bx - 16384) * 256 + threadIdx.x;
        float4 v = ((const float4*)enc)[i];
        uint32_t h01, l01, h23, l23;
        split2(v.x, v.y, h01, l01);
        split2(v.z, v.w, h23, l23);
        ((uint2*)enc_h)[i] = make_uint2(h01, h23);
        ((uint2*)enc_l)[i] = make_uint2(l01, l23);
    }
}

// ---------------------------------------------------------------------------
// Shared GEMM mainloop (v1): 128x128 CTA, 256 threads, 2 CTAs/SM, 2-stage.
// Produces acc[2][8][4] per thread.
// ---------------------------------------------------------------------------
#define PADK 40
#define GT_TILE  (128 * PADK)
#define GT_STAGE (4 * GT_TILE)
#define GEMM1_SMEM_BYTES (2 * GT_STAGE * 2)

#define GEMM_V1_MAINLOOP(Ah, Al, Wh, Wl, K, acc)                              \
    const int tile = t >> 6;                                                  \
    const int l64  = t & 63;                                                  \
    const int lrr  = l64 >> 2;                                                \
    const int lcc  = (l64 & 3) * 8;                                           \
    const __nv_bfloat16* gsrc =                                               \
        (tile == 0) ? Ah : (tile == 1) ? Al : (tile == 2) ? Wh : Wl;          \
    const int rowbase = (tile < 2) ? m0 : n0;                                 \
    const uint32_t smb = smem_u32(sm);                                        \
    const uint32_t sdst0 = smb + ((tile * GT_TILE + lrr * PADK + lcc) << 1);  \
    const __nv_bfloat16* gp = gsrc + (size_t)(rowbase + lrr) * K + lcc;       \
    const uint32_t abase_rel = (((wm * 32 + (lane & 15)) * PADK +             \
                                 ((lane >> 4) << 3)) << 1);                   \
    const uint32_t bbase_rel = ((2 * GT_TILE +                                \
        (wn * 64 + (lane & 7) + ((lane >> 4) << 3)) * PADK +                  \
        (((lane >> 3) & 1) << 3)) << 1);                                      \
    const int NT = K / 32;                                                    \
    {                                                                         \
        const __nv_bfloat16* g = gp;                                          \
        _Pragma("unroll")                                                     \
        for (int i = 0; i < 8; i++)                                           \
            CP_ASYNC16(sdst0 + (uint32_t)((i * 16 * PADK) << 1),              \
                       g + (size_t)(i * 16) * K);                             \
        CP_COMMIT();                                                          \
    }                                                                         \
    for (int kt = 0; kt < NT; kt++) {                                         \
        const int b = kt & 1;                                                 \
        if (kt + 1 < NT) {                                                    \
            const __nv_bfloat16* g = gp + (kt + 1) * 32;                      \
            const uint32_t d = sdst0 +                                        \
                (uint32_t)((((kt + 1) & 1) * GT_STAGE) << 1);                 \
            _Pragma("unroll")                                                 \
            for (int i = 0; i < 8; i++)                                       \
                CP_ASYNC16(d + (uint32_t)((i * 16 * PADK) << 1),              \
                           g + (size_t)(i * 16) * K);                         \
            CP_COMMIT();                                                      \
            CP_WAIT1();                                                       \
        } else {                                                              \
            CP_WAIT0();                                                       \
        }                                                                     \
        __syncthreads();                                                      \
        const uint32_t stage  = smb + (uint32_t)((b * GT_STAGE) << 1);        \
        const uint32_t abaseh = stage + abase_rel;                            \
        const uint32_t abasel = abaseh + (GT_TILE << 1);                      \
        const uint32_t bbaseh = stage + bbase_rel;                            \
        const uint32_t bbasel = bbaseh + (GT_TILE << 1);                      \
        _Pragma("unroll")                                                     \
        for (int ks = 0; ks < 32; ks += 16) {                                 \
            uint32_t a0h[4], a1h[4], a0l[4], a1l[4];                          \
            ldsm_x4(a0h, abaseh + ks * 2);                                    \
            ldsm_x4(a1h, abaseh + ks * 2 + 16 * PADK * 2);                    \
            ldsm_x4(a0l, abasel + ks * 2);                                    \
            ldsm_x4(a1l, abasel + ks * 2 + 16 * PADK * 2);                    \
            _Pragma("unroll")                                                 \
            for (int nbp = 0; nbp < 4; nbp++) {                               \
                uint32_t bh[4], bl[4];                                        \
                ldsm_x4(bh, bbaseh + ks * 2 + nbp * 16 * PADK * 2);           \
                ldsm_x4(bl, bbasel + ks * 2 + nbp * 16 * PADK * 2);           \
                mma16816(acc[0][2 * nbp],     a0h, bh);                       \
                mma16816(acc[0][2 * nbp + 1], a0h, bh + 2);                   \
                mma16816(acc[1][2 * nbp],     a1h, bh);                       \
                mma16816(acc[1][2 * nbp + 1], a1h, bh + 2);                   \
                mma16816(acc[0][2 * nbp],     a0h, bl);                       \
                mma16816(acc[0][2 * nbp + 1], a0h, bl + 2);                   \
                mma16816(acc[1][2 * nbp],     a1h, bl);                       \
                mma16816(acc[1][2 * nbp + 1], a1h, bl + 2);                   \
                mma16816(acc[0][2 * nbp],     a0l, bh);                       \
                mma16816(acc[0][2 * nbp + 1], a0l, bh + 2);                   \
                mma16816(acc[1][2 * nbp],     a1l, bh);                       \
                mma16816(acc[1][2 * nbp + 1], a1l, bh + 2);                   \
            }                                                                 \
        }                                                                     \
        __syncthreads();                                                      \
        /* next kt */                                                         \
    }

// ---------------------------------------------------------------------------
// Generic v1 GEMM (fp32 C + optional bias) — used for vis output projection
// ---------------------------------------------------------------------------
__global__ void __launch_bounds__(256, 2)
gemm_bf3_kernel(const __nv_bfloat16* __restrict__ Ah, const __nv_bfloat16* __restrict__ Al,
                const __nv_bfloat16* __restrict__ Wh, const __nv_bfloat16* __restrict__ Wl,
                const float* __restrict__ bias, float* __restrict__ C,
                int M, int N, int K)
{
    extern __shared__ __nv_bfloat16 sm[];
    const int t    = threadIdx.x;
    const int lane = t & 31;
    const int wid  = t >> 5;
    const int wm   = wid >> 1;
    const int wn   = wid & 1;
    const int m0   = blockIdx.y * 128;
    const int n0   = blockIdx.x * 128;

    float acc[2][8][4];
#pragma unroll
    for (int i = 0; i < 2; i++)
#pragma unroll
        for (int j = 0; j < 8; j++)
#pragma unroll
            for (int q = 0; q < 4; q++) acc[i][j][q] = 0.f;

    GEMM_V1_MAINLOOP(Ah, Al, Wh, Wl, K, acc)

    const int r0 = m0 + wm * 32 + (lane >> 2);
    const int c0 = n0 + wn * 64 + (lane & 3) * 2;
#pragma unroll
    for (int mi = 0; mi < 2; mi++) {
        const int r = r0 + mi * 16;
#pragma unroll
        for (int nb = 0; nb < 8; nb++) {
            const int c = c0 + nb * 8;
            float b0 = 0.f, b1 = 0.f;
            if (bias) { b0 = bias[c]; b1 = bias[c + 1]; }
            *(float2*)(C + (size_t)r * N + c) =
                make_float2(acc[mi][nb][0] + b0, acc[mi][nb][1] + b1);
            *(float2*)(C + (size_t)(r + 8) * N + c) =
                make_float2(acc[mi][nb][2] + b0, acc[mi][nb][3] + b1);
        }
    }
}

// ---------------------------------------------------------------------------
// Fused QKV GEMM: v1 mainloop + RMSNorm + RoPE + sparse-scatter epilogue.
// N = 3072 fixed; each warp's 64-col tile is exactly one head.
// ---------------------------------------------------------------------------
__global__ void __launch_bounds__(256, 2)
gemm_qkv_fused_kernel(const __nv_bfloat16* __restrict__ Ah, const __nv_bfloat16* __restrict__ Al,
                      const __nv_bfloat16* __restrict__ Wh, const __nv_bfloat16* __restrict__ Wl,
                      const float* __restrict__ gq, const float* __restrict__ gk,
                      const float* __restrict__ cosb, const float* __restrict__ sinb,
                      __nv_bfloat16* __restrict__ QAh, __nv_bfloat16* __restrict__ QAl,
                      __nv_bfloat16* __restrict__ KAh, __nv_bfloat16* __restrict__ KAl,
                      __nv_bfloat16* __restrict__ VAh, __nv_bfloat16* __restrict__ VAl)
{
    extern __shared__ __nv_bfloat16 sm[];
    const int t    = threadIdx.x;
    const int lane = t & 31;
    const int wid  = t >> 5;
    const int wm   = wid >> 1;
    const int wn   = wid & 1;
    const int m0   = blockIdx.y * 128;
    const int n0   = blockIdx.x * 128;
    const int K    = INNER;

    float acc[2][8][4];
#pragma unroll
    for (int i = 0; i < 2; i++)
#pragma unroll
        for (int j = 0; j < 8; j++)
#pragma unroll
            for (int q = 0; q < 4; q++) acc[i][j][q] = 0.f;

    GEMM_V1_MAINLOOP(Ah, Al, Wh, Wl, K, acc)

    // ---- fused epilogue ----
    const int nhead = (n0 >> 6) + wn;        // 0..47
    const int sec   = nhead >> 4;            // 0=Q, 1=K, 2=V
    const int hh    = nhead & 15;
    const int dq    = (lane & 3) * 2;        // even base col within head
    const int rbase = m0 + wm * 32 + (lane >> 2);

    __nv_bfloat16* outh = (sec == 0) ? QAh : (sec == 1) ? KAh : VAh;
    __nv_bfloat16* outl = (sec == 0) ? QAl : (sec == 1) ? KAl : VAl;
    const float* gvec = (sec == 0) ? gq : gk;
    const float qscale = (sec == 0) ? ATTN_SCALE : 1.0f;

#pragma unroll
    for (int mi = 0; mi < 2; mi++) {
#pragma unroll
        for (int half = 0; half < 2; half++) {
            const int row = rbase + mi * 16 + half * 8;
            const int vi = half * 2;
            const int j = row & 7, tt = row >> 3;
            const size_t dstb = (((size_t)(j * NUM_HEADS + hh)) * STOT + tt) * HEAD_DIM;
            uint32_t* oh32 = (uint32_t*)(outh + dstb);
            uint32_t* ol32 = (uint32_t*)(outl + dstb);

            if (sec == 2) {
                // V: straight hi/lo split
#pragma unroll
                for (int nb = 0; nb < 8; nb++) {
                    uint32_t hi, lo;
                    split2(acc[mi][nb][vi], acc[mi][nb][vi + 1], hi, lo);
                    const int d = dq + nb * 8;
                    oh32[d >> 1] = hi;
                    ol32[d >> 1] = lo;
                }
            } else {
                // RMSNorm: sum of squares over this thread's 16 cols + 4-lane shfl
                float ss = 0.f;
#pragma unroll
                for (int nb = 0; nb < 8; nb++) {
                    ss += acc[mi][nb][vi] * acc[mi][nb][vi];
                    ss += acc[mi][nb][vi + 1] * acc[mi][nb][vi + 1];
                }
                ss += __shfl_xor_sync(0xffffffffu, ss, 1);
                ss += __shfl_xor_sync(0xffffffffu, ss, 2);
                const float rms = rsqrtf(ss * (1.f / HEAD_DIM) + EPS_RMS);

                const float* cb = cosb + (size_t)row * HEAD_DIM;
                const float* sb = sinb + (size_t)row * HEAD_DIM;
#pragma unroll
                for (int nb = 0; nb < 4; nb++) {
                    const int d0 = dq + nb * 8;         // < 32
                    const int d1 = d0 + 32;
                    const float x00 = acc[mi][nb][vi]         * rms * gvec[d0];
                    const float x01 = acc[mi][nb][vi + 1]     * rms * gvec[d0 + 1];
                    const float x10 = acc[mi][nb + 4][vi]     * rms * gvec[d1];
                    const float x11 = acc[mi][nb + 4][vi + 1] * rms * gvec[d1 + 1];
                    const float y00 = (x00 * cb[d0]     - x10 * sb[d0])     * qscale;
                    const float y01 = (x01 * cb[d0 + 1] - x11 * sb[d0 + 1]) * qscale;
                    const float y10 = (x10 * cb[d1]     + x00 * sb[d1])     * qscale;
                    const float y11 = (x11 * cb[d1 + 1] + x01 * sb[d1 + 1]) * qscale;
                    uint32_t hi, lo;
                    split2(y00, y01, hi, lo);
                    oh32[d0 >> 1] = hi;
                    ol32[d0 >> 1] = lo;
                    split2(y10, y11, hi, lo);
                    oh32[d1 >> 1] = hi;
                    ol32[d1 >> 1] = lo;
                }
            }
        }
    }
}

// ---------------------------------------------------------------------------
// GEMM v2: 256x128 CTA, 512 threads, 3-stage, K-split (small-M GEMMs)
// ---------------------------------------------------------------------------
#define V2_TILE_A (256 * PADK)
#define V2_TILE_W (128 * PADK)
#define V2_STAGE (2 * V2_TILE_A + 2 * V2_TILE_W)
#define GEMM2_SMEM_BYTES (3 * V2_STAGE * 2)

__global__ void __launch_bounds__(512, 1)
gemm_v2_kernel(const __nv_bfloat16* __restrict__ Ah, const __nv_bfloat16* __restrict__ Al,
               const __nv_bfloat16* __restrict__ Wh, const __nv_bfloat16* __restrict__ Wl,
               float* __restrict__ C, int M, int N, int K, int kparts)
{
    extern __shared__ __nv_bfloat16 sm[];
    const int t    = threadIdx.x;
    const int lane = t & 31;
    const int wid  = t >> 5;
    const int wm   = wid >> 1;
    const int wn   = wid & 1;
    const int m0   = blockIdx.y * 256;
    const int n0   = blockIdx.x * 128;

    const int KC    = K / kparts;
    const int kbase = blockIdx.z * KC;
    const int NT    = KC / 32;

    float acc[2][8][4];
#pragma unroll
    for (int i = 0; i < 2; i++)
#pragma unroll
        for (int j = 0; j < 8; j++)
#pragma unroll
            for (int q = 0; q < 4; q++) acc[i][j][q] = 0.f;

    const int rr = t >> 2;
    const int cc = (t & 3) * 8;
    const uint32_t smb = smem_u32(sm);

    const __nv_bfloat16* pA0 = Ah + (size_t)(m0 + rr)       * K + kbase + cc;
    const __nv_bfloat16* pA1 = Ah + (size_t)(m0 + rr + 128) * K + kbase + cc;
    const __nv_bfloat16* pL0 = Al + (size_t)(m0 + rr)       * K + kbase + cc;
    const __nv_bfloat16* pL1 = Al + (size_t)(m0 + rr + 128) * K + kbase + cc;
    const __nv_bfloat16* pWh = Wh + (size_t)(n0 + rr)       * K + kbase + cc;
    const __nv_bfloat16* pWl = Wl + (size_t)(n0 + rr)       * K + kbase + cc;

    const uint32_t dA0 = (uint32_t)((rr * PADK + cc) << 1);
    const uint32_t dA1 = (uint32_t)(((rr + 128) * PADK + cc) << 1);
    const uint32_t dL0 = dA0 + (uint32_t)(V2_TILE_A << 1);
    const uint32_t dL1 = dA1 + (uint32_t)(V2_TILE_A << 1);
    const uint32_t dWh = dA0 + (uint32_t)((2 * V2_TILE_A) << 1);
    const uint32_t dWl = dA0 + (uint32_t)(((2 * V2_TILE_A) + V2_TILE_W) << 1);

#define V2_LOAD(kt, stg) do {                                              \
    const uint32_t sb = smb + (uint32_t)(((stg) * V2_STAGE) << 1);         \
    const int ko = (kt) * 32;                                              \
    CP_ASYNC16(sb + dA0, pA0 + ko);                                        \
    CP_ASYNC16(sb + dA1, pA1 + ko);                                        \
    CP_ASYNC16(sb + dL0, pL0 + ko);                                        \
    CP_ASYNC16(sb + dL1, pL1 + ko);                                        \
    CP_ASYNC16(sb + dWh, pWh + ko);                                        \
    CP_ASYNC16(sb + dWl, pWl + ko);                                        \
    CP_COMMIT();                                                           \
} while (0)

    V2_LOAD(0, 0);
    V2_LOAD(1, 1);

    const uint32_t abase_rel = (uint32_t)((((wm * 32 + (lane & 15)) * PADK +
                                            ((lane >> 4) << 3))) << 1);
    const uint32_t bbase_rel = (uint32_t)(((2 * V2_TILE_A +
                     (wn * 64 + (lane & 7) + ((lane >> 4) << 3)) * PADK +
                     (((lane >> 3) & 1) << 3))) << 1);

    int stg = 0;
    for (int kt = 0; kt < NT; kt++) {
        if (kt + 2 < NT) {
            const int ps = (stg + 2 >= 3) ? (stg - 1) : (stg + 2);
            V2_LOAD(kt + 2, ps);
            CP_WAIT2();
        } else {
            CP_WAIT0();
        }
        __syncthreads();

        const uint32_t stage  = smb + (uint32_t)((stg * V2_STAGE) << 1);
        const uint32_t abaseh = stage + abase_rel;
        const uint32_t abasel = abaseh + (uint32_t)(V2_TILE_A << 1);
        const uint32_t bbaseh = stage + bbase_rel;
        const uint32_t bbasel = bbaseh + (uint32_t)(V2_TILE_W << 1);

#pragma unroll
        for (int ks = 0; ks < 32; ks += 16) {
            uint32_t a0h[4], a1h[4], a0l[4], a1l[4];
            ldsm_x4(a0h, abaseh + ks * 2);
            ldsm_x4(a1h, abaseh + ks * 2 + 16 * PADK * 2);
            ldsm_x4(a0l, abasel + ks * 2);
            ldsm_x4(a1l, abasel + ks * 2 + 16 * PADK * 2);
#pragma unroll
            for (int nbp = 0; nbp < 4; nbp++) {
                uint32_t bh[4], bl[4];
                ldsm_x4(bh, bbaseh + ks * 2 + nbp * 16 * PADK * 2);
                ldsm_x4(bl, bbasel + ks * 2 + nbp * 16 * PADK * 2);
                mma16816(acc[0][2 * nbp],     a0h, bh);
                mma16816(acc[0][2 * nbp + 1], a0h, bh + 2);
                mma16816(acc[1][2 * nbp],     a1h, bh);
                mma16816(acc[1][2 * nbp + 1], a1h, bh + 2);
                mma16816(acc[0][2 * nbp],     a0h, bl);
                mma16816(acc[0][2 * nbp + 1], a0h, bl + 2);
                mma16816(acc[1][2 * nbp],     a1h, bl);
                mma16816(acc[1][2 * nbp + 1], a1h, bl + 2);
                mma16816(acc[0][2 * nbp],     a0l, bh);
                mma16816(acc[0][2 * nbp + 1], a0l, bh + 2);
                mma16816(acc[1][2 * nbp],     a1l, bh);
                mma16816(acc[1][2 * nbp + 1], a1l, bh + 2);
            }
        }
        __syncthreads();
        stg = (stg + 1 >= 3) ? 0 : (stg + 1);
    }

    float* Cz = C + (size_t)blockIdx.z * M * N;
    const int r0 = m0 + wm * 32 + (lane >> 2);
    const int c0 = n0 + wn * 64 + (lane & 3) * 2;
#pragma unroll
    for (int mi = 0; mi < 2; mi++) {
        const int r = r0 + mi * 16;
#pragma unroll
        for (int nb = 0; nb < 8; nb++) {
            const int c = c0 + nb * 8;
            *(float2*)(Cz + (size_t)r * N + c) =
                make_float2(acc[mi][nb][0], acc[mi][nb][1]);
            *(float2*)(Cz + (size_t)(r + 8) * N + c) =
                make_float2(acc[mi][nb][2], acc[mi][nb][3]);
        }
    }
}

// ---------------------------------------------------------------------------
// K-split reduce for txt output GEMM (with bias)
// ---------------------------------------------------------------------------
__global__ void __launch_bounds__(256)
reduce4_kernel(const float* __restrict__ part, const float* __restrict__ bias,
               float* __restrict__ out, int MN, int N)
{
    const int i = blockIdx.x * 256 + threadIdx.x;
    if (i * 4 >= MN) return;
    const int q = MN / 4;
    float4 a = ((const float4*)part)[i];
    float4 b = ((const float4*)part)[i + q];
    float4 c = ((const float4*)part)[i + 2 * q];
    float4 d = ((const float4*)part)[i + 3 * q];
    float4 r = make_float4(a.x + b.x + c.x + d.x, a.y + b.y + c.y + d.y,
                           a.z + b.z + c.z + d.z, a.w + b.w + c.w + d.w);
    if (bias) {
        const int col = (i * 4) % N;
        r.x += bias[col];  r.y += bias[col + 1];
        r.z += bias[col + 2];  r.w += bias[col + 3];
    }
    ((float4*)out)[i] = r;
}

// ---------------------------------------------------------------------------
// RMSNorm + broadcast scatter (text), reads 4 K-split partials directly
// ---------------------------------------------------------------------------
__global__ void __launch_bounds__(256)
enc_post_kernel(const float* __restrict__ part,
                const float* __restrict__ gaq, const float* __restrict__ gak,
                __nv_bfloat16* __restrict__ QAh, __nv_bfloat16* __restrict__ QAl,
                __nv_bfloat16* __restrict__ KAh, __nv_bfloat16* __restrict__ KAl,
                __nv_bfloat16* __restrict__ VAh, __nv_bfloat16* __restrict__ VAl)
{
    const int warp = (blockIdx.x * blockDim.x + threadIdx.x) >> 5;
    const int lane = threadIdx.x & 31;
    const int tt = warp >> 4;
    const int h  = warp & 15;
    if (tt >= T_LEN) return;

    const size_t src = (size_t)tt * INNER3 + h * HEAD_DIM;
    const size_t PQ = (size_t)T_LEN * INNER3;
    float a0 = 0.f, a1 = 0.f, b0 = 0.f, b1 = 0.f, v0 = 0.f, v1 = 0.f;
#pragma unroll
    for (int z = 0; z < 4; z++) {
        const float* p = part + z * PQ + src;
        a0 += p[lane];              a1 += p[lane + 32];
        b0 += p[INNER + lane];      b1 += p[INNER + lane + 32];
        v0 += p[2*INNER + lane];    v1 += p[2*INNER + lane + 32];
    }

    float ra = rsqrtf(warp_sum32(a0 * a0 + a1 * a1) * (1.f / HEAD_DIM) + EPS_RMS);
    float rb = rsqrtf(warp_sum32(b0 * b0 + b1 * b1) * (1.f / HEAD_DIM) + EPS_RMS);

    a0 *= ra * gaq[lane] * ATTN_SCALE;  a1 *= ra * gaq[lane + 32] * ATTN_SCALE;
    b0 *= rb * gak[lane];               b1 *= rb * gak[lane + 32];

#pragma unroll
    for (int j = 0; j < SPARSE_N; j++) {
        const size_t dst =
            (((size_t)(j * NUM_HEADS + h)) * STOT + G_LEN + tt) * HEAD_DIM;
        store_split(QAh, QAl, dst + lane,      a0);
        store_split(QAh, QAl, dst + lane + 32, a1);
        store_split(KAh, KAl, dst + lane,      b0);
        store_split(KAh, KAl, dst + lane + 32, b1);
        store_split(VAh, VAl, dst + lane,      v0);
        store_split(VAh, VAl, dst + lane + 32, v1);
    }
}

// ---------------------------------------------------------------------------
// Flash attention, BQ=256, 512 threads, cp.async K/V double buffering.
// Visual q-tiles write bf16 hi/lo directly to vis buffers (fused gather).
// ---------------------------------------------------------------------------
#define APAD 72
#define AQ_ELEMS (2 * 256 * APAD)
#define KV_TILE  (64 * APAD)
#define KV_STAGE (4 * KV_TILE)
#define ATT_SM_BYTES ((AQ_ELEMS + 2 * KV_STAGE) * 2)

__global__ void __launch_bounds__(512, 1)
attn_mma_kernel(const __nv_bfloat16* __restrict__ Qhg, const __nv_bfloat16* __restrict__ Qlg,
                const __nv_bfloat16* __restrict__ Khg, const __nv_bfloat16* __restrict__ Klg,
                const __nv_bfloat16* __restrict__ Vhg, const __nv_bfloat16* __restrict__ Vlg,
                float* __restrict__ OA,
                __nv_bfloat16* __restrict__ vis_h, __nv_bfloat16* __restrict__ vis_l)
{
    extern __shared__ __nv_bfloat16 smA[];
    const int t    = threadIdx.x;
    const int lane = t & 31;
    const int w    = t >> 5;
    const int jh   = blockIdx.y;
    const int q0   = blockIdx.x * 256;
    const size_t base = (size_t)jh * STOT * HEAD_DIM;

    const uint32_t smb = smem_u32(smA);

    const int tile = t >> 7;
    const int l128 = t & 127;
    const int krr  = l128 >> 3;
    const int kcc  = (l128 & 7) * 8;
    const __nv_bfloat16* kvsrc =
        (tile == 0) ? Khg : (tile == 1) ? Klg : (tile == 2) ? Vhg : Vlg;
    const uint32_t kvdst0 = smb + ((AQ_ELEMS + tile * KV_TILE + krr * APAD + kcc) << 1);

    {
        const __nv_bfloat16* g = kvsrc + base + (size_t)krr * 64 + kcc;
#pragma unroll
        for (int i = 0; i < 4; i++)
            CP_ASYNC16(kvdst0 + (uint32_t)((i * 16 * APAD) << 1),
                       g + (size_t)(i * 16) * 64);
        CP_COMMIT();
    }

    {
        const int row = t >> 1, c0 = (t & 1) * 32;
        const __nv_bfloat16* gh = Qhg + base + (size_t)(q0 + row) * 64 + c0;
        const __nv_bfloat16* gl = Qlg + base + (size_t)(q0 + row) * 64 + c0;
        __nv_bfloat16* sh = smA + row * APAD + c0;
        __nv_bfloat16* sl = smA + 256 * APAD + row * APAD + c0;
#pragma unroll
        for (int c = 0; c < 32; c += 8) {
            *(uint4*)(sh + c) = *(const uint4*)(gh + c);
            *(uint4*)(sl + c) = *(const uint4*)(gl + c);
        }
    }

    float o[8][4];
#pragma unroll
    for (int i = 0; i < 8; i++)
#pragma unroll
        for (int j = 0; j < 4; j++) o[i][j] = 0.f;
    float m0r = -1e30f, m1r = -1e30f, l0r = 0.f, l1r = 0.f;

    const uint32_t qfragh = smb + (((w * 16 + (lane & 15)) * APAD + ((lane >> 4) << 3)) << 1);
    const uint32_t qfragl = qfragh + ((256 * APAD) << 1);
    const uint32_t kfrag_rel = ((((lane & 7) + ((lane >> 4) << 3)) * APAD + (((lane >> 3) & 1) << 3)) << 1);
    const uint32_t vfrag_rel = (((2 * KV_TILE) + ((lane & 7) + (((lane >> 3) & 1) << 3)) * APAD + ((lane >> 4) << 3)) << 1);

    for (int kt = 0; kt < 20; kt++) {
        const int b = kt & 1;
        if (kt + 1 < 20) {
            const __nv_bfloat16* g = kvsrc + base + (size_t)((kt + 1) * 64 + krr) * 64 + kcc;
            const uint32_t d = kvdst0 + (uint32_t)((((kt + 1) & 1) * KV_STAGE) << 1);
#pragma unroll
            for (int i = 0; i < 4; i++)
                CP_ASYNC16(d + (uint32_t)((i * 16 * APAD) << 1),
                           g + (size_t)(i * 16) * 64);
            CP_COMMIT();
            CP_WAIT1();
        } else {
            CP_WAIT0();
        }
        __syncthreads();

        const uint32_t kvstage = smb + (uint32_t)(((AQ_ELEMS + b * KV_STAGE)) << 1);
        const uint32_t kfragh = kvstage + kfrag_rel;
        const uint32_t kfragl = kfragh + (KV_TILE << 1);
        const uint32_t vfrag  = kvstage + vfrag_rel;

        float s[8][4];
#pragma unroll
        for (int i = 0; i < 8; i++)
#pragma unroll
            for (int j = 0; j < 4; j++) s[i][j] = 0.f;

#pragma unroll
        for (int ks = 0; ks < 64; ks += 16) {
            uint32_t ah[4], al[4];
            ldsm_x4(ah, qfragh + ks * 2);
            ldsm_x4(al, qfragl + ks * 2);
#pragma unroll
            for (int nbp = 0; nbp < 4; nbp++) {
                uint32_t kh[4], kl[4];
                ldsm_x4(kh, kfragh + ks * 2 + nbp * 16 * APAD * 2);
                ldsm_x4(kl, kfragl + ks * 2 + nbp * 16 * APAD * 2);
                mma16816(s[2 * nbp],     ah, kh);
                mma16816(s[2 * nbp + 1], ah, kh + 2);
                mma16816(s[2 * nbp],     ah, kl);
                mma16816(s[2 * nbp + 1], ah, kl + 2);
                mma16816(s[2 * nbp],     al, kh);
                mma16816(s[2 * nbp + 1], al, kh + 2);
            }
        }

        float mt0 = -1e30f, mt1 = -1e30f;
#pragma unroll
        for (int nb = 0; nb < 8; nb++) {
            mt0 = fmaxf(mt0, fmaxf(s[nb][0], s[nb][1]));
            mt1 = fmaxf(mt1, fmaxf(s[nb][2], s[nb][3]));
        }
        mt0 = fmaxf(mt0, __shfl_xor_sync(0xffffffffu, mt0, 1));
        mt0 = fmaxf(mt0, __shfl_xor_sync(0xffffffffu, mt0, 2));
        mt1 = fmaxf(mt1, __shfl_xor_sync(0xffffffffu, mt1, 1));
        mt1 = fmaxf(mt1, __shfl_xor_sync(0xffffffffu, mt1, 2));
        const float mn0 = fmaxf(m0r, mt0), mn1 = fmaxf(m1r, mt1);
        const float cf0 = __expf(m0r - mn0), cf1 = __expf(m1r - mn1);
        m0r = mn0;  m1r = mn1;
        float rs0 = 0.f, rs1 = 0.f;
#pragma unroll
        for (int nb = 0; nb < 8; nb++) {
            s[nb][0] = __expf(s[nb][0] - mn0);  rs0 += s[nb][0];
            s[nb][1] = __expf(s[nb][1] - mn0);  rs0 += s[nb][1];
            s[nb][2] = __expf(s[nb][2] - mn1);  rs1 += s[nb][2];
            s[nb][3] = __expf(s[nb][3] - mn1);  rs1 += s[nb][3];
        }
        rs0 += __shfl_xor_sync(0xffffffffu, rs0, 1);
        rs0 += __shfl_xor_sync(0xffffffffu, rs0, 2);
        rs1 += __shfl_xor_sync(0xffffffffu, rs1, 1);
        rs1 += __shfl_xor_sync(0xffffffffu, rs1, 2);
        l0r = l0r * cf0 + rs0;
        l1r = l1r * cf1 + rs1;
#pragma unroll
        for (int db = 0; db < 8; db++) {
            o[db][0] *= cf0;  o[db][1] *= cf0;
            o[db][2] *= cf1;  o[db][3] *= cf1;
        }

#pragma unroll
        for (int kb2 = 0; kb2 < 4; kb2++) {
            uint32_t ph[4], pl[4];
            split2(s[2 * kb2][0],     s[2 * kb2][1],     ph[0], pl[0]);
            split2(s[2 * kb2][2],     s[2 * kb2][3],     ph[1], pl[1]);
            split2(s[2 * kb2 + 1][0], s[2 * kb2 + 1][1], ph[2], pl[2]);
            split2(s[2 * kb2 + 1][2], s[2 * kb2 + 1][3], ph[3], pl[3]);
            const uint32_t vb = vfrag + kb2 * 16 * APAD * 2;
#pragma unroll
            for (int dbp = 0; dbp < 4; dbp++) {
                uint32_t vh4[4], vl4[4];
                ldsm_x4_t(vh4, vb + dbp * 16 * 2);
                ldsm_x4_t(vl4, vb + (KV_TILE << 1) + dbp * 16 * 2);
                mma16816(o[2 * dbp],     ph, vh4);
                mma16816(o[2 * dbp + 1], ph, vh4 + 2);
                mma16816(o[2 * dbp],     ph, vl4);
                mma16816(o[2 * dbp + 1], ph, vl4 + 2);
                mma16816(o[2 * dbp],     pl, vh4);
                mma16816(o[2 * dbp + 1], pl, vh4 + 2);
            }
        }
        __syncthreads();
    }

    const float inv0 = 1.f / l0r, inv1 = 1.f / l1r;
    const int row = q0 + w * 16 + (lane >> 2);
    const int col = (lane & 3) * 2;
    if (blockIdx.x < 4) {
        const int j = jh >> 4, h = jh & 15;
        uint32_t* vh32 = (uint32_t*)vis_h;
        uint32_t* vl32 = (uint32_t*)vis_l;
        const size_t b0 = ((size_t)row * 8 + j) * INNER + h * 64;
        const size_t b1 = ((size_t)(row + 8) * 8 + j) * INNER + h * 64;
#pragma unroll
        for (int db = 0; db < 8; db++) {
            uint32_t hi, lo;
            split2(o[db][0] * inv0, o[db][1] * inv0, hi, lo);
            vh32[(b0 + db * 8 + col) >> 1] = hi;
            vl32[(b0 + db * 8 + col) >> 1] = lo;
            split2(o[db][2] * inv1, o[db][3] * inv1, hi, lo);
            vh32[(b1 + db * 8 + col) >> 1] = hi;
            vl32[(b1 + db * 8 + col) >> 1] = lo;
        }
    } else {
#pragma unroll
        for (int db = 0; db < 8; db++) {
            *(float2*)(OA + base + (size_t)row * 64 + db * 8 + col) =
                make_float2(o[db][0] * inv0, o[db][1] * inv0);
            *(float2*)(OA + base + (size_t)(row + 8) * 64 + db * 8 + col) =
                make_float2(o[db][2] * inv1, o[db][3] * inv1);
        }
    }
}

// ---------------------------------------------------------------------------
// Gather text rows -> bf16 hi/lo (mean over j)
// ---------------------------------------------------------------------------
__global__ void __launch_bounds__(256)
gather_txt_kernel(const float* __restrict__ OA,
                  __nv_bfloat16* __restrict__ th, __nv_bfloat16* __restrict__ tl)
{
    const int i = blockIdx.x * 256 + threadIdx.x;
    const int idx = i * 4;
    const int tt = idx >> 10, e = idx & 1023;
    const int h = e >> 6, d = e & 63;
    float4 acc = make_float4(0.f, 0.f, 0.f, 0.f);
#pragma unroll
    for (int j = 0; j < SPARSE_N; j++) {
        float4 v = *(const float4*)(OA +
            (((size_t)(j * NUM_HEADS + h)) * STOT + G_LEN + tt) * HEAD_DIM + d);
        acc.x += v.x; acc.y += v.y; acc.z += v.z; acc.w += v.w;
    }
    acc.x *= 0.125f; acc.y *= 0.125f; acc.z *= 0.125f; acc.w *= 0.125f;
    uint32_t h01, l01, h23, l23;
    split2(acc.x, acc.y, h01, l01);
    split2(acc.z, acc.w, h23, l23);
    ((uint2*)th)[i] = make_uint2(h01, h23);
    ((uint2*)tl)[i] = make_uint2(l01, l23);
}

// ---------------------------------------------------------------------------
// kernel_launch
// ---------------------------------------------------------------------------
extern "C" void kernel_launch(void* const* d_in, const int* in_sizes, int n_in,
                              void* d_out, int out_size)
{
    const float* hs   = (const float*)d_in[0];
    const float* enc  = (const float*)d_in[1];
    const float* bout  = (const float*)d_in[9];
    const float* baout = (const float*)d_in[11];
    const float* gq   = (const float*)d_in[12];
    const float* gk   = (const float*)d_in[13];
    const float* gaq  = (const float*)d_in[14];
    const float* gak  = (const float*)d_in[15];
    const float* rc   = (const float*)d_in[16];
    const float* rs   = (const float*)d_in[17];
    float* out = (float*)d_out;

    float *encpart, *txtpart, *OA;
    __nv_bfloat16 *hs_h, *hs_l, *enc_h, *enc_l, *w_h, *w_l;
    __nv_bfloat16 *vis_h, *vis_l, *txt_h, *txt_l;
    __nv_bfloat16 *QAh, *QAl, *KAh, *KAl, *VAh, *VAl;
    cudaGetSymbolAddress((void**)&encpart, g_encpart);
    cudaGetSymbolAddress((void**)&txtpart, g_txtpart);
    cudaGetSymbolAddress((void**)&OA,    g_OA);
    cudaGetSymbolAddress((void**)&hs_h,  g_hs_h);
    cudaGetSymbolAddress((void**)&hs_l,  g_hs_l);
    cudaGetSymbolAddress((void**)&enc_h, g_enc_h);
    cudaGetSymbolAddress((void**)&enc_l, g_enc_l);
    cudaGetSymbolAddress((void**)&w_h,   g_w_h);
    cudaGetSymbolAddress((void**)&w_l,   g_w_l);
    cudaGetSymbolAddress((void**)&vis_h, g_vis_h);
    cudaGetSymbolAddress((void**)&vis_l, g_vis_l);
    cudaGetSymbolAddress((void**)&txt_h, g_txt_h);
    cudaGetSymbolAddress((void**)&txt_l, g_txt_l);
    cudaGetSymbolAddress((void**)&QAh,   g_QAh);
    cudaGetSymbolAddress((void**)&QAl,   g_QAl);
    cudaGetSymbolAddress((void**)&KAh,   g_KAh);
    cudaGetSymbolAddress((void**)&KAl,   g_KAl);
    cudaGetSymbolAddress((void**)&VAh,   g_VAh);
    cudaGetSymbolAddress((void**)&VAl,   g_VAl);

    cudaFuncSetAttribute(gemm_bf3_kernel,
                         cudaFuncAttributeMaxDynamicSharedMemorySize, GEMM1_SMEM_BYTES);
    cudaFuncSetAttribute(gemm_qkv_fused_kernel,
                         cudaFuncAttributeMaxDynamicSharedMemorySize, GEMM1_SMEM_BYTES);
    cudaFuncSetAttribute(gemm_v2_kernel,
                         cudaFuncAttributeMaxDynamicSharedMemorySize, GEMM2_SMEM_BYTES);
    cudaFuncSetAttribute(attn_mma_kernel,
                         cudaFuncAttributeMaxDynamicSharedMemorySize, ATT_SM_BYTES);

    const size_t WS = (size_t)INNER * INNER;

    // [0] all conversions (weights + hs + enc)
    cvt_all_kernel<<<16640, 256>>>(
        (const float*)d_in[2], (const float*)d_in[3], (const float*)d_in[4],
        (const float*)d_in[5], (const float*)d_in[6], (const float*)d_in[7],
        (const float*)d_in[8], (const float*)d_in[10], hs, enc,
        w_h, w_l, hs_h, hs_l, enc_h, enc_l);

    // [1] enc QKV GEMM (v2, K-split x4), [2] enc post (fused reduce)
    gemm_v2_kernel<<<dim3(INNER3 / 128, 1, 4), 512, GEMM2_SMEM_BYTES>>>(
        enc_h, enc_l, w_h + 3 * WS, w_l + 3 * WS, encpart, T_LEN, INNER3, INNER, 4);
    enc_post_kernel<<<(T_LEN * NUM_HEADS) / 8, 256>>>(
        encpart, gaq, gak, QAh, QAl, KAh, KAl, VAh, VAl);

    // [3] big QKV GEMM with FUSED RMSNorm+RoPE+scatter epilogue
    gemm_qkv_fused_kernel<<<dim3(INNER3 / 128, S_LEN / 128), 256, GEMM1_SMEM_BYTES>>>(
        hs_h, hs_l, w_h + 0 * WS, w_l + 0 * WS,
        gq, gk, rc, rs, QAh, QAl, KAh, KAl, VAh, VAl);

    // [4] attention (fused vis gather)
    attn_mma_kernel<<<dim3(STOT / 256, NJH), 512, ATT_SM_BYTES>>>(
        QAh, QAl, KAh, KAl, VAh, VAl, OA, vis_h, vis_l);

    // [5] text gather
    gather_txt_kernel<<<(T_LEN * INNER / 4) / 256, 256>>>(OA, txt_h, txt_l);

    // [6] vis out GEMM (v1, bias)
    gemm_bf3_kernel<<<dim3(INNER / 128, S_LEN / 128), 256, GEMM1_SMEM_BYTES>>>(
        vis_h, vis_l, w_h + 6 * WS, w_l + 6 * WS, bout, out, S_LEN, INNER, INNER);

    // [7] txt out GEMM (v2, K-split x4), [8] reduce with bias
    gemm_v2_kernel<<<dim3(INNER / 128, 1, 4), 512, GEMM2_SMEM_BYTES>>>(
        txt_h, txt_l, w_h + 7 * WS, w_l + 7 * WS, txtpart, T_LEN, INNER, INNER, 4);
    reduce4_kernel<<<(T_LEN * INNER / 4) / 256, 256>>>(
        txtpart, baout, out + (size_t)S_LEN * INNER, T_LEN * INNER, INNER);
}

// round 10
// speedup vs baseline: 1.0652x; 1.0015x over previous
#include <cuda_runtime.h>
#include <cuda_bf16.h>
#include <math.h>
#include <stdint.h>

// ---------------------------------------------------------------------------
// Problem constants
// ---------------------------------------------------------------------------
#define S_LEN     8192
#define T_LEN     256
#define NUM_HEADS 16
#define HEAD_DIM  64
#define INNER     1024
#define INNER3    3072
#define SPARSE_N  8
#define G_LEN     1024
#define STOT      1280
#define NJH       128
#define EPS_RMS   1e-5f
#define ATTN_SCALE 0.125f
#define ATT_ELEMS (NJH * STOT * HEAD_DIM)

// ---------------------------------------------------------------------------
// Static device scratch
// ---------------------------------------------------------------------------
__device__ float g_encpart[4 * T_LEN * INNER3];
__device__ float g_txtpart[4 * T_LEN * INNER];
__device__ float g_OA[ATT_ELEMS];

__device__ __nv_bfloat16 g_hs_h[S_LEN * INNER];
__device__ __nv_bfloat16 g_hs_l[S_LEN * INNER];
__device__ __nv_bfloat16 g_enc_h[T_LEN * INNER];
__device__ __nv_bfloat16 g_enc_l[T_LEN * INNER];
__device__ __nv_bfloat16 g_w_h[8 * INNER * INNER];
__device__ __nv_bfloat16 g_w_l[8 * INNER * INNER];
__device__ __nv_bfloat16 g_vis_h[S_LEN * INNER];
__device__ __nv_bfloat16 g_vis_l[S_LEN * INNER];
__device__ __nv_bfloat16 g_txt_h[T_LEN * INNER];
__device__ __nv_bfloat16 g_txt_l[T_LEN * INNER];
__device__ __nv_bfloat16 g_QAh[ATT_ELEMS];
__device__ __nv_bfloat16 g_QAl[ATT_ELEMS];
__device__ __nv_bfloat16 g_KAh[ATT_ELEMS];
__device__ __nv_bfloat16 g_KAl[ATT_ELEMS];
__device__ __nv_bfloat16 g_VAh[ATT_ELEMS];
__device__ __nv_bfloat16 g_VAl[ATT_ELEMS];

// ---------------------------------------------------------------------------
// Helpers
// ---------------------------------------------------------------------------
__device__ __forceinline__ uint32_t smem_u32(const void* p) {
    uint32_t a;
    asm("{ .reg .u64 t; cvta.to.shared.u64 t, %1; cvt.u32.u64 %0, t; }"
        : "=r"(a) : "l"(p));
    return a;
}

#define CP_ASYNC16(dst, src) \
    asm volatile("cp.async.cg.shared.global [%0], [%1], 16;" :: "r"(dst), "l"(src))
#define CP_COMMIT() asm volatile("cp.async.commit_group;" ::: "memory")
#define CP_WAIT0()  asm volatile("cp.async.wait_group 0;" ::: "memory")
#define CP_WAIT1()  asm volatile("cp.async.wait_group 1;" ::: "memory")
#define CP_WAIT2()  asm volatile("cp.async.wait_group 2;" ::: "memory")

__device__ __forceinline__ void ldsm_x4(uint32_t* r, uint32_t a) {
    asm volatile("ldmatrix.sync.aligned.m8n8.x4.shared.b16 {%0,%1,%2,%3}, [%4];"
        : "=r"(r[0]), "=r"(r[1]), "=r"(r[2]), "=r"(r[3]) : "r"(a));
}
__device__ __forceinline__ void ldsm_x4_t(uint32_t* r, uint32_t a) {
    asm volatile("ldmatrix.sync.aligned.m8n8.x4.trans.shared.b16 {%0,%1,%2,%3}, [%4];"
        : "=r"(r[0]), "=r"(r[1]), "=r"(r[2]), "=r"(r[3]) : "r"(a));
}
__device__ __forceinline__ void mma16816(float* c, const uint32_t* a, const uint32_t* b) {
    asm volatile(
        "mma.sync.aligned.m16n8k16.row.col.f32.bf16.bf16.f32 "
        "{%0,%1,%2,%3}, {%4,%5,%6,%7}, {%8,%9}, {%0,%1,%2,%3};"
        : "+f"(c[0]), "+f"(c[1]), "+f"(c[2]), "+f"(c[3])
        : "r"(a[0]), "r"(a[1]), "r"(a[2]), "r"(a[3]), "r"(b[0]), "r"(b[1]));
}

__device__ __forceinline__ uint32_t packbf(__nv_bfloat16 x, __nv_bfloat16 y) {
    return (uint32_t)__bfloat16_as_ushort(x) | ((uint32_t)__bfloat16_as_ushort(y) << 16);
}
__device__ __forceinline__ void split2(float x, float y, uint32_t& hi, uint32_t& lo) {
    __nv_bfloat16 hx = __float2bfloat16(x), hy = __float2bfloat16(y);
    __nv_bfloat16 lx = __float2bfloat16(x - __bfloat162float(hx));
    __nv_bfloat16 ly = __float2bfloat16(y - __bfloat162float(hy));
    hi = packbf(hx, hy);
    lo = packbf(lx, ly);
}
__device__ __forceinline__ void store_split(__nv_bfloat16* ph, __nv_bfloat16* pl,
                                            size_t idx, float v) {
    __nv_bfloat16 h = __float2bfloat16(v);
    ph[idx] = h;
    pl[idx] = __float2bfloat16(v - __bfloat162float(h));
}
__device__ __forceinline__ float warp_sum32(float v) {
#pragma unroll
    for (int o = 16; o > 0; o >>= 1)
        v += __shfl_xor_sync(0xffffffffu, v, o);
    return v;
}

// ---------------------------------------------------------------------------
// Conversions: weights (8192 blocks) and hs+enc (8448 blocks)
// ---------------------------------------------------------------------------
__global__ void __launch_bounds__(256)
cvt8_kernel(const float* w0, const float* w1, const float* w2, const float* w3,
            const float* w4, const float* w5, const float* w6, const float* w7,
            __nv_bfloat16* __restrict__ hi, __nv_bfloat16* __restrict__ lo)
{
    const int wi = blockIdx.x >> 10;
    const int i  = (blockIdx.x & 1023) * 256 + threadIdx.x;
    const float* src;
    switch (wi) {
        case 0: src = w0; break;  case 1: src = w1; break;
        case 2: src = w2; break;  case 3: src = w3; break;
        case 4: src = w4; break;  case 5: src = w5; break;
        case 6: src = w6; break;  default: src = w7; break;
    }
    float4 v = ((const float4*)src)[i];
    uint32_t h01, l01, h23, l23;
    split2(v.x, v.y, h01, l01);
    split2(v.z, v.w, h23, l23);
    const size_t o = (size_t)wi * (INNER * INNER / 4) + i;
    ((uint2*)hi)[o] = make_uint2(h01, h23);
    ((uint2*)lo)[o] = make_uint2(l01, l23);
}

__global__ void __launch_bounds__(256)
cvt_hsenc_kernel(const float* __restrict__ hs, const float* __restrict__ enc,
                 __nv_bfloat16* __restrict__ hs_h, __nv_bfloat16* __restrict__ hs_l,
                 __nv_bfloat16* __restrict__ enc_h, __nv_bfloat16* __restrict__ enc_l)
{
    const int bx = blockIdx.x;
    if (bx < 8192) {
        const int i = bx * 256 + threadIdx.x;
        float4 v = ((const float4*)hs)[i];
        uint32_t h01, l01, h23, l23;
        split2(v.x, v.y, h01, l01);
        split2(v.z, v.w, h23, l23);
        ((uint2*)hs_h)[i] = make_uint2(h01, h23);
        ((uint2*)hs_l)[i] = make_uint2(l01, l23);
    } else {
        const int i = (bx - 8192) * 256 + threadIdx.x;
        float4 v = ((const float4*)enc)[i];
        uint32_t h01, l01, h23, l23;
        split2(v.x, v.y, h01, l01);
        split2(v.z, v.w, h23, l23);
        ((uint2*)enc_h)[i] = make_uint2(h01, h23);
        ((uint2*)enc_l)[i] = make_uint2(l01, l23);
    }
}

// ---------------------------------------------------------------------------
// Pipelined 3-pass MMA block: bh double-buffered, bl reloaded between passes.
// Consumes: abaseh/abasel (A frag bases), bbaseh/bbasel (B frag bases), ks.
// ---------------------------------------------------------------------------
#define MMA_BLOCK_PIPE(acc, abaseh, abasel, bbaseh, bbasel, ks)               \
    {                                                                         \
        uint32_t a0h[4], a1h[4], a0l[4], a1l[4];                              \
        ldsm_x4(a0h, (abaseh) + (ks) * 2);                                    \
        ldsm_x4(a1h, (abaseh) + (ks) * 2 + 16 * PADK * 2);                    \
        ldsm_x4(a0l, (abasel) + (ks) * 2);                                    \
        ldsm_x4(a1l, (abasel) + (ks) * 2 + 16 * PADK * 2);                    \
        uint32_t bh[2][4], bl[4], bln[4];                                     \
        ldsm_x4(bh[0], (bbaseh) + (ks) * 2);                                  \
        ldsm_x4(bl,    (bbasel) + (ks) * 2);                                  \
        _Pragma("unroll")                                                     \
        for (int nbp = 0; nbp < 4; nbp++) {                                   \
            const int c = nbp & 1;                                            \
            mma16816(acc[0][2 * nbp],     a0h, bh[c]);                        \
            mma16816(acc[0][2 * nbp + 1], a0h, bh[c] + 2);                    \
            mma16816(acc[1][2 * nbp],     a1h, bh[c]);                        \
            mma16816(acc[1][2 * nbp + 1], a1h, bh[c] + 2);                    \
            if (nbp < 3)                                                      \
                ldsm_x4(bh[c ^ 1], (bbaseh) + (ks) * 2 +                      \
                        (nbp + 1) * 16 * PADK * 2);                           \
            mma16816(acc[0][2 * nbp],     a0h, bl);                           \
            mma16816(acc[0][2 * nbp + 1], a0h, bl + 2);                       \
            mma16816(acc[1][2 * nbp],     a1h, bl);                           \
            mma16816(acc[1][2 * nbp + 1], a1h, bl + 2);                       \
            if (nbp < 3)                                                      \
                ldsm_x4(bln, (bbasel) + (ks) * 2 +                            \
                        (nbp + 1) * 16 * PADK * 2);                           \
            mma16816(acc[0][2 * nbp],     a0l, bh[c]);                        \
            mma16816(acc[0][2 * nbp + 1], a0l, bh[c] + 2);                    \
            mma16816(acc[1][2 * nbp],     a1l, bh[c]);                        \
            mma16816(acc[1][2 * nbp + 1], a1l, bh[c] + 2);                    \
            if (nbp < 3) {                                                    \
                bl[0] = bln[0]; bl[1] = bln[1];                               \
                bl[2] = bln[2]; bl[3] = bln[3];                               \
            }                                                                 \
        }                                                                     \
    }

// ---------------------------------------------------------------------------
// Shared GEMM mainloop (v1): 128x128 CTA, 256 threads, 2 CTAs/SM, 2-stage.
// ---------------------------------------------------------------------------
#define PADK 40
#define GT_TILE  (128 * PADK)
#define GT_STAGE (4 * GT_TILE)
#define GEMM1_SMEM_BYTES (2 * GT_STAGE * 2)

#define GEMM_V1_MAINLOOP(Ah, Al, Wh, Wl, K, acc)                              \
    const int tile = t >> 6;                                                  \
    const int l64  = t & 63;                                                  \
    const int lrr  = l64 >> 2;                                                \
    const int lcc  = (l64 & 3) * 8;                                           \
    const __nv_bfloat16* gsrc =                                               \
        (tile == 0) ? Ah : (tile == 1) ? Al : (tile == 2) ? Wh : Wl;          \
    const int rowbase = (tile < 2) ? m0 : n0;                                 \
    const uint32_t smb = smem_u32(sm);                                        \
    const uint32_t sdst0 = smb + ((tile * GT_TILE + lrr * PADK + lcc) << 1);  \
    const __nv_bfloat16* gp = gsrc + (size_t)(rowbase + lrr) * K + lcc;       \
    const uint32_t abase_rel = (((wm * 32 + (lane & 15)) * PADK +             \
                                 ((lane >> 4) << 3)) << 1);                   \
    const uint32_t bbase_rel = ((2 * GT_TILE +                                \
        (wn * 64 + (lane & 7) + ((lane >> 4) << 3)) * PADK +                  \
        (((lane >> 3) & 1) << 3)) << 1);                                      \
    const int NT = K / 32;                                                    \
    {                                                                         \
        const __nv_bfloat16* g = gp;                                          \
        _Pragma("unroll")                                                     \
        for (int i = 0; i < 8; i++)                                           \
            CP_ASYNC16(sdst0 + (uint32_t)((i * 16 * PADK) << 1),              \
                       g + (size_t)(i * 16) * K);                             \
        CP_COMMIT();                                                          \
    }                                                                         \
    for (int kt = 0; kt < NT; kt++) {                                         \
        const int b = kt & 1;                                                 \
        if (kt + 1 < NT) {                                                    \
            const __nv_bfloat16* g = gp + (kt + 1) * 32;                      \
            const uint32_t d = sdst0 +                                        \
                (uint32_t)((((kt + 1) & 1) * GT_STAGE) << 1);                 \
            _Pragma("unroll")                                                 \
            for (int i = 0; i < 8; i++)                                       \
                CP_ASYNC16(d + (uint32_t)((i * 16 * PADK) << 1),              \
                           g + (size_t)(i * 16) * K);                         \
            CP_COMMIT();                                                      \
            CP_WAIT1();                                                       \
        } else {                                                              \
            CP_WAIT0();                                                       \
        }                                                                     \
        __syncthreads();                                                      \
        const uint32_t stage  = smb + (uint32_t)((b * GT_STAGE) << 1);        \
        const uint32_t abaseh = stage + abase_rel;                            \
        const uint32_t abasel = abaseh + (GT_TILE << 1);                      \
        const uint32_t bbaseh = stage + bbase_rel;                            \
        const uint32_t bbasel = bbaseh + (GT_TILE << 1);                      \
        _Pragma("unroll")                                                     \
        for (int ks = 0; ks < 32; ks += 16) {                                 \
            MMA_BLOCK_PIPE(acc, abaseh, abasel, bbaseh, bbasel, ks)           \
        }                                                                     \
        __syncthreads();                                                      \
    }

// ---------------------------------------------------------------------------
// Generic v1 GEMM (fp32 C + optional bias)
// ---------------------------------------------------------------------------
__global__ void __launch_bounds__(256, 2)
gemm_bf3_kernel(const __nv_bfloat16* __restrict__ Ah, const __nv_bfloat16* __restrict__ Al,
                const __nv_bfloat16* __restrict__ Wh, const __nv_bfloat16* __restrict__ Wl,
                const float* __restrict__ bias, float* __restrict__ C,
                int M, int N, int K)
{
    extern __shared__ __nv_bfloat16 sm[];
    const int t    = threadIdx.x;
    const int lane = t & 31;
    const int wid  = t >> 5;
    const int wm   = wid >> 1;
    const int wn   = wid & 1;
    const int m0   = blockIdx.y * 128;
    const int n0   = blockIdx.x * 128;

    float acc[2][8][4];
#pragma unroll
    for (int i = 0; i < 2; i++)
#pragma unroll
        for (int j = 0; j < 8; j++)
#pragma unroll
            for (int q = 0; q < 4; q++) acc[i][j][q] = 0.f;

    GEMM_V1_MAINLOOP(Ah, Al, Wh, Wl, K, acc)

    const int r0 = m0 + wm * 32 + (lane >> 2);
    const int c0 = n0 + wn * 64 + (lane & 3) * 2;
#pragma unroll
    for (int mi = 0; mi < 2; mi++) {
        const int r = r0 + mi * 16;
#pragma unroll
        for (int nb = 0; nb < 8; nb++) {
            const int c = c0 + nb * 8;
            float b0 = 0.f, b1 = 0.f;
            if (bias) { b0 = bias[c]; b1 = bias[c + 1]; }
            *(float2*)(C + (size_t)r * N + c) =
                make_float2(acc[mi][nb][0] + b0, acc[mi][nb][1] + b1);
            *(float2*)(C + (size_t)(r + 8) * N + c) =
                make_float2(acc[mi][nb][2] + b0, acc[mi][nb][3] + b1);
        }
    }
}

// ---------------------------------------------------------------------------
// Fused QKV GEMM (RMSNorm + RoPE + scatter epilogue)
// ---------------------------------------------------------------------------
__global__ void __launch_bounds__(256, 2)
gemm_qkv_fused_kernel(const __nv_bfloat16* __restrict__ Ah, const __nv_bfloat16* __restrict__ Al,
                      const __nv_bfloat16* __restrict__ Wh, const __nv_bfloat16* __restrict__ Wl,
                      const float* __restrict__ gq, const float* __restrict__ gk,
                      const float* __restrict__ cosb, const float* __restrict__ sinb,
                      __nv_bfloat16* __restrict__ QAh, __nv_bfloat16* __restrict__ QAl,
                      __nv_bfloat16* __restrict__ KAh, __nv_bfloat16* __restrict__ KAl,
                      __nv_bfloat16* __restrict__ VAh, __nv_bfloat16* __restrict__ VAl)
{
    extern __shared__ __nv_bfloat16 sm[];
    const int t    = threadIdx.x;
    const int lane = t & 31;
    const int wid  = t >> 5;
    const int wm   = wid >> 1;
    const int wn   = wid & 1;
    const int m0   = blockIdx.y * 128;
    const int n0   = blockIdx.x * 128;
    const int K    = INNER;

    float acc[2][8][4];
#pragma unroll
    for (int i = 0; i < 2; i++)
#pragma unroll
        for (int j = 0; j < 8; j++)
#pragma unroll
            for (int q = 0; q < 4; q++) acc[i][j][q] = 0.f;

    GEMM_V1_MAINLOOP(Ah, Al, Wh, Wl, K, acc)

    const int nhead = (n0 >> 6) + wn;
    const int sec   = nhead >> 4;
    const int hh    = nhead & 15;
    const int dq    = (lane & 3) * 2;
    const int rbase = m0 + wm * 32 + (lane >> 2);

    __nv_bfloat16* outh = (sec == 0) ? QAh : (sec == 1) ? KAh : VAh;
    __nv_bfloat16* outl = (sec == 0) ? QAl : (sec == 1) ? KAl : VAl;
    const float* gvec = (sec == 0) ? gq : gk;
    const float qscale = (sec == 0) ? ATTN_SCALE : 1.0f;

#pragma unroll
    for (int mi = 0; mi < 2; mi++) {
#pragma unroll
        for (int half = 0; half < 2; half++) {
            const int row = rbase + mi * 16 + half * 8;
            const int vi = half * 2;
            const int j = row & 7, tt = row >> 3;
            const size_t dstb = (((size_t)(j * NUM_HEADS + hh)) * STOT + tt) * HEAD_DIM;
            uint32_t* oh32 = (uint32_t*)(outh + dstb);
            uint32_t* ol32 = (uint32_t*)(outl + dstb);

            if (sec == 2) {
#pragma unroll
                for (int nb = 0; nb < 8; nb++) {
                    uint32_t hi, lo;
                    split2(acc[mi][nb][vi], acc[mi][nb][vi + 1], hi, lo);
                    const int d = dq + nb * 8;
                    oh32[d >> 1] = hi;
                    ol32[d >> 1] = lo;
                }
            } else {
                float ss = 0.f;
#pragma unroll
                for (int nb = 0; nb < 8; nb++) {
                    ss += acc[mi][nb][vi] * acc[mi][nb][vi];
                    ss += acc[mi][nb][vi + 1] * acc[mi][nb][vi + 1];
                }
                ss += __shfl_xor_sync(0xffffffffu, ss, 1);
                ss += __shfl_xor_sync(0xffffffffu, ss, 2);
                const float rms = rsqrtf(ss * (1.f / HEAD_DIM) + EPS_RMS);

                const float* cb = cosb + (size_t)row * HEAD_DIM;
                const float* sb = sinb + (size_t)row * HEAD_DIM;
#pragma unroll
                for (int nb = 0; nb < 4; nb++) {
                    const int d0 = dq + nb * 8;
                    const int d1 = d0 + 32;
                    const float x00 = acc[mi][nb][vi]         * rms * gvec[d0];
                    const float x01 = acc[mi][nb][vi + 1]     * rms * gvec[d0 + 1];
                    const float x10 = acc[mi][nb + 4][vi]     * rms * gvec[d1];
                    const float x11 = acc[mi][nb + 4][vi + 1] * rms * gvec[d1 + 1];
                    const float y00 = (x00 * cb[d0]     - x10 * sb[d0])     * qscale;
                    const float y01 = (x01 * cb[d0 + 1] - x11 * sb[d0 + 1]) * qscale;
                    const float y10 = (x10 * cb[d1]     + x00 * sb[d1])     * qscale;
                    const float y11 = (x11 * cb[d1 + 1] + x01 * sb[d1 + 1]) * qscale;
                    uint32_t hi, lo;
                    split2(y00, y01, hi, lo);
                    oh32[d0 >> 1] = hi;
                    ol32[d0 >> 1] = lo;
                    split2(y10, y11, hi, lo);
                    oh32[d1 >> 1] = hi;
                    ol32[d1 >> 1] = lo;
                }
            }
        }
    }
}

// ---------------------------------------------------------------------------
// GEMM v2: 256x128 CTA, 512 threads, 3-stage, K-split (small-M GEMMs)
// ---------------------------------------------------------------------------
#define V2_TILE_A (256 * PADK)
#define V2_TILE_W (128 * PADK)
#define V2_STAGE (2 * V2_TILE_A + 2 * V2_TILE_W)
#define GEMM2_SMEM_BYTES (3 * V2_STAGE * 2)

__global__ void __launch_bounds__(512, 1)
gemm_v2_kernel(const __nv_bfloat16* __restrict__ Ah, const __nv_bfloat16* __restrict__ Al,
               const __nv_bfloat16* __restrict__ Wh, const __nv_bfloat16* __restrict__ Wl,
               float* __restrict__ C, int M, int N, int K, int kparts)
{
    extern __shared__ __nv_bfloat16 sm[];
    const int t    = threadIdx.x;
    const int lane = t & 31;
    const int wid  = t >> 5;
    const int wm   = wid >> 1;
    const int wn   = wid & 1;
    const int m0   = blockIdx.y * 256;
    const int n0   = blockIdx.x * 128;

    const int KC    = K / kparts;
    const int kbase = blockIdx.z * KC;
    const int NT    = KC / 32;

    float acc[2][8][4];
#pragma unroll
    for (int i = 0; i < 2; i++)
#pragma unroll
        for (int j = 0; j < 8; j++)
#pragma unroll
            for (int q = 0; q < 4; q++) acc[i][j][q] = 0.f;

    const int rr = t >> 2;
    const int cc = (t & 3) * 8;
    const uint32_t smb = smem_u32(sm);

    const __nv_bfloat16* pA0 = Ah + (size_t)(m0 + rr)       * K + kbase + cc;
    const __nv_bfloat16* pA1 = Ah + (size_t)(m0 + rr + 128) * K + kbase + cc;
    const __nv_bfloat16* pL0 = Al + (size_t)(m0 + rr)       * K + kbase + cc;
    const __nv_bfloat16* pL1 = Al + (size_t)(m0 + rr + 128) * K + kbase + cc;
    const __nv_bfloat16* pWh = Wh + (size_t)(n0 + rr)       * K + kbase + cc;
    const __nv_bfloat16* pWl = Wl + (size_t)(n0 + rr)       * K + kbase + cc;

    const uint32_t dA0 = (uint32_t)((rr * PADK + cc) << 1);
    const uint32_t dA1 = (uint32_t)(((rr + 128) * PADK + cc) << 1);
    const uint32_t dL0 = dA0 + (uint32_t)(V2_TILE_A << 1);
    const uint32_t dL1 = dA1 + (uint32_t)(V2_TILE_A << 1);
    const uint32_t dWh = dA0 + (uint32_t)((2 * V2_TILE_A) << 1);
    const uint32_t dWl = dA0 + (uint32_t)(((2 * V2_TILE_A) + V2_TILE_W) << 1);

#define V2_LOAD(kt, stg) do {                                              \
    const uint32_t sb = smb + (uint32_t)(((stg) * V2_STAGE) << 1);         \
    const int ko = (kt) * 32;                                              \
    CP_ASYNC16(sb + dA0, pA0 + ko);                                        \
    CP_ASYNC16(sb + dA1, pA1 + ko);                                        \
    CP_ASYNC16(sb + dL0, pL0 + ko);                                        \
    CP_ASYNC16(sb + dL1, pL1 + ko);                                        \
    CP_ASYNC16(sb + dWh, pWh + ko);                                        \
    CP_ASYNC16(sb + dWl, pWl + ko);                                        \
    CP_COMMIT();                                                           \
} while (0)

    V2_LOAD(0, 0);
    V2_LOAD(1, 1);

    const uint32_t abase_rel = (uint32_t)((((wm * 32 + (lane & 15)) * PADK +
                                            ((lane >> 4) << 3))) << 1);
    const uint32_t bbase_rel = (uint32_t)(((2 * V2_TILE_A +
                     (wn * 64 + (lane & 7) + ((lane >> 4) << 3)) * PADK +
                     (((lane >> 3) & 1) << 3))) << 1);

    int stg = 0;
    for (int kt = 0; kt < NT; kt++) {
        if (kt + 2 < NT) {
            const int ps = (stg + 2 >= 3) ? (stg - 1) : (stg + 2);
            V2_LOAD(kt + 2, ps);
            CP_WAIT2();
        } else {
            CP_WAIT0();
        }
        __syncthreads();

        const uint32_t stage  = smb + (uint32_t)((stg * V2_STAGE) << 1);
        const uint32_t abaseh = stage + abase_rel;
        const uint32_t abasel = abaseh + (uint32_t)(V2_TILE_A << 1);
        const uint32_t bbaseh = stage + bbase_rel;
        const uint32_t bbasel = bbaseh + (uint32_t)(V2_TILE_W << 1);

#pragma unroll
        for (int ks = 0; ks < 32; ks += 16) {
            MMA_BLOCK_PIPE(acc, abaseh, abasel, bbaseh, bbasel, ks)
        }
        __syncthreads();
        stg = (stg + 1 >= 3) ? 0 : (stg + 1);
    }

    float* Cz = C + (size_t)blockIdx.z * M * N;
    const int r0 = m0 + wm * 32 + (lane >> 2);
    const int c0 = n0 + wn * 64 + (lane & 3) * 2;
#pragma unroll
    for (int mi = 0; mi < 2; mi++) {
        const int r = r0 + mi * 16;
#pragma unroll
        for (int nb = 0; nb < 8; nb++) {
            const int c = c0 + nb * 8;
            *(float2*)(Cz + (size_t)r * N + c) =
                make_float2(acc[mi][nb][0], acc[mi][nb][1]);
            *(float2*)(Cz + (size_t)(r + 8) * N + c) =
                make_float2(acc[mi][nb][2], acc[mi][nb][3]);
        }
    }
}

// ---------------------------------------------------------------------------
// K-split reduce (with bias)
// ---------------------------------------------------------------------------
__global__ void __launch_bounds__(256)
reduce4_kernel(const float* __restrict__ part, const float* __restrict__ bias,
               float* __restrict__ out, int MN, int N)
{
    const int i = blockIdx.x * 256 + threadIdx.x;
    if (i * 4 >= MN) return;
    const int q = MN / 4;
    float4 a = ((const float4*)part)[i];
    float4 b = ((const float4*)part)[i + q];
    float4 c = ((const float4*)part)[i + 2 * q];
    float4 d = ((const float4*)part)[i + 3 * q];
    float4 r = make_float4(a.x + b.x + c.x + d.x, a.y + b.y + c.y + d.y,
                           a.z + b.z + c.z + d.z, a.w + b.w + c.w + d.w);
    if (bias) {
        const int col = (i * 4) % N;
        r.x += bias[col];  r.y += bias[col + 1];
        r.z += bias[col + 2];  r.w += bias[col + 3];
    }
    ((float4*)out)[i] = r;
}

// ---------------------------------------------------------------------------
// RMSNorm + broadcast scatter (text), reads 4 K-split partials directly
// ---------------------------------------------------------------------------
__global__ void __launch_bounds__(256)
enc_post_kernel(const float* __restrict__ part,
                const float* __restrict__ gaq, const float* __restrict__ gak,
                __nv_bfloat16* __restrict__ QAh, __nv_bfloat16* __restrict__ QAl,
                __nv_bfloat16* __restrict__ KAh, __nv_bfloat16* __restrict__ KAl,
                __nv_bfloat16* __restrict__ VAh, __nv_bfloat16* __restrict__ VAl)
{
    const int warp = (blockIdx.x * blockDim.x + threadIdx.x) >> 5;
    const int lane = threadIdx.x & 31;
    const int tt = warp >> 4;
    const int h  = warp & 15;
    if (tt >= T_LEN) return;

    const size_t src = (size_t)tt * INNER3 + h * HEAD_DIM;
    const size_t PQ = (size_t)T_LEN * INNER3;
    float a0 = 0.f, a1 = 0.f, b0 = 0.f, b1 = 0.f, v0 = 0.f, v1 = 0.f;
#pragma unroll
    for (int z = 0; z < 4; z++) {
        const float* p = part + z * PQ + src;
        a0 += p[lane];              a1 += p[lane + 32];
        b0 += p[INNER + lane];      b1 += p[INNER + lane + 32];
        v0 += p[2*INNER + lane];    v1 += p[2*INNER + lane + 32];
    }

    float ra = rsqrtf(warp_sum32(a0 * a0 + a1 * a1) * (1.f / HEAD_DIM) + EPS_RMS);
    float rb = rsqrtf(warp_sum32(b0 * b0 + b1 * b1) * (1.f / HEAD_DIM) + EPS_RMS);

    a0 *= ra * gaq[lane] * ATTN_SCALE;  a1 *= ra * gaq[lane + 32] * ATTN_SCALE;
    b0 *= rb * gak[lane];               b1 *= rb * gak[lane + 32];

#pragma unroll
    for (int j = 0; j < SPARSE_N; j++) {
        const size_t dst =
            (((size_t)(j * NUM_HEADS + h)) * STOT + G_LEN + tt) * HEAD_DIM;
        store_split(QAh, QAl, dst + lane,      a0);
        store_split(QAh, QAl, dst + lane + 32, a1);
        store_split(KAh, KAl, dst + lane,      b0);
        store_split(KAh, KAl, dst + lane + 32, b1);
        store_split(VAh, VAl, dst + lane,      v0);
        store_split(VAh, VAl, dst + lane + 32, v1);
    }
}

// ---------------------------------------------------------------------------
// Flash attention, BQ=256, 512 threads, cp.async K/V double buffering.
// Pipelined B-fragments in score and PV loops. Fused vis gather.
// ---------------------------------------------------------------------------
#define APAD 72
#define AQ_ELEMS (2 * 256 * APAD)
#define KV_TILE  (64 * APAD)
#define KV_STAGE (4 * KV_TILE)
#define ATT_SM_BYTES ((AQ_ELEMS + 2 * KV_STAGE) * 2)

__global__ void __launch_bounds__(512, 1)
attn_mma_kernel(const __nv_bfloat16* __restrict__ Qhg, const __nv_bfloat16* __restrict__ Qlg,
                const __nv_bfloat16* __restrict__ Khg, const __nv_bfloat16* __restrict__ Klg,
                const __nv_bfloat16* __restrict__ Vhg, const __nv_bfloat16* __restrict__ Vlg,
                float* __restrict__ OA,
                __nv_bfloat16* __restrict__ vis_h, __nv_bfloat16* __restrict__ vis_l)
{
    extern __shared__ __nv_bfloat16 smA[];
    const int t    = threadIdx.x;
    const int lane = t & 31;
    const int w    = t >> 5;
    const int jh   = blockIdx.y;
    const int q0   = blockIdx.x * 256;
    const size_t base = (size_t)jh * STOT * HEAD_DIM;

    const uint32_t smb = smem_u32(smA);

    const int tile = t >> 7;
    const int l128 = t & 127;
    const int krr  = l128 >> 3;
    const int kcc  = (l128 & 7) * 8;
    const __nv_bfloat16* kvsrc =
        (tile == 0) ? Khg : (tile == 1) ? Klg : (tile == 2) ? Vhg : Vlg;
    const uint32_t kvdst0 = smb + ((AQ_ELEMS + tile * KV_TILE + krr * APAD + kcc) << 1);

    {
        const __nv_bfloat16* g = kvsrc + base + (size_t)krr * 64 + kcc;
#pragma unroll
        for (int i = 0; i < 4; i++)
            CP_ASYNC16(kvdst0 + (uint32_t)((i * 16 * APAD) << 1),
                       g + (size_t)(i * 16) * 64);
        CP_COMMIT();
    }

    {
        const int row = t >> 1, c0 = (t & 1) * 32;
        const __nv_bfloat16* gh = Qhg + base + (size_t)(q0 + row) * 64 + c0;
        const __nv_bfloat16* gl = Qlg + base + (size_t)(q0 + row) * 64 + c0;
        __nv_bfloat16* sh = smA + row * APAD + c0;
        __nv_bfloat16* sl = smA + 256 * APAD + row * APAD + c0;
#pragma unroll
        for (int c = 0; c < 32; c += 8) {
            *(uint4*)(sh + c) = *(const uint4*)(gh + c);
            *(uint4*)(sl + c) = *(const uint4*)(gl + c);
        }
    }

    float o[8][4];
#pragma unroll
    for (int i = 0; i < 8; i++)
#pragma unroll
        for (int j = 0; j < 4; j++) o[i][j] = 0.f;
    float m0r = -1e30f, m1r = -1e30f, l0r = 0.f, l1r = 0.f;

    const uint32_t qfragh = smb + (((w * 16 + (lane & 15)) * APAD + ((lane >> 4) << 3)) << 1);
    const uint32_t qfragl = qfragh + ((256 * APAD) << 1);
    const uint32_t kfrag_rel = ((((lane & 7) + ((lane >> 4) << 3)) * APAD + (((lane >> 3) & 1) << 3)) << 1);
    const uint32_t vfrag_rel = (((2 * KV_TILE) + ((lane & 7) + (((lane >> 3) & 1) << 3)) * APAD + ((lane >> 4) << 3)) << 1);

    for (int kt = 0; kt < 20; kt++) {
        const int b = kt & 1;
        if (kt + 1 < 20) {
            const __nv_bfloat16* g = kvsrc + base + (size_t)((kt + 1) * 64 + krr) * 64 + kcc;
            const uint32_t d = kvdst0 + (uint32_t)((((kt + 1) & 1) * KV_STAGE) << 1);
#pragma unroll
            for (int i = 0; i < 4; i++)
                CP_ASYNC16(d + (uint32_t)((i * 16 * APAD) << 1),
                           g + (size_t)(i * 16) * 64);
            CP_COMMIT();
            CP_WAIT1();
        } else {
            CP_WAIT0();
        }
        __syncthreads();

        const uint32_t kvstage = smb + (uint32_t)(((AQ_ELEMS + b * KV_STAGE)) << 1);
        const uint32_t kfragh = kvstage + kfrag_rel;
        const uint32_t kfragl = kfragh + (KV_TILE << 1);
        const uint32_t vfrag  = kvstage + vfrag_rel;

        float s[8][4];
#pragma unroll
        for (int i = 0; i < 8; i++)
#pragma unroll
            for (int j = 0; j < 4; j++) s[i][j] = 0.f;

        // ---- scores (pipelined K fragments) ----
#pragma unroll
        for (int ks = 0; ks < 64; ks += 16) {
            uint32_t ah[4], al[4];
            ldsm_x4(ah, qfragh + ks * 2);
            ldsm_x4(al, qfragl + ks * 2);
            uint32_t kh[2][4], kl[4], kln[4];
            ldsm_x4(kh[0], kfragh + ks * 2);
            ldsm_x4(kl,    kfragl + ks * 2);
#pragma unroll
            for (int nbp = 0; nbp < 4; nbp++) {
                const int c = nbp & 1;
                mma16816(s[2 * nbp],     ah, kh[c]);
                mma16816(s[2 * nbp + 1], ah, kh[c] + 2);
                if (nbp < 3)
                    ldsm_x4(kh[c ^ 1], kfragh + ks * 2 + (nbp + 1) * 16 * APAD * 2);
                mma16816(s[2 * nbp],     ah, kl);
                mma16816(s[2 * nbp + 1], ah, kl + 2);
                if (nbp < 3)
                    ldsm_x4(kln, kfragl + ks * 2 + (nbp + 1) * 16 * APAD * 2);
                mma16816(s[2 * nbp],     al, kh[c]);
                mma16816(s[2 * nbp + 1], al, kh[c] + 2);
                if (nbp < 3) {
                    kl[0] = kln[0]; kl[1] = kln[1];
                    kl[2] = kln[2]; kl[3] = kln[3];
                }
            }
        }

        // ---- online softmax ----
        float mt0 = -1e30f, mt1 = -1e30f;
#pragma unroll
        for (int nb = 0; nb < 8; nb++) {
            mt0 = fmaxf(mt0, fmaxf(s[nb][0], s[nb][1]));
            mt1 = fmaxf(mt1, fmaxf(s[nb][2], s[nb][3]));
        }
        mt0 = fmaxf(mt0, __shfl_xor_sync(0xffffffffu, mt0, 1));
        mt0 = fmaxf(mt0, __shfl_xor_sync(0xffffffffu, mt0, 2));
        mt1 = fmaxf(mt1, __shfl_xor_sync(0xffffffffu, mt1, 1));
        mt1 = fmaxf(mt1, __shfl_xor_sync(0xffffffffu, mt1, 2));
        const float mn0 = fmaxf(m0r, mt0), mn1 = fmaxf(m1r, mt1);
        const float cf0 = __expf(m0r - mn0), cf1 = __expf(m1r - mn1);
        m0r = mn0;  m1r = mn1;
        float rs0 = 0.f, rs1 = 0.f;
#pragma unroll
        for (int nb = 0; nb < 8; nb++) {
            s[nb][0] = __expf(s[nb][0] - mn0);  rs0 += s[nb][0];
            s[nb][1] = __expf(s[nb][1] - mn0);  rs0 += s[nb][1];
            s[nb][2] = __expf(s[nb][2] - mn1);  rs1 += s[nb][2];
            s[nb][3] = __expf(s[nb][3] - mn1);  rs1 += s[nb][3];
        }
        rs0 += __shfl_xor_sync(0xffffffffu, rs0, 1);
        rs0 += __shfl_xor_sync(0xffffffffu, rs0, 2);
        rs1 += __shfl_xor_sync(0xffffffffu, rs1, 1);
        rs1 += __shfl_xor_sync(0xffffffffu, rs1, 2);
        l0r = l0r * cf0 + rs0;
        l1r = l1r * cf1 + rs1;
#pragma unroll
        for (int db = 0; db < 8; db++) {
            o[db][0] *= cf0;  o[db][1] *= cf0;
            o[db][2] *= cf1;  o[db][3] *= cf1;
        }

        // ---- PV (pipelined V fragments) ----
#pragma unroll
        for (int kb2 = 0; kb2 < 4; kb2++) {
            uint32_t ph[4], pl[4];
            split2(s[2 * kb2][0],     s[2 * kb2][1],     ph[0], pl[0]);
            split2(s[2 * kb2][2],     s[2 * kb2][3],     ph[1], pl[1]);
            split2(s[2 * kb2 + 1][0], s[2 * kb2 + 1][1], ph[2], pl[2]);
            split2(s[2 * kb2 + 1][2], s[2 * kb2 + 1][3], ph[3], pl[3]);
            const uint32_t vb = vfrag + kb2 * 16 * APAD * 2;
            uint32_t vh[2][4], vl[4], vln[4];
            ldsm_x4_t(vh[0], vb);
            ldsm_x4_t(vl, vb + (KV_TILE << 1));
#pragma unroll
            for (int dbp = 0; dbp < 4; dbp++) {
                const int c = dbp & 1;
                mma16816(o[2 * dbp],     ph, vh[c]);
                mma16816(o[2 * dbp + 1], ph, vh[c] + 2);
                if (dbp < 3)
                    ldsm_x4_t(vh[c ^ 1], vb + (dbp + 1) * 16 * 2);
                mma16816(o[2 * dbp],     ph, vl);
                mma16816(o[2 * dbp + 1], ph, vl + 2);
                if (dbp < 3)
                    ldsm_x4_t(vln, vb + (KV_TILE << 1) + (dbp + 1) * 16 * 2);
                mma16816(o[2 * dbp],     pl, vh[c]);
                mma16816(o[2 * dbp + 1], pl, vh[c] + 2);
                if (dbp < 3) {
                    vl[0] = vln[0]; vl[1] = vln[1];
                    vl[2] = vln[2]; vl[3] = vln[3];
                }
            }
        }
        __syncthreads();
    }

    const float inv0 = 1.f / l0r, inv1 = 1.f / l1r;
    const int row = q0 + w * 16 + (lane >> 2);
    const int col = (lane & 3) * 2;
    if (blockIdx.x < 4) {
        const int j = jh >> 4, h = jh & 15;
        uint32_t* vh32 = (uint32_t*)vis_h;
        uint32_t* vl32 = (uint32_t*)vis_l;
        const size_t b0 = ((size_t)row * 8 + j) * INNER + h * 64;
        const size_t b1 = ((size_t)(row + 8) * 8 + j) * INNER + h * 64;
#pragma unroll
        for (int db = 0; db < 8; db++) {
            uint32_t hi, lo;
            split2(o[db][0] * inv0, o[db][1] * inv0, hi, lo);
            vh32[(b0 + db * 8 + col) >> 1] = hi;
            vl32[(b0 + db * 8 + col) >> 1] = lo;
            split2(o[db][2] * inv1, o[db][3] * inv1, hi, lo);
            vh32[(b1 + db * 8 + col) >> 1] = hi;
            vl32[(b1 + db * 8 + col) >> 1] = lo;
        }
    } else {
#pragma unroll
        for (int db = 0; db < 8; db++) {
            *(float2*)(OA + base + (size_t)row * 64 + db * 8 + col) =
                make_float2(o[db][0] * inv0, o[db][1] * inv0);
            *(float2*)(OA + base + (size_t)(row + 8) * 64 + db * 8 + col) =
                make_float2(o[db][2] * inv1, o[db][3] * inv1);
        }
    }
}

// ---------------------------------------------------------------------------
// Gather text rows -> bf16 hi/lo (mean over j)
// ---------------------------------------------------------------------------
__global__ void __launch_bounds__(256)
gather_txt_kernel(const float* __restrict__ OA,
                  __nv_bfloat16* __restrict__ th, __nv_bfloat16* __restrict__ tl)
{
    const int i = blockIdx.x * 256 + threadIdx.x;
    const int idx = i * 4;
    const int tt = idx >> 10, e = idx & 1023;
    const int h = e >> 6, d = e & 63;
    float4 acc = make_float4(0.f, 0.f, 0.f, 0.f);
#pragma unroll
    for (int j = 0; j < SPARSE_N; j++) {
        float4 v = *(const float4*)(OA +
            (((size_t)(j * NUM_HEADS + h)) * STOT + G_LEN + tt) * HEAD_DIM + d);
        acc.x += v.x; acc.y += v.y; acc.z += v.z; acc.w += v.w;
    }
    acc.x *= 0.125f; acc.y *= 0.125f; acc.z *= 0.125f; acc.w *= 0.125f;
    uint32_t h01, l01, h23, l23;
    split2(acc.x, acc.y, h01, l01);
    split2(acc.z, acc.w, h23, l23);
    ((uint2*)th)[i] = make_uint2(h01, h23);
    ((uint2*)tl)[i] = make_uint2(l01, l23);
}

// ---------------------------------------------------------------------------
// kernel_launch
// ---------------------------------------------------------------------------
extern "C" void kernel_launch(void* const* d_in, const int* in_sizes, int n_in,
                              void* d_out, int out_size)
{
    const float* hs   = (const float*)d_in[0];
    const float* enc  = (const float*)d_in[1];
    const float* bout  = (const float*)d_in[9];
    const float* baout = (const float*)d_in[11];
    const float* gq   = (const float*)d_in[12];
    const float* gk   = (const float*)d_in[13];
    const float* gaq  = (const float*)d_in[14];
    const float* gak  = (const float*)d_in[15];
    const float* rc   = (const float*)d_in[16];
    const float* rs   = (const float*)d_in[17];
    float* out = (float*)d_out;

    float *encpart, *txtpart, *OA;
    __nv_bfloat16 *hs_h, *hs_l, *enc_h, *enc_l, *w_h, *w_l;
    __nv_bfloat16 *vis_h, *vis_l, *txt_h, *txt_l;
    __nv_bfloat16 *QAh, *QAl, *KAh, *KAl, *VAh, *VAl;
    cudaGetSymbolAddress((void**)&encpart, g_encpart);
    cudaGetSymbolAddress((void**)&txtpart, g_txtpart);
    cudaGetSymbolAddress((void**)&OA,    g_OA);
    cudaGetSymbolAddress((void**)&hs_h,  g_hs_h);
    cudaGetSymbolAddress((void**)&hs_l,  g_hs_l);
    cudaGetSymbolAddress((void**)&enc_h, g_enc_h);
    cudaGetSymbolAddress((void**)&enc_l, g_enc_l);
    cudaGetSymbolAddress((void**)&w_h,   g_w_h);
    cudaGetSymbolAddress((void**)&w_l,   g_w_l);
    cudaGetSymbolAddress((void**)&vis_h, g_vis_h);
    cudaGetSymbolAddress((void**)&vis_l, g_vis_l);
    cudaGetSymbolAddress((void**)&txt_h, g_txt_h);
    cudaGetSymbolAddress((void**)&txt_l, g_txt_l);
    cudaGetSymbolAddress((void**)&QAh,   g_QAh);
    cudaGetSymbolAddress((void**)&QAl,   g_QAl);
    cudaGetSymbolAddress((void**)&KAh,   g_KAh);
    cudaGetSymbolAddress((void**)&KAl,   g_KAl);
    cudaGetSymbolAddress((void**)&VAh,   g_VAh);
    cudaGetSymbolAddress((void**)&VAl,   g_VAl);

    cudaFuncSetAttribute(gemm_bf3_kernel,
                         cudaFuncAttributeMaxDynamicSharedMemorySize, GEMM1_SMEM_BYTES);
    cudaFuncSetAttribute(gemm_qkv_fused_kernel,
                         cudaFuncAttributeMaxDynamicSharedMemorySize, GEMM1_SMEM_BYTES);
    cudaFuncSetAttribute(gemm_v2_kernel,
                         cudaFuncAttributeMaxDynamicSharedMemorySize, GEMM2_SMEM_BYTES);
    cudaFuncSetAttribute(attn_mma_kernel,
                         cudaFuncAttributeMaxDynamicSharedMemorySize, ATT_SM_BYTES);

    const size_t WS = (size_t)INNER * INNER;

    // [0] weight conversions, [1] hs+enc conversions
    cvt8_kernel<<<8192, 256>>>(
        (const float*)d_in[2], (const float*)d_in[3], (const float*)d_in[4],
        (const float*)d_in[5], (const float*)d_in[6], (const float*)d_in[7],
        (const float*)d_in[8], (const float*)d_in[10], w_h, w_l);
    cvt_hsenc_kernel<<<8448, 256>>>(hs, enc, hs_h, hs_l, enc_h, enc_l);

    // [2] enc QKV GEMM (v2, K-split x4), [3] enc post (fused reduce)
    gemm_v2_kernel<<<dim3(INNER3 / 128, 1, 4), 512, GEMM2_SMEM_BYTES>>>(
        enc_h, enc_l, w_h + 3 * WS, w_l + 3 * WS, encpart, T_LEN, INNER3, INNER, 4);
    enc_post_kernel<<<(T_LEN * NUM_HEADS) / 8, 256>>>(
        encpart, gaq, gak, QAh, QAl, KAh, KAl, VAh, VAl);

    // [4] big QKV GEMM (fused epilogue)
    gemm_qkv_fused_kernel<<<dim3(INNER3 / 128, S_LEN / 128), 256, GEMM1_SMEM_BYTES>>>(
        hs_h, hs_l, w_h + 0 * WS, w_l + 0 * WS,
        gq, gk, rc, rs, QAh, QAl, KAh, KAl, VAh, VAl);

    // [5] attention (fused vis gather)  <- profiled launch
    attn_mma_kernel<<<dim3(STOT / 256, NJH), 512, ATT_SM_BYTES>>>(
        QAh, QAl, KAh, KAl, VAh, VAl, OA, vis_h, vis_l);

    // [6] text gather
    gather_txt_kernel<<<(T_LEN * INNER / 4) / 256, 256>>>(OA, txt_h, txt_l);

    // [7] vis out GEMM (v1, bias)
    gemm_bf3_kernel<<<dim3(INNER / 128, S_LEN / 128), 256, GEMM1_SMEM_BYTES>>>(
        vis_h, vis_l, w_h + 6 * WS, w_l + 6 * WS, bout, out, S_LEN, INNER, INNER);

    // [8] txt out GEMM (v2, K-split x4), [9] reduce with bias
    gemm_v2_kernel<<<dim3(INNER / 128, 1, 4), 512, GEMM2_SMEM_BYTES>>>(
        txt_h, txt_l, w_h + 7 * WS, w_l + 7 * WS, txtpart, T_LEN, INNER, INNER, 4);
    reduce4_kernel<<<(T_LEN * INNER / 4) / 256, 256>>>(
        txtpart, baout, out + (size_t)S_LEN * INNER, T_LEN * INNER, INNER);
}

// round 11
// speedup vs baseline: 1.0975x; 1.0303x over previous
#include <cuda_runtime.h>
#include <cuda_bf16.h>
#include <math.h>
#include <stdint.h>

// ---------------------------------------------------------------------------
// Problem constants
// ---------------------------------------------------------------------------
#define S_LEN     8192
#define T_LEN     256
#define NUM_HEADS 16
#define HEAD_DIM  64
#define INNER     1024
#define INNER3    3072
#define SPARSE_N  8
#define G_LEN     1024
#define STOT      1280
#define NJH       128
#define EPS_RMS   1e-5f
#define ATTN_SCALE 0.125f
#define SMAX      8.0f          // Cauchy-Schwarz bound on scores (|q|=1, |k|=8)
#define ATT_ELEMS (NJH * STOT * HEAD_DIM)

// ---------------------------------------------------------------------------
// Static device scratch
// ---------------------------------------------------------------------------
__device__ float g_encpart[4 * T_LEN * INNER3];
__device__ float g_txtpart[4 * T_LEN * INNER];
__device__ float g_OA[ATT_ELEMS];

__device__ __nv_bfloat16 g_hs_h[S_LEN * INNER];
__device__ __nv_bfloat16 g_hs_l[S_LEN * INNER];
__device__ __nv_bfloat16 g_enc_h[T_LEN * INNER];
__device__ __nv_bfloat16 g_enc_l[T_LEN * INNER];
__device__ __nv_bfloat16 g_w_h[8 * INNER * INNER];
__device__ __nv_bfloat16 g_w_l[8 * INNER * INNER];
__device__ __nv_bfloat16 g_vis_h[S_LEN * INNER];
__device__ __nv_bfloat16 g_vis_l[S_LEN * INNER];
__device__ __nv_bfloat16 g_txt_h[T_LEN * INNER];
__device__ __nv_bfloat16 g_txt_l[T_LEN * INNER];
__device__ __nv_bfloat16 g_QAh[ATT_ELEMS];
__device__ __nv_bfloat16 g_QAl[ATT_ELEMS];
__device__ __nv_bfloat16 g_KAh[ATT_ELEMS];
__device__ __nv_bfloat16 g_KAl[ATT_ELEMS];
__device__ __nv_bfloat16 g_VAh[ATT_ELEMS];
__device__ __nv_bfloat16 g_VAl[ATT_ELEMS];

// ---------------------------------------------------------------------------
// Helpers
// ---------------------------------------------------------------------------
__device__ __forceinline__ uint32_t smem_u32(const void* p) {
    uint32_t a;
    asm("{ .reg .u64 t; cvta.to.shared.u64 t, %1; cvt.u32.u64 %0, t; }"
        : "=r"(a) : "l"(p));
    return a;
}

#define CP_ASYNC16(dst, src) \
    asm volatile("cp.async.cg.shared.global [%0], [%1], 16;" :: "r"(dst), "l"(src))
#define CP_COMMIT() asm volatile("cp.async.commit_group;" ::: "memory")
#define CP_WAIT0()  asm volatile("cp.async.wait_group 0;" ::: "memory")
#define CP_WAIT1()  asm volatile("cp.async.wait_group 1;" ::: "memory")
#define CP_WAIT2()  asm volatile("cp.async.wait_group 2;" ::: "memory")

__device__ __forceinline__ void ldsm_x4(uint32_t* r, uint32_t a) {
    asm volatile("ldmatrix.sync.aligned.m8n8.x4.shared.b16 {%0,%1,%2,%3}, [%4];"
        : "=r"(r[0]), "=r"(r[1]), "=r"(r[2]), "=r"(r[3]) : "r"(a));
}
__device__ __forceinline__ void ldsm_x4_t(uint32_t* r, uint32_t a) {
    asm volatile("ldmatrix.sync.aligned.m8n8.x4.trans.shared.b16 {%0,%1,%2,%3}, [%4];"
        : "=r"(r[0]), "=r"(r[1]), "=r"(r[2]), "=r"(r[3]) : "r"(a));
}
__device__ __forceinline__ void mma16816(float* c, const uint32_t* a, const uint32_t* b) {
    asm volatile(
        "mma.sync.aligned.m16n8k16.row.col.f32.bf16.bf16.f32 "
        "{%0,%1,%2,%3}, {%4,%5,%6,%7}, {%8,%9}, {%0,%1,%2,%3};"
        : "+f"(c[0]), "+f"(c[1]), "+f"(c[2]), "+f"(c[3])
        : "r"(a[0]), "r"(a[1]), "r"(a[2]), "r"(a[3]), "r"(b[0]), "r"(b[1]));
}

__device__ __forceinline__ uint32_t packbf(__nv_bfloat16 x, __nv_bfloat16 y) {
    return (uint32_t)__bfloat16_as_ushort(x) | ((uint32_t)__bfloat16_as_ushort(y) << 16);
}
__device__ __forceinline__ void split2(float x, float y, uint32_t& hi, uint32_t& lo) {
    __nv_bfloat16 hx = __float2bfloat16(x), hy = __float2bfloat16(y);
    __nv_bfloat16 lx = __float2bfloat16(x - __bfloat162float(hx));
    __nv_bfloat16 ly = __float2bfloat16(y - __bfloat162float(hy));
    hi = packbf(hx, hy);
    lo = packbf(lx, ly);
}
__device__ __forceinline__ void store_split(__nv_bfloat16* ph, __nv_bfloat16* pl,
                                            size_t idx, float v) {
    __nv_bfloat16 h = __float2bfloat16(v);
    ph[idx] = h;
    pl[idx] = __float2bfloat16(v - __bfloat162float(h));
}
__device__ __forceinline__ float warp_sum32(float v) {
#pragma unroll
    for (int o = 16; o > 0; o >>= 1)
        v += __shfl_xor_sync(0xffffffffu, v, o);
    return v;
}

__device__ __forceinline__ void cvt4(const float* __restrict__ src,
                                     __nv_bfloat16* __restrict__ hi,
                                     __nv_bfloat16* __restrict__ lo,
                                     int base /* float4 units */)
{
    // 4 float4 per thread, stride 256 (MLP=4)
    float4 v0 = ((const float4*)src)[base];
    float4 v1 = ((const float4*)src)[base + 256];
    float4 v2 = ((const float4*)src)[base + 512];
    float4 v3 = ((const float4*)src)[base + 768];
    uint32_t a, b, c, d;
    split2(v0.x, v0.y, a, c);  split2(v0.z, v0.w, b, d);
    ((uint2*)hi)[base] = make_uint2(a, b);
    ((uint2*)lo)[base] = make_uint2(c, d);
    split2(v1.x, v1.y, a, c);  split2(v1.z, v1.w, b, d);
    ((uint2*)hi)[base + 256] = make_uint2(a, b);
    ((uint2*)lo)[base + 256] = make_uint2(c, d);
    split2(v2.x, v2.y, a, c);  split2(v2.z, v2.w, b, d);
    ((uint2*)hi)[base + 512] = make_uint2(a, b);
    ((uint2*)lo)[base + 512] = make_uint2(c, d);
    split2(v3.x, v3.y, a, c);  split2(v3.z, v3.w, b, d);
    ((uint2*)hi)[base + 768] = make_uint2(a, b);
    ((uint2*)lo)[base + 768] = make_uint2(c, d);
}

// ---------------------------------------------------------------------------
// Conversions with 4x ILP: weights (2048 blocks) and hs+enc (2112 blocks)
// ---------------------------------------------------------------------------
__global__ void __launch_bounds__(256)
cvt_w_kernel(const float* w0, const float* w1, const float* w2, const float* w3,
             const float* w4, const float* w5, const float* w6, const float* w7,
             __nv_bfloat16* __restrict__ hi, __nv_bfloat16* __restrict__ lo)
{
    const int wi = blockIdx.x >> 8;                 // 0..7
    const int ib = (blockIdx.x & 255) * 1024 + threadIdx.x;
    const float* src;
    switch (wi) {
        case 0: src = w0; break;  case 1: src = w1; break;
        case 2: src = w2; break;  case 3: src = w3; break;
        case 4: src = w4; break;  case 5: src = w5; break;
        case 6: src = w6; break;  default: src = w7; break;
    }
    const size_t off = (size_t)wi * (INNER * INNER / 4);
    cvt4(src, (__nv_bfloat16*)((uint2*)hi + off) - 0,  // base pointers per weight
         (__nv_bfloat16*)((uint2*)lo + off) - 0, ib);
}

__global__ void __launch_bounds__(256)
cvt_hsenc_kernel(const float* __restrict__ hs, const float* __restrict__ enc,
                 __nv_bfloat16* __restrict__ hs_h, __nv_bfloat16* __restrict__ hs_l,
                 __nv_bfloat16* __restrict__ enc_h, __nv_bfloat16* __restrict__ enc_l)
{
    const int bx = blockIdx.x;
    if (bx < 2048) {
        cvt4(hs, hs_h, hs_l, bx * 1024 + threadIdx.x);
    } else {
        cvt4(enc, enc_h, enc_l, (bx - 2048) * 1024 + threadIdx.x);
    }
}

// ---------------------------------------------------------------------------
// Pipelined 3-pass MMA block
// ---------------------------------------------------------------------------
#define MMA_BLOCK_PIPE(acc, abaseh, abasel, bbaseh, bbasel, ks)               \
    {                                                                         \
        uint32_t a0h[4], a1h[4], a0l[4], a1l[4];                              \
        ldsm_x4(a0h, (abaseh) + (ks) * 2);                                    \
        ldsm_x4(a1h, (abaseh) + (ks) * 2 + 16 * PADK * 2);                    \
        ldsm_x4(a0l, (abasel) + (ks) * 2);                                    \
        ldsm_x4(a1l, (abasel) + (ks) * 2 + 16 * PADK * 2);                    \
        uint32_t bh[2][4], bl[4], bln[4];                                     \
        ldsm_x4(bh[0], (bbaseh) + (ks) * 2);                                  \
        ldsm_x4(bl,    (bbasel) + (ks) * 2);                                  \
        _Pragma("unroll")                                                     \
        for (int nbp = 0; nbp < 4; nbp++) {                                   \
            const int c = nbp & 1;                                            \
            mma16816(acc[0][2 * nbp],     a0h, bh[c]);                        \
            mma16816(acc[0][2 * nbp + 1], a0h, bh[c] + 2);                    \
            mma16816(acc[1][2 * nbp],     a1h, bh[c]);                        \
            mma16816(acc[1][2 * nbp + 1], a1h, bh[c] + 2);                    \
            if (nbp < 3)                                                      \
                ldsm_x4(bh[c ^ 1], (bbaseh) + (ks) * 2 +                      \
                        (nbp + 1) * 16 * PADK * 2);                           \
            mma16816(acc[0][2 * nbp],     a0h, bl);                           \
            mma16816(acc[0][2 * nbp + 1], a0h, bl + 2);                       \
            mma16816(acc[1][2 * nbp],     a1h, bl);                           \
            mma16816(acc[1][2 * nbp + 1], a1h, bl + 2);                       \
            if (nbp < 3)                                                      \
                ldsm_x4(bln, (bbasel) + (ks) * 2 +                            \
                        (nbp + 1) * 16 * PADK * 2);                           \
            mma16816(acc[0][2 * nbp],     a0l, bh[c]);                        \
            mma16816(acc[0][2 * nbp + 1], a0l, bh[c] + 2);                    \
            mma16816(acc[1][2 * nbp],     a1l, bh[c]);                        \
            mma16816(acc[1][2 * nbp + 1], a1l, bh[c] + 2);                    \
            if (nbp < 3) {                                                    \
                bl[0] = bln[0]; bl[1] = bln[1];                               \
                bl[2] = bln[2]; bl[3] = bln[3];                               \
            }                                                                 \
        }                                                                     \
    }

// ---------------------------------------------------------------------------
// Shared GEMM mainloop (v1): 128x128 CTA, 256 threads, 2 CTAs/SM, 2-stage.
// ---------------------------------------------------------------------------
#define PADK 40
#define GT_TILE  (128 * PADK)
#define GT_STAGE (4 * GT_TILE)
#define GEMM1_SMEM_BYTES (2 * GT_STAGE * 2)

#define GEMM_V1_MAINLOOP(Ah, Al, Wh, Wl, K, acc)                              \
    const int tile = t >> 6;                                                  \
    const int l64  = t & 63;                                                  \
    const int lrr  = l64 >> 2;                                                \
    const int lcc  = (l64 & 3) * 8;                                           \
    const __nv_bfloat16* gsrc =                                               \
        (tile == 0) ? Ah : (tile == 1) ? Al : (tile == 2) ? Wh : Wl;          \
    const int rowbase = (tile < 2) ? m0 : n0;                                 \
    const uint32_t smb = smem_u32(sm);                                        \
    const uint32_t sdst0 = smb + ((tile * GT_TILE + lrr * PADK + lcc) << 1);  \
    const __nv_bfloat16* gp = gsrc + (size_t)(rowbase + lrr) * K + lcc;       \
    const uint32_t abase_rel = (((wm * 32 + (lane & 15)) * PADK +             \
                                 ((lane >> 4) << 3)) << 1);                   \
    const uint32_t bbase_rel = ((2 * GT_TILE +                                \
        (wn * 64 + (lane & 7) + ((lane >> 4) << 3)) * PADK +                  \
        (((lane >> 3) & 1) << 3)) << 1);                                      \
    const int NT = K / 32;                                                    \
    {                                                                         \
        const __nv_bfloat16* g = gp;                                          \
        _Pragma("unroll")                                                     \
        for (int i = 0; i < 8; i++)                                           \
            CP_ASYNC16(sdst0 + (uint32_t)((i * 16 * PADK) << 1),              \
                       g + (size_t)(i * 16) * K);                             \
        CP_COMMIT();                                                          \
    }                                                                         \
    for (int kt = 0; kt < NT; kt++) {                                         \
        const int b = kt & 1;                                                 \
        if (kt + 1 < NT) {                                                    \
            const __nv_bfloat16* g = gp + (kt + 1) * 32;                      \
            const uint32_t d = sdst0 +                                        \
                (uint32_t)((((kt + 1) & 1) * GT_STAGE) << 1);                 \
            _Pragma("unroll")                                                 \
            for (int i = 0; i < 8; i++)                                       \
                CP_ASYNC16(d + (uint32_t)((i * 16 * PADK) << 1),              \
                           g + (size_t)(i * 16) * K);                         \
            CP_COMMIT();                                                      \
            CP_WAIT1();                                                       \
        } else {                                                              \
            CP_WAIT0();                                                       \
        }                                                                     \
        __syncthreads();                                                      \
        const uint32_t stage  = smb + (uint32_t)((b * GT_STAGE) << 1);        \
        const uint32_t abaseh = stage + abase_rel;                            \
        const uint32_t abasel = abaseh + (GT_TILE << 1);                      \
        const uint32_t bbaseh = stage + bbase_rel;                            \
        const uint32_t bbasel = bbaseh + (GT_TILE << 1);                      \
        _Pragma("unroll")                                                     \
        for (int ks = 0; ks < 32; ks += 16) {                                 \
            MMA_BLOCK_PIPE(acc, abaseh, abasel, bbaseh, bbasel, ks)           \
        }                                                                     \
        __syncthreads();                                                      \
    }

// ---------------------------------------------------------------------------
// Generic v1 GEMM (fp32 C + optional bias)
// ---------------------------------------------------------------------------
__global__ void __launch_bounds__(256, 2)
gemm_bf3_kernel(const __nv_bfloat16* __restrict__ Ah, const __nv_bfloat16* __restrict__ Al,
                const __nv_bfloat16* __restrict__ Wh, const __nv_bfloat16* __restrict__ Wl,
                const float* __restrict__ bias, float* __restrict__ C,
                int M, int N, int K)
{
    extern __shared__ __nv_bfloat16 sm[];
    const int t    = threadIdx.x;
    const int lane = t & 31;
    const int wid  = t >> 5;
    const int wm   = wid >> 1;
    const int wn   = wid & 1;
    const int m0   = blockIdx.y * 128;
    const int n0   = blockIdx.x * 128;

    float acc[2][8][4];
#pragma unroll
    for (int i = 0; i < 2; i++)
#pragma unroll
        for (int j = 0; j < 8; j++)
#pragma unroll
            for (int q = 0; q < 4; q++) acc[i][j][q] = 0.f;

    GEMM_V1_MAINLOOP(Ah, Al, Wh, Wl, K, acc)

    const int r0 = m0 + wm * 32 + (lane >> 2);
    const int c0 = n0 + wn * 64 + (lane & 3) * 2;
#pragma unroll
    for (int mi = 0; mi < 2; mi++) {
        const int r = r0 + mi * 16;
#pragma unroll
        for (int nb = 0; nb < 8; nb++) {
            const int c = c0 + nb * 8;
            float b0 = 0.f, b1 = 0.f;
            if (bias) { b0 = bias[c]; b1 = bias[c + 1]; }
            *(float2*)(C + (size_t)r * N + c) =
                make_float2(acc[mi][nb][0] + b0, acc[mi][nb][1] + b1);
            *(float2*)(C + (size_t)(r + 8) * N + c) =
                make_float2(acc[mi][nb][2] + b0, acc[mi][nb][3] + b1);
        }
    }
}

// ---------------------------------------------------------------------------
// Fused QKV GEMM (RMSNorm + RoPE + scatter epilogue)
// ---------------------------------------------------------------------------
__global__ void __launch_bounds__(256, 2)
gemm_qkv_fused_kernel(const __nv_bfloat16* __restrict__ Ah, const __nv_bfloat16* __restrict__ Al,
                      const __nv_bfloat16* __restrict__ Wh, const __nv_bfloat16* __restrict__ Wl,
                      const float* __restrict__ gq, const float* __restrict__ gk,
                      const float* __restrict__ cosb, const float* __restrict__ sinb,
                      __nv_bfloat16* __restrict__ QAh, __nv_bfloat16* __restrict__ QAl,
                      __nv_bfloat16* __restrict__ KAh, __nv_bfloat16* __restrict__ KAl,
                      __nv_bfloat16* __restrict__ VAh, __nv_bfloat16* __restrict__ VAl)
{
    extern __shared__ __nv_bfloat16 sm[];
    const int t    = threadIdx.x;
    const int lane = t & 31;
    const int wid  = t >> 5;
    const int wm   = wid >> 1;
    const int wn   = wid & 1;
    const int m0   = blockIdx.y * 128;
    const int n0   = blockIdx.x * 128;
    const int K    = INNER;

    float acc[2][8][4];
#pragma unroll
    for (int i = 0; i < 2; i++)
#pragma unroll
        for (int j = 0; j < 8; j++)
#pragma unroll
            for (int q = 0; q < 4; q++) acc[i][j][q] = 0.f;

    GEMM_V1_MAINLOOP(Ah, Al, Wh, Wl, K, acc)

    const int nhead = (n0 >> 6) + wn;
    const int sec   = nhead >> 4;
    const int hh    = nhead & 15;
    const int dq    = (lane & 3) * 2;
    const int rbase = m0 + wm * 32 + (lane >> 2);

    __nv_bfloat16* outh = (sec == 0) ? QAh : (sec == 1) ? KAh : VAh;
    __nv_bfloat16* outl = (sec == 0) ? QAl : (sec == 1) ? KAl : VAl;
    const float* gvec = (sec == 0) ? gq : gk;
    const float qscale = (sec == 0) ? ATTN_SCALE : 1.0f;

#pragma unroll
    for (int mi = 0; mi < 2; mi++) {
#pragma unroll
        for (int half = 0; half < 2; half++) {
            const int row = rbase + mi * 16 + half * 8;
            const int vi = half * 2;
            const int j = row & 7, tt = row >> 3;
            const size_t dstb = (((size_t)(j * NUM_HEADS + hh)) * STOT + tt) * HEAD_DIM;
            uint32_t* oh32 = (uint32_t*)(outh + dstb);
            uint32_t* ol32 = (uint32_t*)(outl + dstb);

            if (sec == 2) {
#pragma unroll
                for (int nb = 0; nb < 8; nb++) {
                    uint32_t hi, lo;
                    split2(acc[mi][nb][vi], acc[mi][nb][vi + 1], hi, lo);
                    const int d = dq + nb * 8;
                    oh32[d >> 1] = hi;
                    ol32[d >> 1] = lo;
                }
            } else {
                float ss = 0.f;
#pragma unroll
                for (int nb = 0; nb < 8; nb++) {
                    ss += acc[mi][nb][vi] * acc[mi][nb][vi];
                    ss += acc[mi][nb][vi + 1] * acc[mi][nb][vi + 1];
                }
                ss += __shfl_xor_sync(0xffffffffu, ss, 1);
                ss += __shfl_xor_sync(0xffffffffu, ss, 2);
                const float rms = rsqrtf(ss * (1.f / HEAD_DIM) + EPS_RMS);

                const float* cb = cosb + (size_t)row * HEAD_DIM;
                const float* sb = sinb + (size_t)row * HEAD_DIM;
#pragma unroll
                for (int nb = 0; nb < 4; nb++) {
                    const int d0 = dq + nb * 8;
                    const int d1 = d0 + 32;
                    const float x00 = acc[mi][nb][vi]         * rms * gvec[d0];
                    const float x01 = acc[mi][nb][vi + 1]     * rms * gvec[d0 + 1];
                    const float x10 = acc[mi][nb + 4][vi]     * rms * gvec[d1];
                    const float x11 = acc[mi][nb + 4][vi + 1] * rms * gvec[d1 + 1];
                    const float y00 = (x00 * cb[d0]     - x10 * sb[d0])     * qscale;
                    const float y01 = (x01 * cb[d0 + 1] - x11 * sb[d0 + 1]) * qscale;
                    const float y10 = (x10 * cb[d1]     + x00 * sb[d1])     * qscale;
                    const float y11 = (x11 * cb[d1 + 1] + x01 * sb[d1 + 1]) * qscale;
                    uint32_t hi, lo;
                    split2(y00, y01, hi, lo);
                    oh32[d0 >> 1] = hi;
                    ol32[d0 >> 1] = lo;
                    split2(y10, y11, hi, lo);
                    oh32[d1 >> 1] = hi;
                    ol32[d1 >> 1] = lo;
                }
            }
        }
    }
}

// ---------------------------------------------------------------------------
// GEMM v2: 256x128 CTA, 512 threads, 3-stage, K-split (small-M GEMMs)
// ---------------------------------------------------------------------------
#define V2_TILE_A (256 * PADK)
#define V2_TILE_W (128 * PADK)
#define V2_STAGE (2 * V2_TILE_A + 2 * V2_TILE_W)
#define GEMM2_SMEM_BYTES (3 * V2_STAGE * 2)

__global__ void __launch_bounds__(512, 1)
gemm_v2_kernel(const __nv_bfloat16* __restrict__ Ah, const __nv_bfloat16* __restrict__ Al,
               const __nv_bfloat16* __restrict__ Wh, const __nv_bfloat16* __restrict__ Wl,
               float* __restrict__ C, int M, int N, int K, int kparts)
{
    extern __shared__ __nv_bfloat16 sm[];
    const int t    = threadIdx.x;
    const int lane = t & 31;
    const int wid  = t >> 5;
    const int wm   = wid >> 1;
    const int wn   = wid & 1;
    const int m0   = blockIdx.y * 256;
    const int n0   = blockIdx.x * 128;

    const int KC    = K / kparts;
    const int kbase = blockIdx.z * KC;
    const int NT    = KC / 32;

    float acc[2][8][4];
#pragma unroll
    for (int i = 0; i < 2; i++)
#pragma unroll
        for (int j = 0; j < 8; j++)
#pragma unroll
            for (int q = 0; q < 4; q++) acc[i][j][q] = 0.f;

    const int rr = t >> 2;
    const int cc = (t & 3) * 8;
    const uint32_t smb = smem_u32(sm);

    const __nv_bfloat16* pA0 = Ah + (size_t)(m0 + rr)       * K + kbase + cc;
    const __nv_bfloat16* pA1 = Ah + (size_t)(m0 + rr + 128) * K + kbase + cc;
    const __nv_bfloat16* pL0 = Al + (size_t)(m0 + rr)       * K + kbase + cc;
    const __nv_bfloat16* pL1 = Al + (size_t)(m0 + rr + 128) * K + kbase + cc;
    const __nv_bfloat16* pWh = Wh + (size_t)(n0 + rr)       * K + kbase + cc;
    const __nv_bfloat16* pWl = Wl + (size_t)(n0 + rr)       * K + kbase + cc;

    const uint32_t dA0 = (uint32_t)((rr * PADK + cc) << 1);
    const uint32_t dA1 = (uint32_t)(((rr + 128) * PADK + cc) << 1);
    const uint32_t dL0 = dA0 + (uint32_t)(V2_TILE_A << 1);
    const uint32_t dL1 = dA1 + (uint32_t)(V2_TILE_A << 1);
    const uint32_t dWh = dA0 + (uint32_t)((2 * V2_TILE_A) << 1);
    const uint32_t dWl = dA0 + (uint32_t)(((2 * V2_TILE_A) + V2_TILE_W) << 1);

#define V2_LOAD(kt, stg) do {                                              \
    const uint32_t sb = smb + (uint32_t)(((stg) * V2_STAGE) << 1);         \
    const int ko = (kt) * 32;                                              \
    CP_ASYNC16(sb + dA0, pA0 + ko);                                        \
    CP_ASYNC16(sb + dA1, pA1 + ko);                                        \
    CP_ASYNC16(sb + dL0, pL0 + ko);                                        \
    CP_ASYNC16(sb + dL1, pL1 + ko);                                        \
    CP_ASYNC16(sb + dWh, pWh + ko);                                        \
    CP_ASYNC16(sb + dWl, pWl + ko);                                        \
    CP_COMMIT();                                                           \
} while (0)

    V2_LOAD(0, 0);
    V2_LOAD(1, 1);

    const uint32_t abase_rel = (uint32_t)((((wm * 32 + (lane & 15)) * PADK +
                                            ((lane >> 4) << 3))) << 1);
    const uint32_t bbase_rel = (uint32_t)(((2 * V2_TILE_A +
                     (wn * 64 + (lane & 7) + ((lane >> 4) << 3)) * PADK +
                     (((lane >> 3) & 1) << 3))) << 1);

    int stg = 0;
    for (int kt = 0; kt < NT; kt++) {
        if (kt + 2 < NT) {
            const int ps = (stg + 2 >= 3) ? (stg - 1) : (stg + 2);
            V2_LOAD(kt + 2, ps);
            CP_WAIT2();
        } else {
            CP_WAIT0();
        }
        __syncthreads();

        const uint32_t stage  = smb + (uint32_t)((stg * V2_STAGE) << 1);
        const uint32_t abaseh = stage + abase_rel;
        const uint32_t abasel = abaseh + (uint32_t)(V2_TILE_A << 1);
        const uint32_t bbaseh = stage + bbase_rel;
        const uint32_t bbasel = bbaseh + (uint32_t)(V2_TILE_W << 1);

#pragma unroll
        for (int ks = 0; ks < 32; ks += 16) {
            MMA_BLOCK_PIPE(acc, abaseh, abasel, bbaseh, bbasel, ks)
        }
        __syncthreads();
        stg = (stg + 1 >= 3) ? 0 : (stg + 1);
    }

    float* Cz = C + (size_t)blockIdx.z * M * N;
    const int r0 = m0 + wm * 32 + (lane >> 2);
    const int c0 = n0 + wn * 64 + (lane & 3) * 2;
#pragma unroll
    for (int mi = 0; mi < 2; mi++) {
        const int r = r0 + mi * 16;
#pragma unroll
        for (int nb = 0; nb < 8; nb++) {
            const int c = c0 + nb * 8;
            *(float2*)(Cz + (size_t)r * N + c) =
                make_float2(acc[mi][nb][0], acc[mi][nb][1]);
            *(float2*)(Cz + (size_t)(r + 8) * N + c) =
                make_float2(acc[mi][nb][2], acc[mi][nb][3]);
        }
    }
}

// ---------------------------------------------------------------------------
// K-split reduce (with bias)
// ---------------------------------------------------------------------------
__global__ void __launch_bounds__(256)
reduce4_kernel(const float* __restrict__ part, const float* __restrict__ bias,
               float* __restrict__ out, int MN, int N)
{
    const int i = blockIdx.x * 256 + threadIdx.x;
    if (i * 4 >= MN) return;
    const int q = MN / 4;
    float4 a = ((const float4*)part)[i];
    float4 b = ((const float4*)part)[i + q];
    float4 c = ((const float4*)part)[i + 2 * q];
    float4 d = ((const float4*)part)[i + 3 * q];
    float4 r = make_float4(a.x + b.x + c.x + d.x, a.y + b.y + c.y + d.y,
                           a.z + b.z + c.z + d.z, a.w + b.w + c.w + d.w);
    if (bias) {
        const int col = (i * 4) % N;
        r.x += bias[col];  r.y += bias[col + 1];
        r.z += bias[col + 2];  r.w += bias[col + 3];
    }
    ((float4*)out)[i] = r;
}

// ---------------------------------------------------------------------------
// RMSNorm + broadcast scatter (text), reads 4 K-split partials directly
// ---------------------------------------------------------------------------
__global__ void __launch_bounds__(256)
enc_post_kernel(const float* __restrict__ part,
                const float* __restrict__ gaq, const float* __restrict__ gak,
                __nv_bfloat16* __restrict__ QAh, __nv_bfloat16* __restrict__ QAl,
                __nv_bfloat16* __restrict__ KAh, __nv_bfloat16* __restrict__ KAl,
                __nv_bfloat16* __restrict__ VAh, __nv_bfloat16* __restrict__ VAl)
{
    const int warp = (blockIdx.x * blockDim.x + threadIdx.x) >> 5;
    const int lane = threadIdx.x & 31;
    const int tt = warp >> 4;
    const int h  = warp & 15;
    if (tt >= T_LEN) return;

    const size_t src = (size_t)tt * INNER3 + h * HEAD_DIM;
    const size_t PQ = (size_t)T_LEN * INNER3;
    float a0 = 0.f, a1 = 0.f, b0 = 0.f, b1 = 0.f, v0 = 0.f, v1 = 0.f;
#pragma unroll
    for (int z = 0; z < 4; z++) {
        const float* p = part + z * PQ + src;
        a0 += p[lane];              a1 += p[lane + 32];
        b0 += p[INNER + lane];      b1 += p[INNER + lane + 32];
        v0 += p[2*INNER + lane];    v1 += p[2*INNER + lane + 32];
    }

    float ra = rsqrtf(warp_sum32(a0 * a0 + a1 * a1) * (1.f / HEAD_DIM) + EPS_RMS);
    float rb = rsqrtf(warp_sum32(b0 * b0 + b1 * b1) * (1.f / HEAD_DIM) + EPS_RMS);

    a0 *= ra * gaq[lane] * ATTN_SCALE;  a1 *= ra * gaq[lane + 32] * ATTN_SCALE;
    b0 *= rb * gak[lane];               b1 *= rb * gak[lane + 32];

#pragma unroll
    for (int j = 0; j < SPARSE_N; j++) {
        const size_t dst =
            (((size_t)(j * NUM_HEADS + h)) * STOT + G_LEN + tt) * HEAD_DIM;
        store_split(QAh, QAl, dst + lane,      a0);
        store_split(QAh, QAl, dst + lane + 32, a1);
        store_split(KAh, KAl, dst + lane,      b0);
        store_split(KAh, KAl, dst + lane + 32, b1);
        store_split(VAh, VAl, dst + lane,      v0);
        store_split(VAh, VAl, dst + lane + 32, v1);
    }
}

// ---------------------------------------------------------------------------
// Flash attention, BQ=256, 512 threads, cp.async K/V double buffering.
// STATIC-MAX softmax (scores bounded by SMAX); fused vis gather.
// ---------------------------------------------------------------------------
#define APAD 72
#define AQ_ELEMS (2 * 256 * APAD)
#define KV_TILE  (64 * APAD)
#define KV_STAGE (4 * KV_TILE)
#define ATT_SM_BYTES ((AQ_ELEMS + 2 * KV_STAGE) * 2)

__global__ void __launch_bounds__(512, 1)
attn_mma_kernel(const __nv_bfloat16* __restrict__ Qhg, const __nv_bfloat16* __restrict__ Qlg,
                const __nv_bfloat16* __restrict__ Khg, const __nv_bfloat16* __restrict__ Klg,
                const __nv_bfloat16* __restrict__ Vhg, const __nv_bfloat16* __restrict__ Vlg,
                float* __restrict__ OA,
                __nv_bfloat16* __restrict__ vis_h, __nv_bfloat16* __restrict__ vis_l)
{
    extern __shared__ __nv_bfloat16 smA[];
    const int t    = threadIdx.x;
    const int lane = t & 31;
    const int w    = t >> 5;
    const int jh   = blockIdx.y;
    const int q0   = blockIdx.x * 256;
    const size_t base = (size_t)jh * STOT * HEAD_DIM;

    const uint32_t smb = smem_u32(smA);

    const int tile = t >> 7;
    const int l128 = t & 127;
    const int krr  = l128 >> 3;
    const int kcc  = (l128 & 7) * 8;
    const __nv_bfloat16* kvsrc =
        (tile == 0) ? Khg : (tile == 1) ? Klg : (tile == 2) ? Vhg : Vlg;
    const uint32_t kvdst0 = smb + ((AQ_ELEMS + tile * KV_TILE + krr * APAD + kcc) << 1);

    {
        const __nv_bfloat16* g = kvsrc + base + (size_t)krr * 64 + kcc;
#pragma unroll
        for (int i = 0; i < 4; i++)
            CP_ASYNC16(kvdst0 + (uint32_t)((i * 16 * APAD) << 1),
                       g + (size_t)(i * 16) * 64);
        CP_COMMIT();
    }

    {
        const int row = t >> 1, c0 = (t & 1) * 32;
        const __nv_bfloat16* gh = Qhg + base + (size_t)(q0 + row) * 64 + c0;
        const __nv_bfloat16* gl = Qlg + base + (size_t)(q0 + row) * 64 + c0;
        __nv_bfloat16* sh = smA + row * APAD + c0;
        __nv_bfloat16* sl = smA + 256 * APAD + row * APAD + c0;
#pragma unroll
        for (int c = 0; c < 32; c += 8) {
            *(uint4*)(sh + c) = *(const uint4*)(gh + c);
            *(uint4*)(sl + c) = *(const uint4*)(gl + c);
        }
    }

    float o[8][4];
#pragma unroll
    for (int i = 0; i < 8; i++)
#pragma unroll
        for (int j = 0; j < 4; j++) o[i][j] = 0.f;
    float l0r = 0.f, l1r = 0.f;

    const uint32_t qfragh = smb + (((w * 16 + (lane & 15)) * APAD + ((lane >> 4) << 3)) << 1);
    const uint32_t qfragl = qfragh + ((256 * APAD) << 1);
    const uint32_t kfrag_rel = ((((lane & 7) + ((lane >> 4) << 3)) * APAD + (((lane >> 3) & 1) << 3)) << 1);
    const uint32_t vfrag_rel = (((2 * KV_TILE) + ((lane & 7) + (((lane >> 3) & 1) << 3)) * APAD + ((lane >> 4) << 3)) << 1);

    for (int kt = 0; kt < 20; kt++) {
        const int b = kt & 1;
        if (kt + 1 < 20) {
            const __nv_bfloat16* g = kvsrc + base + (size_t)((kt + 1) * 64 + krr) * 64 + kcc;
            const uint32_t d = kvdst0 + (uint32_t)((((kt + 1) & 1) * KV_STAGE) << 1);
#pragma unroll
            for (int i = 0; i < 4; i++)
                CP_ASYNC16(d + (uint32_t)((i * 16 * APAD) << 1),
                           g + (size_t)(i * 16) * 64);
            CP_COMMIT();
            CP_WAIT1();
        } else {
            CP_WAIT0();
        }
        __syncthreads();

        const uint32_t kvstage = smb + (uint32_t)(((AQ_ELEMS + b * KV_STAGE)) << 1);
        const uint32_t kfragh = kvstage + kfrag_rel;
        const uint32_t kfragl = kfragh + (KV_TILE << 1);
        const uint32_t vfrag  = kvstage + vfrag_rel;

        float s[8][4];
#pragma unroll
        for (int i = 0; i < 8; i++)
#pragma unroll
            for (int j = 0; j < 4; j++) s[i][j] = 0.f;

        // ---- scores (pipelined K fragments) ----
#pragma unroll
        for (int ks = 0; ks < 64; ks += 16) {
            uint32_t ah[4], al[4];
            ldsm_x4(ah, qfragh + ks * 2);
            ldsm_x4(al, qfragl + ks * 2);
            uint32_t kh[2][4], kl[4], kln[4];
            ldsm_x4(kh[0], kfragh + ks * 2);
            ldsm_x4(kl,    kfragl + ks * 2);
#pragma unroll
            for (int nbp = 0; nbp < 4; nbp++) {
                const int c = nbp & 1;
                mma16816(s[2 * nbp],     ah, kh[c]);
                mma16816(s[2 * nbp + 1], ah, kh[c] + 2);
                if (nbp < 3)
                    ldsm_x4(kh[c ^ 1], kfragh + ks * 2 + (nbp + 1) * 16 * APAD * 2);
                mma16816(s[2 * nbp],     ah, kl);
                mma16816(s[2 * nbp + 1], ah, kl + 2);
                if (nbp < 3)
                    ldsm_x4(kln, kfragl + ks * 2 + (nbp + 1) * 16 * APAD * 2);
                mma16816(s[2 * nbp],     al, kh[c]);
                mma16816(s[2 * nbp + 1], al, kh[c] + 2);
                if (nbp < 3) {
                    kl[0] = kln[0]; kl[1] = kln[1];
                    kl[2] = kln[2]; kl[3] = kln[3];
                }
            }
        }

        // ---- static-max softmax: p = exp(s - SMAX), no corrections ----
        float rs0 = 0.f, rs1 = 0.f;
#pragma unroll
        for (int nb = 0; nb < 8; nb++) {
            s[nb][0] = __expf(s[nb][0] - SMAX);  rs0 += s[nb][0];
            s[nb][1] = __expf(s[nb][1] - SMAX);  rs0 += s[nb][1];
            s[nb][2] = __expf(s[nb][2] - SMAX);  rs1 += s[nb][2];
            s[nb][3] = __expf(s[nb][3] - SMAX);  rs1 += s[nb][3];
        }
        rs0 += __shfl_xor_sync(0xffffffffu, rs0, 1);
        rs0 += __shfl_xor_sync(0xffffffffu, rs0, 2);
        rs1 += __shfl_xor_sync(0xffffffffu, rs1, 1);
        rs1 += __shfl_xor_sync(0xffffffffu, rs1, 2);
        l0r += rs0;
        l1r += rs1;

        // ---- PV (pipelined V fragments) ----
#pragma unroll
        for (int kb2 = 0; kb2 < 4; kb2++) {
            uint32_t ph[4], pl[4];
            split2(s[2 * kb2][0],     s[2 * kb2][1],     ph[0], pl[0]);
            split2(s[2 * kb2][2],     s[2 * kb2][3],     ph[1], pl[1]);
            split2(s[2 * kb2 + 1][0], s[2 * kb2 + 1][1], ph[2], pl[2]);
            split2(s[2 * kb2 + 1][2], s[2 * kb2 + 1][3], ph[3], pl[3]);
            const uint32_t vb = vfrag + kb2 * 16 * APAD * 2;
            uint32_t vh[2][4], vl[4], vln[4];
            ldsm_x4_t(vh[0], vb);
            ldsm_x4_t(vl, vb + (KV_TILE << 1));
#pragma unroll
            for (int dbp = 0; dbp < 4; dbp++) {
                const int c = dbp & 1;
                mma16816(o[2 * dbp],     ph, vh[c]);
                mma16816(o[2 * dbp + 1], ph, vh[c] + 2);
                if (dbp < 3)
                    ldsm_x4_t(vh[c ^ 1], vb + (dbp + 1) * 16 * 2);
                mma16816(o[2 * dbp],     ph, vl);
                mma16816(o[2 * dbp + 1], ph, vl + 2);
                if (dbp < 3)
                    ldsm_x4_t(vln, vb + (KV_TILE << 1) + (dbp + 1) * 16 * 2);
                mma16816(o[2 * dbp],     pl, vh[c]);
                mma16816(o[2 * dbp + 1], pl, vh[c] + 2);
                if (dbp < 3) {
                    vl[0] = vln[0]; vl[1] = vln[1];
                    vl[2] = vln[2]; vl[3] = vln[3];
                }
            }
        }
        __syncthreads();
    }

    const float inv0 = 1.f / l0r, inv1 = 1.f / l1r;
    const int row = q0 + w * 16 + (lane >> 2);
    const int col = (lane & 3) * 2;
    if (blockIdx.x < 4) {
        const int j = jh >> 4, h = jh & 15;
        uint32_t* vh32 = (uint32_t*)vis_h;
        uint32_t* vl32 = (uint32_t*)vis_l;
        const size_t b0 = ((size_t)row * 8 + j) * INNER + h * 64;
        const size_t b1 = ((size_t)(row + 8) * 8 + j) * INNER + h * 64;
#pragma unroll
        for (int db = 0; db < 8; db++) {
            uint32_t hi, lo;
            split2(o[db][0] * inv0, o[db][1] * inv0, hi, lo);
            vh32[(b0 + db * 8 + col) >> 1] = hi;
            vl32[(b0 + db * 8 + col) >> 1] = lo;
            split2(o[db][2] * inv1, o[db][3] * inv1, hi, lo);
            vh32[(b1 + db * 8 + col) >> 1] = hi;
            vl32[(b1 + db * 8 + col) >> 1] = lo;
        }
    } else {
#pragma unroll
        for (int db = 0; db < 8; db++) {
            *(float2*)(OA + base + (size_t)row * 64 + db * 8 + col) =
                make_float2(o[db][0] * inv0, o[db][1] * inv0);
            *(float2*)(OA + base + (size_t)(row + 8) * 64 + db * 8 + col) =
                make_float2(o[db][2] * inv1, o[db][3] * inv1);
        }
    }
}

// ---------------------------------------------------------------------------
// Gather text rows -> bf16 hi/lo (mean over j)
// ---------------------------------------------------------------------------
__global__ void __launch_bounds__(256)
gather_txt_kernel(const float* __restrict__ OA,
                  __nv_bfloat16* __restrict__ th, __nv_bfloat16* __restrict__ tl)
{
    const int i = blockIdx.x * 256 + threadIdx.x;
    const int idx = i * 4;
    const int tt = idx >> 10, e = idx & 1023;
    const int h = e >> 6, d = e & 63;
    float4 acc = make_float4(0.f, 0.f, 0.f, 0.f);
#pragma unroll
    for (int j = 0; j < SPARSE_N; j++) {
        float4 v = *(const float4*)(OA +
            (((size_t)(j * NUM_HEADS + h)) * STOT + G_LEN + tt) * HEAD_DIM + d);
        acc.x += v.x; acc.y += v.y; acc.z += v.z; acc.w += v.w;
    }
    acc.x *= 0.125f; acc.y *= 0.125f; acc.z *= 0.125f; acc.w *= 0.125f;
    uint32_t h01, l01, h23, l23;
    split2(acc.x, acc.y, h01, l01);
    split2(acc.z, acc.w, h23, l23);
    ((uint2*)th)[i] = make_uint2(h01, h23);
    ((uint2*)tl)[i] = make_uint2(l01, l23);
}

// ---------------------------------------------------------------------------
// kernel_launch
// ---------------------------------------------------------------------------
extern "C" void kernel_launch(void* const* d_in, const int* in_sizes, int n_in,
                              void* d_out, int out_size)
{
    const float* hs   = (const float*)d_in[0];
    const float* enc  = (const float*)d_in[1];
    const float* bout  = (const float*)d_in[9];
    const float* baout = (const float*)d_in[11];
    const float* gq   = (const float*)d_in[12];
    const float* gk   = (const float*)d_in[13];
    const float* gaq  = (const float*)d_in[14];
    const float* gak  = (const float*)d_in[15];
    const float* rc   = (const float*)d_in[16];
    const float* rs   = (const float*)d_in[17];
    float* out = (float*)d_out;

    float *encpart, *txtpart, *OA;
    __nv_bfloat16 *hs_h, *hs_l, *enc_h, *enc_l, *w_h, *w_l;
    __nv_bfloat16 *vis_h, *vis_l, *txt_h, *txt_l;
    __nv_bfloat16 *QAh, *QAl, *KAh, *KAl, *VAh, *VAl;
    cudaGetSymbolAddress((void**)&encpart, g_encpart);
    cudaGetSymbolAddress((void**)&txtpart, g_txtpart);
    cudaGetSymbolAddress((void**)&OA,    g_OA);
    cudaGetSymbolAddress((void**)&hs_h,  g_hs_h);
    cudaGetSymbolAddress((void**)&hs_l,  g_hs_l);
    cudaGetSymbolAddress((void**)&enc_h, g_enc_h);
    cudaGetSymbolAddress((void**)&enc_l, g_enc_l);
    cudaGetSymbolAddress((void**)&w_h,   g_w_h);
    cudaGetSymbolAddress((void**)&w_l,   g_w_l);
    cudaGetSymbolAddress((void**)&vis_h, g_vis_h);
    cudaGetSymbolAddress((void**)&vis_l, g_vis_l);
    cudaGetSymbolAddress((void**)&txt_h, g_txt_h);
    cudaGetSymbolAddress((void**)&txt_l, g_txt_l);
    cudaGetSymbolAddress((void**)&QAh,   g_QAh);
    cudaGetSymbolAddress((void**)&QAl,   g_QAl);
    cudaGetSymbolAddress((void**)&KAh,   g_KAh);
    cudaGetSymbolAddress((void**)&KAl,   g_KAl);
    cudaGetSymbolAddress((void**)&VAh,   g_VAh);
    cudaGetSymbolAddress((void**)&VAl,   g_VAl);

    cudaFuncSetAttribute(gemm_bf3_kernel,
                         cudaFuncAttributeMaxDynamicSharedMemorySize, GEMM1_SMEM_BYTES);
    cudaFuncSetAttribute(gemm_qkv_fused_kernel,
                         cudaFuncAttributeMaxDynamicSharedMemorySize, GEMM1_SMEM_BYTES);
    cudaFuncSetAttribute(gemm_v2_kernel,
                         cudaFuncAttributeMaxDynamicSharedMemorySize, GEMM2_SMEM_BYTES);
    cudaFuncSetAttribute(attn_mma_kernel,
                         cudaFuncAttributeMaxDynamicSharedMemorySize, ATT_SM_BYTES);

    const size_t WS = (size_t)INNER * INNER;

    // [0] weight conversions (4x ILP), [1] hs+enc conversions (4x ILP)
    cvt_w_kernel<<<2048, 256>>>(
        (const float*)d_in[2], (const float*)d_in[3], (const float*)d_in[4],
        (const float*)d_in[5], (const float*)d_in[6], (const float*)d_in[7],
        (const float*)d_in[8], (const float*)d_in[10], w_h, w_l);
    cvt_hsenc_kernel<<<2112, 256>>>(hs, enc, hs_h, hs_l, enc_h, enc_l);

    // [2] enc QKV GEMM (v2, K-split x4), [3] enc post (fused reduce)
    gemm_v2_kernel<<<dim3(INNER3 / 128, 1, 4), 512, GEMM2_SMEM_BYTES>>>(
        enc_h, enc_l, w_h + 3 * WS, w_l + 3 * WS, encpart, T_LEN, INNER3, INNER, 4);
    enc_post_kernel<<<(T_LEN * NUM_HEADS) / 8, 256>>>(
        encpart, gaq, gak, QAh, QAl, KAh, KAl, VAh, VAl);

    // [4] big QKV GEMM (fused epilogue)
    gemm_qkv_fused_kernel<<<dim3(INNER3 / 128, S_LEN / 128), 256, GEMM1_SMEM_BYTES>>>(
        hs_h, hs_l, w_h + 0 * WS, w_l + 0 * WS,
        gq, gk, rc, rs, QAh, QAl, KAh, KAl, VAh, VAl);

    // [5] attention (static-max softmax, fused vis gather)  <- profiled launch
    attn_mma_kernel<<<dim3(STOT / 256, NJH), 512, ATT_SM_BYTES>>>(
        QAh, QAl, KAh, KAl, VAh, VAl, OA, vis_h, vis_l);

    // [6] text gather
    gather_txt_kernel<<<(T_LEN * INNER / 4) / 256, 256>>>(OA, txt_h, txt_l);

    // [7] vis out GEMM (v1, bias)
    gemm_bf3_kernel<<<dim3(INNER / 128, S_LEN / 128), 256, GEMM1_SMEM_BYTES>>>(
        vis_h, vis_l, w_h + 6 * WS, w_l + 6 * WS, bout, out, S_LEN, INNER, INNER);

    // [8] txt out GEMM (v2, K-split x4), [9] reduce with bias
    gemm_v2_kernel<<<dim3(INNER / 128, 1, 4), 512, GEMM2_SMEM_BYTES>>>(
        txt_h, txt_l, w_h + 7 * WS, w_l + 7 * WS, txtpart, T_LEN, INNER, INNER, 4);
    reduce4_kernel<<<(T_LEN * INNER / 4) / 256, 256>>>(
        txtpart, baout, out + (size_t)S_LEN * INNER, T_LEN * INNER, INNER);
}